// round 2
// baseline (speedup 1.0000x reference)
#include <cuda_runtime.h>
#include <math.h>

#define BB   64
#define SS   512
#define HH   1024
#define G4   4096
#define NCTA 128

// ---------------- device scratch (zero-init .bss, no runtime allocation) -----
__device__ float g_P0[BB * SS * G4];       // layer-0 time-parallel preactivations
__device__ float g_P1[BB * SS * G4];       // layer-1 time-parallel preactivations
__device__ float g_Hout[BB * SS * HH];     // h1 over time, for fc head
__device__ float g_h0[2][BB * HH];         // double-buffered layer-0 hidden
__device__ float g_h1[2][BB * HH];         // double-buffered layer-1 hidden
__device__ unsigned g_bar;                 // grid barrier counter

__device__ __forceinline__ float4 ldg4(const float* p)  { return __ldg((const float4*)p); }
__device__ __forceinline__ float4 ldcg4(const float* p) { return __ldcg((const float4*)p); }
__device__ __forceinline__ float sigf(float x) { return 1.0f / (1.0f + __expf(-x)); }
__device__ __forceinline__ float tanha(float x) { return 1.0f - 2.0f / (__expf(2.0f * x) + 1.0f); }

// ---------------- init: reset barrier + zero hidden state (runs every replay) -
__global__ void init_kernel() {
    int tid = blockIdx.x * blockDim.x + threadIdx.x;
    int n = BB * HH;
    for (int i = tid; i < n; i += gridDim.x * blockDim.x) {
        g_h0[0][i] = 0.f; g_h0[1][i] = 0.f;
        g_h1[0][i] = 0.f; g_h1[1][i] = 0.f;
    }
    if (blockIdx.x == 0 && tid == 0) g_bar = 0u;
}

// ---------------- precompute: OUT = A1@M1 + A2@M2 + bias1 + bias2 ------------
// OUT is [32768, 4096]; tile 64x64, 256 threads, 4x4 per thread, reg-prefetch.
__global__ void __launch_bounds__(256)
gemm2_kernel(const float* __restrict__ A1, const float* __restrict__ M1, int K1,
             const float* __restrict__ A2, const float* __restrict__ M2, int K2,
             const float* __restrict__ bs1, const float* __restrict__ bs2,
             int which)
{
    float* OUT = which ? g_P1 : g_P0;
    __shared__ __align__(16) float a_sm[16][68];
    __shared__ __align__(16) float w_sm[16][68];
    const int tid = threadIdx.x;
    const int n0 = blockIdx.x * 64;
    const int m0 = blockIdx.y * 64;
    const int ar = tid >> 2, aq = tid & 3;      // a staging: row 0..63, k-quad 0..3
    const int wk = tid >> 4, wq = tid & 15;     // w staging: k 0..15, col-quad
    const int ty = tid >> 4, tx = tid & 15;     // compute: 4 rows x 4 cols

    float acc[4][4] = {};
    const int nch1 = K1 >> 4;
    const int nch  = nch1 + (K2 >> 4);

    float4 ra = ldg4(A1 + (size_t)(m0 + ar) * K1 + aq * 4);
    float4 rw = ldg4(M1 + (size_t)wk * G4 + n0 + wq * 4);

    for (int ch = 0; ch < nch; ++ch) {
        __syncthreads();
        a_sm[aq * 4 + 0][ar] = ra.x;
        a_sm[aq * 4 + 1][ar] = ra.y;
        a_sm[aq * 4 + 2][ar] = ra.z;
        a_sm[aq * 4 + 3][ar] = ra.w;
        *(float4*)&w_sm[wk][wq * 4] = rw;
        __syncthreads();
        if (ch + 1 < nch) {
            int c2 = ch + 1;
            const float* A; const float* Wm; int k0, K;
            if (c2 < nch1) { A = A1; Wm = M1; K = K1; k0 = c2 * 16; }
            else           { A = A2; Wm = M2; K = K2; k0 = (c2 - nch1) * 16; }
            ra = ldg4(A + (size_t)(m0 + ar) * K + k0 + aq * 4);
            rw = ldg4(Wm + (size_t)(k0 + wk) * G4 + n0 + wq * 4);
        }
#pragma unroll
        for (int k = 0; k < 16; ++k) {
            float4 av = *(const float4*)&a_sm[k][ty * 4];
            float4 wv = *(const float4*)&w_sm[k][tx * 4];
            acc[0][0] += av.x * wv.x; acc[0][1] += av.x * wv.y; acc[0][2] += av.x * wv.z; acc[0][3] += av.x * wv.w;
            acc[1][0] += av.y * wv.x; acc[1][1] += av.y * wv.y; acc[1][2] += av.y * wv.z; acc[1][3] += av.y * wv.w;
            acc[2][0] += av.z * wv.x; acc[2][1] += av.z * wv.y; acc[2][2] += av.z * wv.z; acc[2][3] += av.z * wv.w;
            acc[3][0] += av.w * wv.x; acc[3][1] += av.w * wv.y; acc[3][2] += av.w * wv.z; acc[3][3] += av.w * wv.w;
        }
    }
    float4 b1v = ldg4(bs1 + n0 + tx * 4);
    float4 b2v = ldg4(bs2 + n0 + tx * 4);
    float4 bsum = make_float4(b1v.x + b2v.x, b1v.y + b2v.y, b1v.z + b2v.z, b1v.w + b2v.w);
#pragma unroll
    for (int i = 0; i < 4; ++i) {
        float4 v = make_float4(acc[i][0] + bsum.x, acc[i][1] + bsum.y,
                               acc[i][2] + bsum.z, acc[i][3] + bsum.w);
        *(float4*)&OUT[(size_t)(m0 + ty * 4 + i) * G4 + n0 + tx * 4] = v;
    }
}

// ---------------- grid barrier (128 CTAs co-resident; fenced release/acquire) -
__device__ __forceinline__ void gbar(unsigned& epoch)
{
    __syncthreads();
    epoch += NCTA;
    if (threadIdx.x == 0) {
        __threadfence();
        atomicAdd(&g_bar, 1u);
        while (*(volatile unsigned*)&g_bar < epoch) { }
        __threadfence();
    }
    __syncthreads();
}

// ---------------- recurrent GEMM helper: acc += h@Wslice (K=1024 or 2048) ----
// out tile: 64 batch x 32 gate-cols (4 gates x 8 units of this CTA).
__device__ __forceinline__ void mm_acc(
    float acc[2][4],
    const float* __restrict__ hA, const float* __restrict__ WA,
    const float* __restrict__ hB, const float* __restrict__ WB,
    int u0, float (*a_sm)[68], float (*w_sm)[36])
{
    const int tid = threadIdx.x;
    const int lb = tid >> 2, lq = tid & 3;      // a staging
    const int wk = tid >> 3, wq = tid & 7;      // w staging
    const int gcol = (wq >> 1) * HH + u0 + (wq & 1) * 4;
    const int cty = tid >> 3, ctx = tid & 7;    // compute: 2 rows x 4 cols
    const int nch = WB ? 64 : 32;

    float4 ra0 = ldcg4(hA + lb * HH + lq * 4);
    float4 ra1 = ldcg4(hA + lb * HH + (lq + 4) * 4);
    float4 rw  = ldg4(WA + (size_t)wk * G4 + gcol);

    for (int ch = 0; ch < nch; ++ch) {
        __syncthreads();
        a_sm[lq * 4 + 0][lb] = ra0.x;
        a_sm[lq * 4 + 1][lb] = ra0.y;
        a_sm[lq * 4 + 2][lb] = ra0.z;
        a_sm[lq * 4 + 3][lb] = ra0.w;
        a_sm[(lq + 4) * 4 + 0][lb] = ra1.x;
        a_sm[(lq + 4) * 4 + 1][lb] = ra1.y;
        a_sm[(lq + 4) * 4 + 2][lb] = ra1.z;
        a_sm[(lq + 4) * 4 + 3][lb] = ra1.w;
        *(float4*)&w_sm[wk][wq * 4] = rw;
        __syncthreads();
        if (ch + 1 < nch) {
            int c2 = ch + 1;
            const float* hb = (c2 < 32) ? hA : hB;
            const float* wm = (c2 < 32) ? WA : WB;
            int k0 = (c2 & 31) * 32;
            ra0 = ldcg4(hb + lb * HH + k0 + lq * 4);
            ra1 = ldcg4(hb + lb * HH + k0 + (lq + 4) * 4);
            rw  = ldg4(wm + (size_t)(k0 + wk) * G4 + gcol);
        }
#pragma unroll
        for (int k = 0; k < 32; ++k) {
            float2 av = *(const float2*)&a_sm[k][cty * 2];
            float4 wv = *(const float4*)&w_sm[k][ctx * 4];
            acc[0][0] += av.x * wv.x; acc[0][1] += av.x * wv.y;
            acc[0][2] += av.x * wv.z; acc[0][3] += av.x * wv.w;
            acc[1][0] += av.y * wv.x; acc[1][1] += av.y * wv.y;
            acc[1][2] += av.y * wv.z; acc[1][3] += av.y * wv.w;
        }
    }
}

// ---------------- persistent recurrent kernel --------------------------------
__global__ void __launch_bounds__(256, 1)
recur_kernel(const float* __restrict__ U0, const float* __restrict__ W1,
             const float* __restrict__ U1, float* __restrict__ out)
{
    __shared__ __align__(16) float a_sm[32][68];
    __shared__ __align__(16) float w_sm[32][36];
    __shared__ float pre_sm[32][65];
    __shared__ float c0_sm[8][65];
    __shared__ float c1_sm[8][65];

    const int tid = threadIdx.x;
    const int u0 = blockIdx.x * 8;          // this CTA's hidden-unit base
    for (int i = tid; i < 8 * 65; i += 256) {
        ((float*)c0_sm)[i] = 0.f;
        ((float*)c1_sm)[i] = 0.f;
    }
    __syncthreads();

    unsigned epoch = 0;
    const int cty = tid >> 3, ctx = tid & 7;          // GEMM compute map
    const int cu = tid & 7,  cb = tid >> 3;           // cell map
    const int gc = (ctx >> 1) * HH + u0 + (ctx & 1) * 4;

    for (int t = 0; t < SS; ++t) {
        const int prv = t & 1;
        const int cur = prv ^ 1;

        // ---- layer 0: pre = P0[t] + h0_prev @ U0 ----
        float acc[2][4] = {};
        mm_acc(acc, g_h0[prv], U0, (const float*)0, (const float*)0, u0, a_sm, w_sm);
#pragma unroll
        for (int i = 0; i < 2; ++i) {
            int b = cty * 2 + i;
            float4 p = ldg4(&g_P0[((size_t)b * SS + t) * G4 + gc]);
            pre_sm[ctx * 4 + 0][b] = acc[i][0] + p.x;
            pre_sm[ctx * 4 + 1][b] = acc[i][1] + p.y;
            pre_sm[ctx * 4 + 2][b] = acc[i][2] + p.z;
            pre_sm[ctx * 4 + 3][b] = acc[i][3] + p.w;
        }
        __syncthreads();
#pragma unroll
        for (int half = 0; half < 2; ++half) {
            int b = cb + half * 32;
            float f  = sigf(pre_sm[cu][b]);
            float ii = sigf(pre_sm[8 + cu][b]);
            float g  = tanha(pre_sm[16 + cu][b]);
            float o  = sigf(pre_sm[24 + cu][b]);
            float cn = f * c0_sm[cu][b] + ii * g;
            c0_sm[cu][b] = cn;
            float h = o * tanha(cn);
            g_h0[cur][b * HH + u0 + cu] = h;
            if (t == SS - 1) {
                out[98304 + b * HH + u0 + cu] = h;     // hN[0]
                out[229376 + b * HH + u0 + cu] = cn;   // cN[0]
            }
        }
        gbar(epoch);

        // ---- layer 1: pre = P1[t] + h0_cur @ W1 + h1_prev @ U1 ----
        float acc2[2][4] = {};
        mm_acc(acc2, g_h0[cur], W1, g_h1[prv], U1, u0, a_sm, w_sm);
#pragma unroll
        for (int i = 0; i < 2; ++i) {
            int b = cty * 2 + i;
            float4 p = ldg4(&g_P1[((size_t)b * SS + t) * G4 + gc]);
            pre_sm[ctx * 4 + 0][b] = acc2[i][0] + p.x;
            pre_sm[ctx * 4 + 1][b] = acc2[i][1] + p.y;
            pre_sm[ctx * 4 + 2][b] = acc2[i][2] + p.z;
            pre_sm[ctx * 4 + 3][b] = acc2[i][3] + p.w;
        }
        __syncthreads();
#pragma unroll
        for (int half = 0; half < 2; ++half) {
            int b = cb + half * 32;
            float f  = sigf(pre_sm[cu][b]);
            float ii = sigf(pre_sm[8 + cu][b]);
            float g  = tanha(pre_sm[16 + cu][b]);
            float o  = sigf(pre_sm[24 + cu][b]);
            float cn = f * c1_sm[cu][b] + ii * g;
            c1_sm[cu][b] = cn;
            float h = o * tanha(cn);
            g_h1[cur][b * HH + u0 + cu] = h;
            g_Hout[((size_t)b * SS + t) * HH + u0 + cu] = h;
            if (t == SS - 1) {
                out[98304 + 65536 + b * HH + u0 + cu] = h;    // hN[1]
                out[229376 + 65536 + b * HH + u0 + cu] = cn;  // cN[1]
            }
        }
        gbar(epoch);
    }
}

// ---------------- output head: y = Hout @ fc_W + fc_b ------------------------
__global__ void __launch_bounds__(256)
head_kernel(const float* __restrict__ fcW, const float* __restrict__ fcb,
            float* __restrict__ out)
{
    int warp = (blockIdx.x * blockDim.x + threadIdx.x) >> 5;
    int lane = threadIdx.x & 31;
    if (warp >= BB * SS) return;
    const float* hrow = &g_Hout[(size_t)warp * HH];
    float a0 = 0.f, a1 = 0.f, a2 = 0.f;
    for (int k = lane; k < HH; k += 32) {
        float h = __ldg(&hrow[k]);
        a0 += h * __ldg(&fcW[k * 3 + 0]);
        a1 += h * __ldg(&fcW[k * 3 + 1]);
        a2 += h * __ldg(&fcW[k * 3 + 2]);
    }
#pragma unroll
    for (int off = 16; off; off >>= 1) {
        a0 += __shfl_xor_sync(0xffffffffu, a0, off);
        a1 += __shfl_xor_sync(0xffffffffu, a1, off);
        a2 += __shfl_xor_sync(0xffffffffu, a2, off);
    }
    if (lane == 0) {
        out[warp * 3 + 0] = a0 + __ldg(&fcb[0]);
        out[warp * 3 + 1] = a1 + __ldg(&fcb[1]);
        out[warp * 3 + 2] = a2 + __ldg(&fcb[2]);
    }
}

extern "C" void kernel_launch(void* const* d_in, const int* in_sizes, int n_in,
                              void* d_out, int out_size)
{
    const float* x    = (const float*)d_in[0];
    const float* z    = (const float*)d_in[1];
    const float* W0   = (const float*)d_in[2];
    const float* bW0  = (const float*)d_in[3];
    const float* U0   = (const float*)d_in[4];
    const float* V0   = (const float*)d_in[5];
    const float* b0   = (const float*)d_in[6];
    const float* W1   = (const float*)d_in[7];
    const float* bW1  = (const float*)d_in[8];
    const float* U1   = (const float*)d_in[9];
    const float* V1   = (const float*)d_in[10];
    const float* b1   = (const float*)d_in[11];
    const float* fcW  = (const float*)d_in[12];
    const float* fcb  = (const float*)d_in[13];
    float* out = (float*)d_out;

    init_kernel<<<256, 256>>>();
    gemm2_kernel<<<dim3(64, 512), 256>>>(x, W0, 512, z, V0, 128, bW0, b0, 0);
    gemm2_kernel<<<dim3(64, 512), 256>>>(z, V1, 128, (const float*)0, (const float*)0, 0, bW1, b1, 1);
    recur_kernel<<<NCTA, 256>>>(U0, W1, U1, out);
    head_kernel<<<4096, 256>>>(fcW, fcb, out);
}

// round 3
// speedup vs baseline: 2.1867x; 2.1867x over previous
#include <cuda_runtime.h>
#include <cuda_bf16.h>
#include <math.h>

#define BB   64
#define SS   512
#define HH   1024
#define G4   4096
#define NCTA 128
#define PADK 136

typedef unsigned int u32;

// ---------------- device scratch (no runtime allocation) ---------------------
__device__ float g_P0[BB * SS * G4];
__device__ float g_P1[BB * SS * G4];
__device__ float g_Hout[BB * SS * HH];
__device__ __nv_bfloat16 g_Wth[3ULL * G4 * HH];   // [mat][col 0..4095][k] hi
__device__ __nv_bfloat16 g_Wtl[3ULL * G4 * HH];   // lo
__device__ __nv_bfloat16 g_h0h[2][BB * HH], g_h0l[2][BB * HH];
__device__ __nv_bfloat16 g_h1h[2][BB * HH], g_h1l[2][BB * HH];
__device__ unsigned g_bar;

__device__ __forceinline__ float4 ldg4(const float* p)  { return __ldg((const float4*)p); }
__device__ __forceinline__ float sigf(float x) { return 1.0f / (1.0f + __expf(-x)); }
__device__ __forceinline__ float tanha(float x) { return 1.0f - 2.0f / (__expf(2.0f * x) + 1.0f); }

__device__ __forceinline__ void mma16816(float* c, u32 a0, u32 a1, u32 a2, u32 a3,
                                         u32 b0, u32 b1)
{
    asm volatile(
        "mma.sync.aligned.m16n8k16.row.col.f32.bf16.bf16.f32 "
        "{%0,%1,%2,%3}, {%4,%5,%6,%7}, {%8,%9}, {%0,%1,%2,%3};\n"
        : "+f"(c[0]), "+f"(c[1]), "+f"(c[2]), "+f"(c[3])
        : "r"(a0), "r"(a1), "r"(a2), "r"(a3), "r"(b0), "r"(b1));
}

// ---------------- init -------------------------------------------------------
__global__ void init_kernel() {
    int tid = blockIdx.x * blockDim.x + threadIdx.x;
    __nv_bfloat16 z = __float2bfloat16(0.f);
    for (int i = tid; i < BB * HH; i += gridDim.x * blockDim.x) {
        g_h0h[0][i] = z; g_h0h[1][i] = z; g_h0l[0][i] = z; g_h0l[1][i] = z;
        g_h1h[0][i] = z; g_h1h[1][i] = z; g_h1l[0][i] = z; g_h1l[1][i] = z;
    }
    if (blockIdx.x == 0 && threadIdx.x == 0) g_bar = 0u;
}

// ---------------- prep: split + transpose recurrent weights ------------------
__global__ void prep_kernel(const float* __restrict__ U0,
                            const float* __restrict__ W1,
                            const float* __restrict__ U1)
{
    size_t stride = (size_t)gridDim.x * blockDim.x;
    size_t total = 3ULL * G4 * HH;
    for (size_t idx = (size_t)blockIdx.x * blockDim.x + threadIdx.x; idx < total; idx += stride) {
        int m = (int)(idx >> 22);
        size_t r = idx & ((1ULL << 22) - 1);
        int c = (int)(r >> 10);
        int k = (int)(r & 1023);
        const float* src = (m == 0) ? U0 : ((m == 1) ? W1 : U1);
        float v = __ldg(&src[(size_t)k * G4 + c]);
        __nv_bfloat16 hi = __float2bfloat16(v);
        g_Wth[idx] = hi;
        g_Wtl[idx] = __float2bfloat16(v - __bfloat162float(hi));
    }
}

// ---------------- precompute GEMM (fp32): OUT = A1@M1 + A2@M2 + b1 + b2 ------
__global__ void __launch_bounds__(256)
gemm2_kernel(const float* __restrict__ A1, const float* __restrict__ M1, int K1,
             const float* __restrict__ A2, const float* __restrict__ M2, int K2,
             const float* __restrict__ bs1, const float* __restrict__ bs2,
             int which)
{
    float* OUT = which ? g_P1 : g_P0;
    __shared__ __align__(16) float a_sm[16][68];
    __shared__ __align__(16) float w_sm[16][68];
    const int tid = threadIdx.x;
    const int n0 = blockIdx.x * 64;
    const int m0 = blockIdx.y * 64;
    const int ar = tid >> 2, aq = tid & 3;
    const int wk = tid >> 4, wq = tid & 15;
    const int ty = tid >> 4, tx = tid & 15;

    float acc[4][4] = {};
    const int nch1 = K1 >> 4;
    const int nch  = nch1 + (K2 >> 4);

    float4 ra = ldg4(A1 + (size_t)(m0 + ar) * K1 + aq * 4);
    float4 rw = ldg4(M1 + (size_t)wk * G4 + n0 + wq * 4);

    for (int ch = 0; ch < nch; ++ch) {
        __syncthreads();
        a_sm[aq * 4 + 0][ar] = ra.x;
        a_sm[aq * 4 + 1][ar] = ra.y;
        a_sm[aq * 4 + 2][ar] = ra.z;
        a_sm[aq * 4 + 3][ar] = ra.w;
        *(float4*)&w_sm[wk][wq * 4] = rw;
        __syncthreads();
        if (ch + 1 < nch) {
            int c2 = ch + 1;
            const float* A; const float* Wm; int k0, K;
            if (c2 < nch1) { A = A1; Wm = M1; K = K1; k0 = c2 * 16; }
            else           { A = A2; Wm = M2; K = K2; k0 = (c2 - nch1) * 16; }
            ra = ldg4(A + (size_t)(m0 + ar) * K + k0 + aq * 4);
            rw = ldg4(Wm + (size_t)(k0 + wk) * G4 + n0 + wq * 4);
        }
#pragma unroll
        for (int k = 0; k < 16; ++k) {
            float4 av = *(const float4*)&a_sm[k][ty * 4];
            float4 wv = *(const float4*)&w_sm[k][tx * 4];
            acc[0][0] += av.x * wv.x; acc[0][1] += av.x * wv.y; acc[0][2] += av.x * wv.z; acc[0][3] += av.x * wv.w;
            acc[1][0] += av.y * wv.x; acc[1][1] += av.y * wv.y; acc[1][2] += av.y * wv.z; acc[1][3] += av.y * wv.w;
            acc[2][0] += av.z * wv.x; acc[2][1] += av.z * wv.y; acc[2][2] += av.z * wv.z; acc[2][3] += av.z * wv.w;
            acc[3][0] += av.w * wv.x; acc[3][1] += av.w * wv.y; acc[3][2] += av.w * wv.z; acc[3][3] += av.w * wv.w;
        }
    }
    float4 b1v = ldg4(bs1 + n0 + tx * 4);
    float4 b2v = ldg4(bs2 + n0 + tx * 4);
    float4 bsum = make_float4(b1v.x + b2v.x, b1v.y + b2v.y, b1v.z + b2v.z, b1v.w + b2v.w);
#pragma unroll
    for (int i = 0; i < 4; ++i) {
        float4 v = make_float4(acc[i][0] + bsum.x, acc[i][1] + bsum.y,
                               acc[i][2] + bsum.z, acc[i][3] + bsum.w);
        *(float4*)&OUT[(size_t)(m0 + ty * 4 + i) * G4 + n0 + tx * 4] = v;
    }
}

// ---------------- grid barrier ----------------------------------------------
__device__ __forceinline__ void gbar(unsigned& epoch)
{
    __syncthreads();
    epoch += NCTA;
    if (threadIdx.x == 0) {
        __threadfence();
        atomicAdd(&g_bar, 1u);
        while (*(volatile unsigned*)&g_bar < epoch) { }
        __threadfence();
    }
    __syncthreads();
}

// ---------------- recurrent smem layout --------------------------------------
struct RecSmem {
    __nv_bfloat16 As[2][64][PADK];   // [hi/lo][batch row][k]
    __nv_bfloat16 Bs[2][32][PADK];   // [hi/lo][cta col][k]
    float pre[32][65];
    float c0[8][65];
    float c1[8][65];
};
#define REC_SMEM_BYTES (sizeof(RecSmem))

// acc[n][4] += (h_hi+h_lo) @ (W_hi+W_lo) over K=1024 (skip lo*lo)
__device__ __forceinline__ void mma_part(
    float acc[2][4],
    const __nv_bfloat16* __restrict__ hh, const __nv_bfloat16* __restrict__ hl,
    const __nv_bfloat16* __restrict__ wth, const __nv_bfloat16* __restrict__ wtl,
    int u0, RecSmem* sm)
{
    const int tid = threadIdx.x;
    const int lane = tid & 31, w = tid >> 5;
    const int wm16 = (w >> 1) * 16;
    const int wn16 = (w & 1) * 16;
    const int g = lane >> 2, q2 = (lane & 3) * 2;

    uint4 rah[4], ral[4], rbh[2], rbl[2];

#pragma unroll
    for (int i = 0; i < 4; ++i) {
        int idx = tid + i * 256, row = idx >> 4, kq = idx & 15;
        rah[i] = __ldcg((const uint4*)(hh + row * HH + kq * 8));
        ral[i] = __ldcg((const uint4*)(hl + row * HH + kq * 8));
    }
#pragma unroll
    for (int i = 0; i < 2; ++i) {
        int idx = tid + i * 256, col = idx >> 4, kq = idx & 15;
        size_t gc = (size_t)((col >> 3) * HH + u0 + (col & 7)) * HH;
        rbh[i] = __ldg((const uint4*)(wth + gc + kq * 8));
        rbl[i] = __ldg((const uint4*)(wtl + gc + kq * 8));
    }

#pragma unroll 1
    for (int ch = 0; ch < 8; ++ch) {
#pragma unroll
        for (int i = 0; i < 4; ++i) {
            int idx = tid + i * 256, row = idx >> 4, kq = idx & 15;
            *(uint4*)&sm->As[0][row][kq * 8] = rah[i];
            *(uint4*)&sm->As[1][row][kq * 8] = ral[i];
        }
#pragma unroll
        for (int i = 0; i < 2; ++i) {
            int idx = tid + i * 256, col = idx >> 4, kq = idx & 15;
            *(uint4*)&sm->Bs[0][col][kq * 8] = rbh[i];
            *(uint4*)&sm->Bs[1][col][kq * 8] = rbl[i];
        }
        __syncthreads();
        if (ch + 1 < 8) {
            int k0 = (ch + 1) * 128;
#pragma unroll
            for (int i = 0; i < 4; ++i) {
                int idx = tid + i * 256, row = idx >> 4, kq = idx & 15;
                rah[i] = __ldcg((const uint4*)(hh + row * HH + k0 + kq * 8));
                ral[i] = __ldcg((const uint4*)(hl + row * HH + k0 + kq * 8));
            }
#pragma unroll
            for (int i = 0; i < 2; ++i) {
                int idx = tid + i * 256, col = idx >> 4, kq = idx & 15;
                size_t gc = (size_t)((col >> 3) * HH + u0 + (col & 7)) * HH;
                rbh[i] = __ldg((const uint4*)(wth + gc + k0 + kq * 8));
                rbl[i] = __ldg((const uint4*)(wtl + gc + k0 + kq * 8));
            }
        }
#pragma unroll
        for (int kk = 0; kk < 8; ++kk) {
            const int kb = kk * 16;
            u32 a0 = *(const u32*)&sm->As[0][wm16 + g][kb + q2];
            u32 a1 = *(const u32*)&sm->As[0][wm16 + g + 8][kb + q2];
            u32 a2 = *(const u32*)&sm->As[0][wm16 + g][kb + q2 + 8];
            u32 a3 = *(const u32*)&sm->As[0][wm16 + g + 8][kb + q2 + 8];
            u32 l0 = *(const u32*)&sm->As[1][wm16 + g][kb + q2];
            u32 l1 = *(const u32*)&sm->As[1][wm16 + g + 8][kb + q2];
            u32 l2 = *(const u32*)&sm->As[1][wm16 + g][kb + q2 + 8];
            u32 l3 = *(const u32*)&sm->As[1][wm16 + g + 8][kb + q2 + 8];
#pragma unroll
            for (int n = 0; n < 2; ++n) {
                int bc = wn16 + n * 8 + g;
                u32 bh0 = *(const u32*)&sm->Bs[0][bc][kb + q2];
                u32 bh1 = *(const u32*)&sm->Bs[0][bc][kb + q2 + 8];
                u32 bl0 = *(const u32*)&sm->Bs[1][bc][kb + q2];
                u32 bl1 = *(const u32*)&sm->Bs[1][bc][kb + q2 + 8];
                mma16816(acc[n], a0, a1, a2, a3, bh0, bh1);
                mma16816(acc[n], l0, l1, l2, l3, bh0, bh1);
                mma16816(acc[n], a0, a1, a2, a3, bl0, bl1);
            }
        }
        __syncthreads();
    }
}

// ---------------- persistent recurrent kernel --------------------------------
__global__ void __launch_bounds__(256, 1)
recur_kernel(float* __restrict__ out)
{
    extern __shared__ unsigned char smraw[];
    RecSmem* sm = (RecSmem*)smraw;

    const int tid = threadIdx.x;
    const int u0 = blockIdx.x * 8;
    for (int i = tid; i < 8 * 65; i += 256) {
        ((float*)sm->c0)[i] = 0.f;
        ((float*)sm->c1)[i] = 0.f;
    }
    __syncthreads();

    const int lane = tid & 31, w = tid >> 5;
    const int wm16 = (w >> 1) * 16, wn16 = (w & 1) * 16;
    const int g = lane >> 2, q2 = (lane & 3) * 2;
    const int cu = tid & 7, cb = tid >> 3;

    const __nv_bfloat16* WU0h = g_Wth;
    const __nv_bfloat16* WU0l = g_Wtl;
    const __nv_bfloat16* WW1h = g_Wth + (size_t)G4 * HH;
    const __nv_bfloat16* WW1l = g_Wtl + (size_t)G4 * HH;
    const __nv_bfloat16* WU1h = g_Wth + 2ULL * G4 * HH;
    const __nv_bfloat16* WU1l = g_Wtl + 2ULL * G4 * HH;

    unsigned epoch = 0;
    for (int t = 0; t < SS; ++t) {
        const int prv = t & 1;
        const int cur = prv ^ 1;

        // ---------- layer 0 ----------
        {
            float acc[2][4] = {};
            mma_part(acc, g_h0h[prv], g_h0l[prv], WU0h, WU0l, u0, sm);
#pragma unroll
            for (int n = 0; n < 2; ++n) {
                int gate = (wn16 >> 3) + n;
                int cc = gate * 8 + q2;
                size_t b0i = ((size_t)(wm16 + g) * SS + t) * G4 + (size_t)gate * HH + u0 + q2;
                size_t b1i = ((size_t)(wm16 + g + 8) * SS + t) * G4 + (size_t)gate * HH + u0 + q2;
                float2 p0 = *(const float2*)&g_P0[b0i];
                float2 p1 = *(const float2*)&g_P0[b1i];
                sm->pre[cc][wm16 + g]         = acc[n][0] + p0.x;
                sm->pre[cc + 1][wm16 + g]     = acc[n][1] + p0.y;
                sm->pre[cc][wm16 + g + 8]     = acc[n][2] + p1.x;
                sm->pre[cc + 1][wm16 + g + 8] = acc[n][3] + p1.y;
            }
            __syncthreads();
#pragma unroll
            for (int half = 0; half < 2; ++half) {
                int b = cb + half * 32;
                float f  = sigf(sm->pre[cu][b]);
                float ii = sigf(sm->pre[8 + cu][b]);
                float gg = tanha(sm->pre[16 + cu][b]);
                float o  = sigf(sm->pre[24 + cu][b]);
                float cn = f * sm->c0[cu][b] + ii * gg;
                sm->c0[cu][b] = cn;
                float h = o * tanha(cn);
                __nv_bfloat16 hh = __float2bfloat16(h);
                __nv_bfloat16 hl = __float2bfloat16(h - __bfloat162float(hh));
                g_h0h[cur][b * HH + u0 + cu] = hh;
                g_h0l[cur][b * HH + u0 + cu] = hl;
                if (t == SS - 1) {
                    out[98304 + b * HH + u0 + cu] = h;
                    out[229376 + b * HH + u0 + cu] = cn;
                }
            }
        }
        gbar(epoch);

        // ---------- layer 1 ----------
        {
            float acc[2][4] = {};
            mma_part(acc, g_h0h[cur], g_h0l[cur], WW1h, WW1l, u0, sm);
            mma_part(acc, g_h1h[prv], g_h1l[prv], WU1h, WU1l, u0, sm);
#pragma unroll
            for (int n = 0; n < 2; ++n) {
                int gate = (wn16 >> 3) + n;
                int cc = gate * 8 + q2;
                size_t b0i = ((size_t)(wm16 + g) * SS + t) * G4 + (size_t)gate * HH + u0 + q2;
                size_t b1i = ((size_t)(wm16 + g + 8) * SS + t) * G4 + (size_t)gate * HH + u0 + q2;
                float2 p0 = *(const float2*)&g_P1[b0i];
                float2 p1 = *(const float2*)&g_P1[b1i];
                sm->pre[cc][wm16 + g]         = acc[n][0] + p0.x;
                sm->pre[cc + 1][wm16 + g]     = acc[n][1] + p0.y;
                sm->pre[cc][wm16 + g + 8]     = acc[n][2] + p1.x;
                sm->pre[cc + 1][wm16 + g + 8] = acc[n][3] + p1.y;
            }
            __syncthreads();
#pragma unroll
            for (int half = 0; half < 2; ++half) {
                int b = cb + half * 32;
                float f  = sigf(sm->pre[cu][b]);
                float ii = sigf(sm->pre[8 + cu][b]);
                float gg = tanha(sm->pre[16 + cu][b]);
                float o  = sigf(sm->pre[24 + cu][b]);
                float cn = f * sm->c1[cu][b] + ii * gg;
                sm->c1[cu][b] = cn;
                float h = o * tanha(cn);
                __nv_bfloat16 hh = __float2bfloat16(h);
                __nv_bfloat16 hl = __float2bfloat16(h - __bfloat162float(hh));
                g_h1h[cur][b * HH + u0 + cu] = hh;
                g_h1l[cur][b * HH + u0 + cu] = hl;
                g_Hout[((size_t)b * SS + t) * HH + u0 + cu] = h;
                if (t == SS - 1) {
                    out[98304 + 65536 + b * HH + u0 + cu] = h;
                    out[229376 + 65536 + b * HH + u0 + cu] = cn;
                }
            }
        }
        gbar(epoch);
    }
}

// ---------------- output head ------------------------------------------------
__global__ void __launch_bounds__(256)
head_kernel(const float* __restrict__ fcW, const float* __restrict__ fcb,
            float* __restrict__ out)
{
    int warp = (blockIdx.x * blockDim.x + threadIdx.x) >> 5;
    int lane = threadIdx.x & 31;
    if (warp >= BB * SS) return;
    const float* hrow = &g_Hout[(size_t)warp * HH];
    float a0 = 0.f, a1 = 0.f, a2 = 0.f;
    for (int k = lane; k < HH; k += 32) {
        float h = __ldg(&hrow[k]);
        a0 += h * __ldg(&fcW[k * 3 + 0]);
        a1 += h * __ldg(&fcW[k * 3 + 1]);
        a2 += h * __ldg(&fcW[k * 3 + 2]);
    }
#pragma unroll
    for (int off = 16; off; off >>= 1) {
        a0 += __shfl_xor_sync(0xffffffffu, a0, off);
        a1 += __shfl_xor_sync(0xffffffffu, a1, off);
        a2 += __shfl_xor_sync(0xffffffffu, a2, off);
    }
    if (lane == 0) {
        out[warp * 3 + 0] = a0 + __ldg(&fcb[0]);
        out[warp * 3 + 1] = a1 + __ldg(&fcb[1]);
        out[warp * 3 + 2] = a2 + __ldg(&fcb[2]);
    }
}

extern "C" void kernel_launch(void* const* d_in, const int* in_sizes, int n_in,
                              void* d_out, int out_size)
{
    const float* x    = (const float*)d_in[0];
    const float* z    = (const float*)d_in[1];
    const float* W0   = (const float*)d_in[2];
    const float* bW0  = (const float*)d_in[3];
    const float* U0   = (const float*)d_in[4];
    const float* V0   = (const float*)d_in[5];
    const float* b0   = (const float*)d_in[6];
    const float* W1   = (const float*)d_in[7];
    const float* bW1  = (const float*)d_in[8];
    const float* U1   = (const float*)d_in[9];
    const float* V1   = (const float*)d_in[10];
    const float* b1   = (const float*)d_in[11];
    const float* fcW  = (const float*)d_in[12];
    const float* fcb  = (const float*)d_in[13];
    float* out = (float*)d_out;

    static int smem_set = 0;
    if (!smem_set) {
        cudaFuncSetAttribute(recur_kernel, cudaFuncAttributeMaxDynamicSharedMemorySize,
                             (int)REC_SMEM_BYTES);
        smem_set = 1;
    }

    init_kernel<<<256, 256>>>();
    prep_kernel<<<4096, 256>>>(U0, W1, U1);
    gemm2_kernel<<<dim3(64, 512), 256>>>(x, W0, 512, z, V0, 128, bW0, b0, 0);
    gemm2_kernel<<<dim3(64, 512), 256>>>(z, V1, 128, (const float*)0, (const float*)0, 0, bW1, b1, 1);
    recur_kernel<<<NCTA, 256, REC_SMEM_BYTES>>>(out);
    head_kernel<<<4096, 256>>>(fcW, fcb, out);
}

// round 4
// speedup vs baseline: 3.7441x; 1.7122x over previous
#include <cuda_runtime.h>
#include <cuda_fp16.h>
#include <math.h>

#define BB   64
#define SS   512
#define HH   1024
#define G4   4096
#define NCTA 128
#define KC   64
#define NCH  16
#define PK   72

typedef unsigned int u32;

// ---------------- device scratch ---------------------------------------------
__device__ float g_P0[BB * SS * G4];
__device__ float g_P1[BB * SS * G4];
__device__ float g_Hout[BB * SS * HH];
__device__ __half g_Wt[3ULL * G4 * HH];   // [mat][col][k]; mat0=U0, 1=W1, 2=U1
__device__ __half g_h0[2][BB * HH];
__device__ __half g_h1[2][BB * HH];
__device__ unsigned g_bar;

__device__ __forceinline__ float4 ldg4(const float* p)  { return __ldg((const float4*)p); }
__device__ __forceinline__ float sigf(float x)  { return 1.0f / (1.0f + __expf(-x)); }
__device__ __forceinline__ float tanha(float x) { return 1.0f - 2.0f / (__expf(2.0f * x) + 1.0f); }

__device__ __forceinline__ void mma16816(float* c, u32 a0, u32 a1, u32 a2, u32 a3,
                                         u32 b0, u32 b1)
{
    asm volatile(
        "mma.sync.aligned.m16n8k16.row.col.f32.f16.f16.f32 "
        "{%0,%1,%2,%3}, {%4,%5,%6,%7}, {%8,%9}, {%0,%1,%2,%3};\n"
        : "+f"(c[0]), "+f"(c[1]), "+f"(c[2]), "+f"(c[3])
        : "r"(a0), "r"(a1), "r"(a2), "r"(a3), "r"(b0), "r"(b1));
}

__device__ __forceinline__ void cpa16(void* dst, const void* src) {
    u32 d = (u32)__cvta_generic_to_shared(dst);
    asm volatile("cp.async.cg.shared.global [%0], [%1], 16;\n" :: "r"(d), "l"(src));
}
#define CP_COMMIT() asm volatile("cp.async.commit_group;\n" ::: "memory")

// ---------------- init -------------------------------------------------------
__global__ void init_kernel() {
    int tid = blockIdx.x * blockDim.x + threadIdx.x;
    __half z = __float2half(0.f);
    for (int i = tid; i < BB * HH; i += gridDim.x * blockDim.x) {
        g_h0[0][i] = z; g_h0[1][i] = z;
        g_h1[0][i] = z; g_h1[1][i] = z;
    }
    if (blockIdx.x == 0 && threadIdx.x == 0) g_bar = 0u;
}

// ---------------- prep: coalesced transpose to [col][k] fp16 -----------------
__global__ void __launch_bounds__(256)
prep_kernel(const float* __restrict__ U0, const float* __restrict__ W1,
            const float* __restrict__ U1)
{
    __shared__ float tile[64][65];
    int mat = blockIdx.z;
    const float* src = (mat == 0) ? U0 : ((mat == 1) ? W1 : U1);
    int c0 = blockIdx.x * 64;
    int k0 = blockIdx.y * 64;
    int tid = threadIdx.x;
#pragma unroll
    for (int i = 0; i < 4; ++i) {
        int lin = tid + i * 256;
        int kr = lin >> 4, cq = lin & 15;
        float4 v = ldg4(src + (size_t)(k0 + kr) * G4 + c0 + cq * 4);
        tile[kr][cq * 4 + 0] = v.x; tile[kr][cq * 4 + 1] = v.y;
        tile[kr][cq * 4 + 2] = v.z; tile[kr][cq * 4 + 3] = v.w;
    }
    __syncthreads();
#pragma unroll
    for (int i = 0; i < 2; ++i) {
        int lin = tid + i * 256;
        int cr = lin >> 3, seg = (lin & 7) * 8;
        __half tmp[8];
#pragma unroll
        for (int j = 0; j < 8; ++j) tmp[j] = __float2half(tile[seg + j][cr]);
        *(uint4*)(g_Wt + ((size_t)mat * G4 + c0 + cr) * HH + k0 + seg) = *(uint4*)tmp;
    }
}

// ---------------- precompute GEMM (fp32) -------------------------------------
__global__ void __launch_bounds__(256)
gemm2_kernel(const float* __restrict__ A1, const float* __restrict__ M1, int K1,
             const float* __restrict__ A2, const float* __restrict__ M2, int K2,
             const float* __restrict__ bs1, const float* __restrict__ bs2,
             int which)
{
    float* OUT = which ? g_P1 : g_P0;
    __shared__ __align__(16) float a_sm[16][68];
    __shared__ __align__(16) float w_sm[16][68];
    const int tid = threadIdx.x;
    const int n0 = blockIdx.x * 64;
    const int m0 = blockIdx.y * 64;
    const int ar = tid >> 2, aq = tid & 3;
    const int wk = tid >> 4, wq = tid & 15;
    const int ty = tid >> 4, tx = tid & 15;

    float acc[4][4] = {};
    const int nch1 = K1 >> 4;
    const int nch  = nch1 + (K2 >> 4);

    float4 ra = ldg4(A1 + (size_t)(m0 + ar) * K1 + aq * 4);
    float4 rw = ldg4(M1 + (size_t)wk * G4 + n0 + wq * 4);

    for (int ch = 0; ch < nch; ++ch) {
        __syncthreads();
        a_sm[aq * 4 + 0][ar] = ra.x;
        a_sm[aq * 4 + 1][ar] = ra.y;
        a_sm[aq * 4 + 2][ar] = ra.z;
        a_sm[aq * 4 + 3][ar] = ra.w;
        *(float4*)&w_sm[wk][wq * 4] = rw;
        __syncthreads();
        if (ch + 1 < nch) {
            int c2 = ch + 1;
            const float* A; const float* Wm; int k0, K;
            if (c2 < nch1) { A = A1; Wm = M1; K = K1; k0 = c2 * 16; }
            else           { A = A2; Wm = M2; K = K2; k0 = (c2 - nch1) * 16; }
            ra = ldg4(A + (size_t)(m0 + ar) * K + k0 + aq * 4);
            rw = ldg4(Wm + (size_t)(k0 + wk) * G4 + n0 + wq * 4);
        }
#pragma unroll
        for (int k = 0; k < 16; ++k) {
            float4 av = *(const float4*)&a_sm[k][ty * 4];
            float4 wv = *(const float4*)&w_sm[k][tx * 4];
            acc[0][0] += av.x * wv.x; acc[0][1] += av.x * wv.y; acc[0][2] += av.x * wv.z; acc[0][3] += av.x * wv.w;
            acc[1][0] += av.y * wv.x; acc[1][1] += av.y * wv.y; acc[1][2] += av.y * wv.z; acc[1][3] += av.y * wv.w;
            acc[2][0] += av.z * wv.x; acc[2][1] += av.z * wv.y; acc[2][2] += av.z * wv.z; acc[2][3] += av.z * wv.w;
            acc[3][0] += av.w * wv.x; acc[3][1] += av.w * wv.y; acc[3][2] += av.w * wv.z; acc[3][3] += av.w * wv.w;
        }
    }
    float4 b1v = ldg4(bs1 + n0 + tx * 4);
    float4 b2v = ldg4(bs2 + n0 + tx * 4);
    float4 bsum = make_float4(b1v.x + b2v.x, b1v.y + b2v.y, b1v.z + b2v.z, b1v.w + b2v.w);
#pragma unroll
    for (int i = 0; i < 4; ++i) {
        float4 v = make_float4(acc[i][0] + bsum.x, acc[i][1] + bsum.y,
                               acc[i][2] + bsum.z, acc[i][3] + bsum.w);
        *(float4*)&OUT[(size_t)(m0 + ty * 4 + i) * G4 + n0 + tx * 4] = v;
    }
}

// ---------------- grid barrier ----------------------------------------------
__device__ __forceinline__ void gbar(unsigned& epoch)
{
    __syncthreads();
    epoch += NCTA;
    if (threadIdx.x == 0) {
        __threadfence();
        atomicAdd(&g_bar, 1u);
        while (*(volatile unsigned*)&g_bar < epoch) { }
        __threadfence();
    }
    __syncthreads();
}

// ---------------- recurrent smem ---------------------------------------------
struct RecSmem {
    __half A1[3][64][PK];    // h0 chunks
    __half A2[3][64][PK];    // h1 chunks
    __half B1[3][64][PK];    // [W1slice(32) | U0slice(32)] chunks
    __half B2[3][32][PK];    // U1slice chunks
    float pre1[32][66];
    float pre0[32][66];
    float c0[8][66];
    float c1[8][66];
};
#define REC_SMEM_BYTES ((int)sizeof(RecSmem))

// ---------------- persistent recurrent kernel --------------------------------
__global__ void __launch_bounds__(256, 1)
recur_kernel(float* __restrict__ out)
{
    extern __shared__ unsigned char smraw[];
    RecSmem* sm = (RecSmem*)smraw;

    const int tid = threadIdx.x;
    const int u0 = blockIdx.x * 8;
    const int lane = tid & 31, w = tid >> 5;
    const int g = lane >> 2, q2 = (lane & 3) * 2;
    const int cu = tid & 7, cb = tid >> 3;

    // staging maps (constant per thread)
    const int lin1 = tid + 256;
    const int arow0 = tid >> 3,  aseg0 = (tid & 7) * 8;
    const int arow1 = lin1 >> 3, aseg1 = (lin1 & 7) * 8;
    const size_t offA0 = (size_t)arow0 * HH + aseg0;
    const size_t offA1 = (size_t)arow1 * HH + aseg1;
    // B1: rows 0..31 -> W1 (mat1), rows 32..63 -> U0 (mat0)
    const int jj0 = arow0 & 31, jj1 = arow1 & 31;
    const __half* pB1_0 = g_Wt + ((size_t)1 * G4 + ((jj0 >> 3) << 10) + u0 + (jj0 & 7)) * HH + aseg0;
    const __half* pB1_1 = g_Wt + ((size_t)0 * G4 + ((jj1 >> 3) << 10) + u0 + (jj1 & 7)) * HH + aseg1;
    const __half* pB2_0 = g_Wt + ((size_t)2 * G4 + ((jj0 >> 3) << 10) + u0 + (jj0 & 7)) * HH + aseg0;

    // compute maps
    const int wlo = (w < 4) ? w : (w - 4);
    const int wm = (wlo >> 1) * 32;
    const int wn = (w < 4) ? ((wlo & 1) * 32) : ((wlo & 1) * 16);

    // ---- prologue: zero cell state, compute layer0(t=0) from P0[0] ----
    for (int i = tid; i < 8 * 66; i += 256) ((float*)sm->c1)[i] = 0.f;
#pragma unroll
    for (int half = 0; half < 2; ++half) {
        int b = cb + half * 32;
        size_t base = ((size_t)b * SS) * G4 + u0 + cu;
        float pf = g_P0[base];
        float pi = g_P0[base + 1024];
        float pg = g_P0[base + 2048];
        float po = g_P0[base + 3072];
        float cn = sigf(pi) * tanha(pg);
        sm->c0[cu][b] = cn;
        float h = sigf(po) * tanha(cn);
        g_h0[0][b * HH + u0 + cu] = __float2half(h);
    }
    unsigned epoch = 0;
    gbar(epoch);

    for (int t = 0; t < SS; ++t) {
        const __half* h0r = g_h0[t & 1];
        const __half* h1r = g_h1[(t + 1) & 1];
        __half* h0w = g_h0[(t + 1) & 1];
        __half* h1w = g_h1[t & 1];

        float acc[2][4][4];
#pragma unroll
        for (int a = 0; a < 2; ++a)
#pragma unroll
            for (int b = 0; b < 4; ++b)
#pragma unroll
                for (int c = 0; c < 4; ++c) acc[a][b][c] = 0.f;

        // prologue loads: chunks 0,1
#pragma unroll
        for (int pc = 0; pc < 2; ++pc) {
            int k0 = pc * KC;
            cpa16(&sm->A1[pc][arow0][aseg0], h0r + offA0 + k0);
            cpa16(&sm->A1[pc][arow1][aseg1], h0r + offA1 + k0);
            cpa16(&sm->A2[pc][arow0][aseg0], h1r + offA0 + k0);
            cpa16(&sm->A2[pc][arow1][aseg1], h1r + offA1 + k0);
            cpa16(&sm->B1[pc][arow0][aseg0], pB1_0 + k0);
            cpa16(&sm->B1[pc][arow1][aseg1], pB1_1 + k0);
            cpa16(&sm->B2[pc][arow0][aseg0], pB2_0 + k0);
            CP_COMMIT();
        }

        for (int ch = 0; ch < NCH; ++ch) {
            if (ch < NCH - 1) asm volatile("cp.async.wait_group 1;\n" ::: "memory");
            else              asm volatile("cp.async.wait_group 0;\n" ::: "memory");
            __syncthreads();
            if (ch + 2 < NCH) {
                int buf = (ch + 2) % 3;
                int k0 = (ch + 2) * KC;
                cpa16(&sm->A1[buf][arow0][aseg0], h0r + offA0 + k0);
                cpa16(&sm->A1[buf][arow1][aseg1], h0r + offA1 + k0);
                cpa16(&sm->A2[buf][arow0][aseg0], h1r + offA0 + k0);
                cpa16(&sm->A2[buf][arow1][aseg1], h1r + offA1 + k0);
                cpa16(&sm->B1[buf][arow0][aseg0], pB1_0 + k0);
                cpa16(&sm->B1[buf][arow1][aseg1], pB1_1 + k0);
                cpa16(&sm->B2[buf][arow0][aseg0], pB2_0 + k0);
                CP_COMMIT();
            }
            const int buf = ch % 3;
            if (w < 4) {
#pragma unroll
                for (int kk = 0; kk < 4; ++kk) {
                    const int kb = kk * 16;
                    u32 a[2][4];
#pragma unroll
                    for (int mt = 0; mt < 2; ++mt) {
                        a[mt][0] = *(const u32*)&sm->A1[buf][wm + mt * 16 + g][kb + q2];
                        a[mt][1] = *(const u32*)&sm->A1[buf][wm + mt * 16 + g + 8][kb + q2];
                        a[mt][2] = *(const u32*)&sm->A1[buf][wm + mt * 16 + g][kb + q2 + 8];
                        a[mt][3] = *(const u32*)&sm->A1[buf][wm + mt * 16 + g + 8][kb + q2 + 8];
                    }
#pragma unroll
                    for (int nt = 0; nt < 4; ++nt) {
                        int bc = wn + nt * 8 + g;
                        u32 b0 = *(const u32*)&sm->B1[buf][bc][kb + q2];
                        u32 b1 = *(const u32*)&sm->B1[buf][bc][kb + q2 + 8];
                        mma16816(acc[0][nt], a[0][0], a[0][1], a[0][2], a[0][3], b0, b1);
                        mma16816(acc[1][nt], a[1][0], a[1][1], a[1][2], a[1][3], b0, b1);
                    }
                }
            } else {
#pragma unroll
                for (int kk = 0; kk < 4; ++kk) {
                    const int kb = kk * 16;
                    u32 a[2][4];
#pragma unroll
                    for (int mt = 0; mt < 2; ++mt) {
                        a[mt][0] = *(const u32*)&sm->A2[buf][wm + mt * 16 + g][kb + q2];
                        a[mt][1] = *(const u32*)&sm->A2[buf][wm + mt * 16 + g + 8][kb + q2];
                        a[mt][2] = *(const u32*)&sm->A2[buf][wm + mt * 16 + g][kb + q2 + 8];
                        a[mt][3] = *(const u32*)&sm->A2[buf][wm + mt * 16 + g + 8][kb + q2 + 8];
                    }
#pragma unroll
                    for (int nt = 0; nt < 2; ++nt) {
                        int bc = wn + nt * 8 + g;
                        u32 b0 = *(const u32*)&sm->B2[buf][bc][kb + q2];
                        u32 b1 = *(const u32*)&sm->B2[buf][bc][kb + q2 + 8];
                        mma16816(acc[0][nt], a[0][0], a[0][1], a[0][2], a[0][3], b0, b1);
                        mma16816(acc[1][nt], a[1][0], a[1][1], a[1][2], a[1][3], b0, b1);
                    }
                }
            }
        }
        __syncthreads();

        // ---- epilogue stage 1: warps 0-3 write pre1/pre0 (+P) ----
        if (w < 4) {
            const bool isL1 = (wn == 0);
#pragma unroll
            for (int mt = 0; mt < 2; ++mt) {
                int r0 = wm + mt * 16 + g;
#pragma unroll
                for (int nt = 0; nt < 4; ++nt) {
                    int cj = (wn & 31) + nt * 8 + q2;     // 0..31 within its half
                    int gate = cj >> 3, un = cj & 7;
                    if (isL1) {
                        const float* base = g_P1 + ((size_t)gate << 10) + u0 + un;
                        float2 pa = *(const float2*)(base + ((size_t)r0 * SS + t) * G4);
                        float2 pb = *(const float2*)(base + ((size_t)(r0 + 8) * SS + t) * G4);
                        sm->pre1[cj][r0]         = acc[0][nt][0] * 0.f + acc[mt][nt][0] + pa.x;
                        sm->pre1[cj + 1][r0]     = acc[mt][nt][1] + pa.y;
                        sm->pre1[cj][r0 + 8]     = acc[mt][nt][2] + pb.x;
                        sm->pre1[cj + 1][r0 + 8] = acc[mt][nt][3] + pb.y;
                    } else if (t < SS - 1) {
                        const float* base = g_P0 + ((size_t)gate << 10) + u0 + un;
                        float2 pa = *(const float2*)(base + ((size_t)r0 * SS + t + 1) * G4);
                        float2 pb = *(const float2*)(base + ((size_t)(r0 + 8) * SS + t + 1) * G4);
                        sm->pre0[cj][r0]         = acc[mt][nt][0] + pa.x;
                        sm->pre0[cj + 1][r0]     = acc[mt][nt][1] + pa.y;
                        sm->pre0[cj][r0 + 8]     = acc[mt][nt][2] + pb.x;
                        sm->pre0[cj + 1][r0 + 8] = acc[mt][nt][3] + pb.y;
                    }
                }
            }
        }
        __syncthreads();

        // ---- epilogue stage 2: warps 4-7 add U1 term into pre1 ----
        if (w >= 4) {
#pragma unroll
            for (int mt = 0; mt < 2; ++mt) {
                int r0 = wm + mt * 16 + g;
#pragma unroll
                for (int nt = 0; nt < 2; ++nt) {
                    int cj = wn + nt * 8 + q2;
                    sm->pre1[cj][r0]         += acc[mt][nt][0];
                    sm->pre1[cj + 1][r0]     += acc[mt][nt][1];
                    sm->pre1[cj][r0 + 8]     += acc[mt][nt][2];
                    sm->pre1[cj + 1][r0 + 8] += acc[mt][nt][3];
                }
            }
        }
        __syncthreads();

        // ---- cells ----
#pragma unroll
        for (int half = 0; half < 2; ++half) {
            int b = cb + half * 32;
            // layer 1 at time t
            {
                float f  = sigf(sm->pre1[cu][b]);
                float ii = sigf(sm->pre1[8 + cu][b]);
                float gg = tanha(sm->pre1[16 + cu][b]);
                float oo = sigf(sm->pre1[24 + cu][b]);
                float cn = f * sm->c1[cu][b] + ii * gg;
                sm->c1[cu][b] = cn;
                float h = oo * tanha(cn);
                h1w[b * HH + u0 + cu] = __float2half(h);
                g_Hout[((size_t)b * SS + t) * HH + u0 + cu] = h;
                if (t == SS - 1) {
                    out[98304 + 65536 + b * HH + u0 + cu] = h;
                    out[229376 + 65536 + b * HH + u0 + cu] = cn;
                }
            }
            // layer 0 at time t+1
            if (t < SS - 1) {
                float f  = sigf(sm->pre0[cu][b]);
                float ii = sigf(sm->pre0[8 + cu][b]);
                float gg = tanha(sm->pre0[16 + cu][b]);
                float oo = sigf(sm->pre0[24 + cu][b]);
                float cn = f * sm->c0[cu][b] + ii * gg;
                sm->c0[cu][b] = cn;
                float h = oo * tanha(cn);
                h0w[b * HH + u0 + cu] = __float2half(h);
                if (t == SS - 2) {
                    out[98304 + b * HH + u0 + cu] = h;
                    out[229376 + b * HH + u0 + cu] = cn;
                }
            }
        }
        gbar(epoch);
    }
}

// ---------------- output head ------------------------------------------------
__global__ void __launch_bounds__(256)
head_kernel(const float* __restrict__ fcW, const float* __restrict__ fcb,
            float* __restrict__ out)
{
    int warp = (blockIdx.x * blockDim.x + threadIdx.x) >> 5;
    int lane = threadIdx.x & 31;
    if (warp >= BB * SS) return;
    const float* hrow = &g_Hout[(size_t)warp * HH];
    float a0 = 0.f, a1 = 0.f, a2 = 0.f;
    for (int k = lane; k < HH; k += 32) {
        float h = __ldg(&hrow[k]);
        a0 += h * __ldg(&fcW[k * 3 + 0]);
        a1 += h * __ldg(&fcW[k * 3 + 1]);
        a2 += h * __ldg(&fcW[k * 3 + 2]);
    }
#pragma unroll
    for (int off = 16; off; off >>= 1) {
        a0 += __shfl_xor_sync(0xffffffffu, a0, off);
        a1 += __shfl_xor_sync(0xffffffffu, a1, off);
        a2 += __shfl_xor_sync(0xffffffffu, a2, off);
    }
    if (lane == 0) {
        out[warp * 3 + 0] = a0 + __ldg(&fcb[0]);
        out[warp * 3 + 1] = a1 + __ldg(&fcb[1]);
        out[warp * 3 + 2] = a2 + __ldg(&fcb[2]);
    }
}

extern "C" void kernel_launch(void* const* d_in, const int* in_sizes, int n_in,
                              void* d_out, int out_size)
{
    const float* x    = (const float*)d_in[0];
    const float* z    = (const float*)d_in[1];
    const float* W0   = (const float*)d_in[2];
    const float* bW0  = (const float*)d_in[3];
    const float* U0   = (const float*)d_in[4];
    const float* V0   = (const float*)d_in[5];
    const float* b0   = (const float*)d_in[6];
    const float* W1   = (const float*)d_in[7];
    const float* bW1  = (const float*)d_in[8];
    const float* U1   = (const float*)d_in[9];
    const float* V1   = (const float*)d_in[10];
    const float* b1   = (const float*)d_in[11];
    const float* fcW  = (const float*)d_in[12];
    const float* fcb  = (const float*)d_in[13];
    float* out = (float*)d_out;

    static int smem_set = 0;
    if (!smem_set) {
        cudaFuncSetAttribute(recur_kernel, cudaFuncAttributeMaxDynamicSharedMemorySize,
                             REC_SMEM_BYTES);
        smem_set = 1;
    }

    init_kernel<<<256, 256>>>();
    prep_kernel<<<dim3(64, 16, 3), 256>>>(U0, W1, U1);
    gemm2_kernel<<<dim3(64, 512), 256>>>(x, W0, 512, z, V0, 128, bW0, b0, 0);
    gemm2_kernel<<<dim3(64, 512), 256>>>(z, V1, 128, (const float*)0, (const float*)0, 0, bW1, b1, 1);
    recur_kernel<<<NCTA, 256, REC_SMEM_BYTES>>>(out);
    head_kernel<<<4096, 256>>>(fcW, fcb, out);
}

// round 6
// speedup vs baseline: 4.7207x; 1.2608x over previous
#include <cuda_runtime.h>
#include <cuda_fp16.h>
#include <cuda_bf16.h>
#include <math.h>

#define BB   64
#define SS   512
#define HH   1024
#define G4   4096
#define NCTA 128
#define KC   64
#define NCH  16
#define PK   72
#define PK2  1032
#define KA   640

typedef unsigned int u32;
typedef __nv_bfloat16 bf16;

// ---------------- device scratch ---------------------------------------------
__device__ float g_P0[BB * SS * G4];
__device__ float g_P1[BB * SS * G4];
__device__ float g_Hout[BB * SS * HH];
__device__ __half g_Wt[3ULL * G4 * HH];   // recur weights [mat][col][k] fp16
__device__ bf16 g_Ah[BB * SS * KA], g_Al[BB * SS * KA];     // [r][640] = [x|z] hi/lo
__device__ bf16 g_B0h[G4 * KA],     g_B0l[G4 * KA];         // [n][640] = [W0|V0]^T
__device__ bf16 g_B1h[G4 * 128],    g_B1l[G4 * 128];        // [n][128] = V1^T
__device__ __half g_h0[2][BB * HH];
__device__ __half g_h1[2][BB * HH];
__device__ unsigned g_bar;

__device__ __forceinline__ float4 ldg4(const float* p)  { return __ldg((const float4*)p); }
__device__ __forceinline__ float sigf(float x)  { return 1.0f / (1.0f + __expf(-x)); }
__device__ __forceinline__ float tanha(float x) { return 1.0f - 2.0f / (__expf(2.0f * x) + 1.0f); }

__device__ __forceinline__ void mma_h(float* c, u32 a0, u32 a1, u32 a2, u32 a3,
                                      u32 b0, u32 b1)
{
    asm volatile(
        "mma.sync.aligned.m16n8k16.row.col.f32.f16.f16.f32 "
        "{%0,%1,%2,%3}, {%4,%5,%6,%7}, {%8,%9}, {%0,%1,%2,%3};\n"
        : "+f"(c[0]), "+f"(c[1]), "+f"(c[2]), "+f"(c[3])
        : "r"(a0), "r"(a1), "r"(a2), "r"(a3), "r"(b0), "r"(b1));
}
__device__ __forceinline__ void mma_b(float* c, u32 a0, u32 a1, u32 a2, u32 a3,
                                      u32 b0, u32 b1)
{
    asm volatile(
        "mma.sync.aligned.m16n8k16.row.col.f32.bf16.bf16.f32 "
        "{%0,%1,%2,%3}, {%4,%5,%6,%7}, {%8,%9}, {%0,%1,%2,%3};\n"
        : "+f"(c[0]), "+f"(c[1]), "+f"(c[2]), "+f"(c[3])
        : "r"(a0), "r"(a1), "r"(a2), "r"(a3), "r"(b0), "r"(b1));
}

__device__ __forceinline__ void cpa16(void* dst, const void* src) {
    u32 d = (u32)__cvta_generic_to_shared(dst);
    asm volatile("cp.async.cg.shared.global [%0], [%1], 16;\n" :: "r"(d), "l"(src));
}
#define CP_COMMIT() asm volatile("cp.async.commit_group;\n" ::: "memory")

// ---------------- init -------------------------------------------------------
__global__ void init_kernel() {
    int tid = blockIdx.x * blockDim.x + threadIdx.x;
    __half z = __float2half(0.f);
    for (int i = tid; i < BB * HH; i += gridDim.x * blockDim.x) {
        g_h0[0][i] = z; g_h0[1][i] = z;
        g_h1[0][i] = z; g_h1[1][i] = z;
    }
    if (blockIdx.x == 0 && threadIdx.x == 0) g_bar = 0u;
}

// ---------------- prep: recur weights -> fp16 [col][k] ------------------------
__global__ void __launch_bounds__(256)
prep_kernel(const float* __restrict__ U0, const float* __restrict__ W1,
            const float* __restrict__ U1)
{
    __shared__ float tile[64][65];
    int mat = blockIdx.z;
    const float* src = (mat == 0) ? U0 : ((mat == 1) ? W1 : U1);
    int c0 = blockIdx.x * 64;
    int k0 = blockIdx.y * 64;
    int tid = threadIdx.x;
#pragma unroll
    for (int i = 0; i < 4; ++i) {
        int lin = tid + i * 256;
        int kr = lin >> 4, cq = lin & 15;
        float4 v = ldg4(src + (size_t)(k0 + kr) * G4 + c0 + cq * 4);
        tile[kr][cq * 4 + 0] = v.x; tile[kr][cq * 4 + 1] = v.y;
        tile[kr][cq * 4 + 2] = v.z; tile[kr][cq * 4 + 3] = v.w;
    }
    __syncthreads();
#pragma unroll
    for (int i = 0; i < 2; ++i) {
        int lin = tid + i * 256;
        int cr = lin >> 3, seg = (lin & 7) * 8;
        __half tmp[8];
#pragma unroll
        for (int j = 0; j < 8; ++j) tmp[j] = __float2half(tile[seg + j][cr]);
        *(uint4*)(g_Wt + ((size_t)mat * G4 + c0 + cr) * HH + k0 + seg) = *(uint4*)tmp;
    }
}

// ---------------- prep2a: A = [x|z] rows -> bf16 hi/lo [32768][640] ----------
__global__ void __launch_bounds__(256)
prep2a_kernel(const float* __restrict__ x, const float* __restrict__ z)
{
    size_t stride = (size_t)gridDim.x * blockDim.x;
    size_t total = (size_t)BB * SS * KA;
    for (size_t idx = (size_t)blockIdx.x * blockDim.x + threadIdx.x; idx < total; idx += stride) {
        size_t r = idx / KA;
        int k = (int)(idx - r * KA);
        float v = (k < 512) ? __ldg(&x[r * 512 + k]) : __ldg(&z[r * 128 + (k - 512)]);
        bf16 hi = __float2bfloat16(v);
        g_Ah[idx] = hi;
        g_Al[idx] = __float2bfloat16(v - __bfloat162float(hi));
    }
}

// ---------------- prep2b: transpose W [K x 4096] -> bf16 hi/lo [4096][ldb] ---
// which: 0 -> B0 cols 0..511 from W0 ; 1 -> B0 cols 512..639 from V0 ; 2 -> B1 from V1
__global__ void __launch_bounds__(256)
prep2b_kernel(const float* __restrict__ W, int which)
{
    __shared__ float tile[64][65];
    int n0 = blockIdx.x * 64;
    int k0 = blockIdx.y * 64;
    int tid = threadIdx.x;
#pragma unroll
    for (int i = 0; i < 4; ++i) {
        int lin = tid + i * 256;
        int kr = lin >> 4, nq = lin & 15;
        float4 v = ldg4(W + (size_t)(k0 + kr) * G4 + n0 + nq * 4);
        tile[kr][nq * 4 + 0] = v.x; tile[kr][nq * 4 + 1] = v.y;
        tile[kr][nq * 4 + 2] = v.z; tile[kr][nq * 4 + 3] = v.w;
    }
    __syncthreads();
    bf16* dsth; bf16* dstl; int ldb, kb;
    if (which == 0)      { dsth = g_B0h; dstl = g_B0l; ldb = KA;  kb = k0; }
    else if (which == 1) { dsth = g_B0h; dstl = g_B0l; ldb = KA;  kb = 512 + k0; }
    else                 { dsth = g_B1h; dstl = g_B1l; ldb = 128; kb = k0; }
#pragma unroll
    for (int i = 0; i < 2; ++i) {
        int lin = tid + i * 256;
        int nr = lin >> 3, seg = (lin & 7) * 8;
        bf16 th[8], tl[8];
#pragma unroll
        for (int j = 0; j < 8; ++j) {
            float v = tile[seg + j][nr];
            th[j] = __float2bfloat16(v);
            tl[j] = __float2bfloat16(v - __bfloat162float(th[j]));
        }
        *(uint4*)(dsth + (size_t)(n0 + nr) * ldb + kb + seg) = *(uint4*)th;
        *(uint4*)(dstl + (size_t)(n0 + nr) * ldb + kb + seg) = *(uint4*)tl;
    }
}

// ---------------- tensorized precompute GEMM ---------------------------------
// which=0: P0 = A(full 640) @ B0 + bW0+b0 ; which=1: P1 = A(z part) @ B1 + bW1+b1
struct GSmem {
    bf16 Ah[3][64][PK];
    bf16 Al[3][64][PK];
    bf16 Bh[3][64][PK];
    bf16 Bl[3][64][PK];
};
#define G_SMEM_BYTES ((int)sizeof(GSmem))

__global__ void __launch_bounds__(256, 2)
gemm_mma_kernel(int which, const float* __restrict__ bs1, const float* __restrict__ bs2)
{
    const bf16* __restrict__ Ah; const bf16* __restrict__ Al;
    const bf16* __restrict__ Bh; const bf16* __restrict__ Bl;
    int lda, ldb, K; float* OUT;
    if (which == 0) { Ah = g_Ah;       Al = g_Al;       lda = KA; Bh = g_B0h; Bl = g_B0l; ldb = KA;  K = KA;  OUT = g_P0; }
    else            { Ah = g_Ah + 512; Al = g_Al + 512; lda = KA; Bh = g_B1h; Bl = g_B1l; ldb = 128; K = 128; OUT = g_P1; }

    extern __shared__ unsigned char smraw[];
    GSmem* sm = (GSmem*)smraw;
    const int tid = threadIdx.x;
    const int n0 = blockIdx.x * 64;
    const int m0 = blockIdx.y * 64;
    const int lane = tid & 31, w = tid >> 5;
    const int g = lane >> 2, q2 = (lane & 3) * 2;
    const int wm = (w >> 2) * 32;
    const int wn = (w & 3) * 16;
    const int nch = K / KC;

    const int l0 = tid * 2, l1 = tid * 2 + 1;
    const int ar0 = l0 >> 3, as0 = (l0 & 7) * 8;
    const int ar1 = l1 >> 3, as1 = (l1 & 7) * 8;

    float acc[2][2][4];
#pragma unroll
    for (int a = 0; a < 2; ++a)
#pragma unroll
        for (int b = 0; b < 2; ++b)
#pragma unroll
            for (int c = 0; c < 4; ++c) acc[a][b][c] = 0.f;

#pragma unroll
    for (int pc = 0; pc < 2; ++pc) {
        int k0 = pc * KC;
        cpa16(&sm->Ah[pc][ar0][as0], Ah + (size_t)(m0 + ar0) * lda + k0 + as0);
        cpa16(&sm->Ah[pc][ar1][as1], Ah + (size_t)(m0 + ar1) * lda + k0 + as1);
        cpa16(&sm->Al[pc][ar0][as0], Al + (size_t)(m0 + ar0) * lda + k0 + as0);
        cpa16(&sm->Al[pc][ar1][as1], Al + (size_t)(m0 + ar1) * lda + k0 + as1);
        cpa16(&sm->Bh[pc][ar0][as0], Bh + (size_t)(n0 + ar0) * ldb + k0 + as0);
        cpa16(&sm->Bh[pc][ar1][as1], Bh + (size_t)(n0 + ar1) * ldb + k0 + as1);
        cpa16(&sm->Bl[pc][ar0][as0], Bl + (size_t)(n0 + ar0) * ldb + k0 + as0);
        cpa16(&sm->Bl[pc][ar1][as1], Bl + (size_t)(n0 + ar1) * ldb + k0 + as1);
        CP_COMMIT();
    }

    for (int ch = 0; ch < nch; ++ch) {
        if (ch < nch - 1) asm volatile("cp.async.wait_group 1;\n" ::: "memory");
        else              asm volatile("cp.async.wait_group 0;\n" ::: "memory");
        __syncthreads();
        if (ch + 2 < nch) {
            int buf = (ch + 2) % 3;
            int k0 = (ch + 2) * KC;
            cpa16(&sm->Ah[buf][ar0][as0], Ah + (size_t)(m0 + ar0) * lda + k0 + as0);
            cpa16(&sm->Ah[buf][ar1][as1], Ah + (size_t)(m0 + ar1) * lda + k0 + as1);
            cpa16(&sm->Al[buf][ar0][as0], Al + (size_t)(m0 + ar0) * lda + k0 + as0);
            cpa16(&sm->Al[buf][ar1][as1], Al + (size_t)(m0 + ar1) * lda + k0 + as1);
            cpa16(&sm->Bh[buf][ar0][as0], Bh + (size_t)(n0 + ar0) * ldb + k0 + as0);
            cpa16(&sm->Bh[buf][ar1][as1], Bh + (size_t)(n0 + ar1) * ldb + k0 + as1);
            cpa16(&sm->Bl[buf][ar0][as0], Bl + (size_t)(n0 + ar0) * ldb + k0 + as0);
            cpa16(&sm->Bl[buf][ar1][as1], Bl + (size_t)(n0 + ar1) * ldb + k0 + as1);
            CP_COMMIT();
        }
        const int buf = ch % 3;
#pragma unroll
        for (int kk = 0; kk < 4; ++kk) {
            const int kb = kk * 16;
            u32 ah[2][4], al[2][4];
#pragma unroll
            for (int mt = 0; mt < 2; ++mt) {
                int r = wm + mt * 16 + g;
                ah[mt][0] = *(const u32*)&sm->Ah[buf][r][kb + q2];
                ah[mt][1] = *(const u32*)&sm->Ah[buf][r + 8][kb + q2];
                ah[mt][2] = *(const u32*)&sm->Ah[buf][r][kb + q2 + 8];
                ah[mt][3] = *(const u32*)&sm->Ah[buf][r + 8][kb + q2 + 8];
                al[mt][0] = *(const u32*)&sm->Al[buf][r][kb + q2];
                al[mt][1] = *(const u32*)&sm->Al[buf][r + 8][kb + q2];
                al[mt][2] = *(const u32*)&sm->Al[buf][r][kb + q2 + 8];
                al[mt][3] = *(const u32*)&sm->Al[buf][r + 8][kb + q2 + 8];
            }
#pragma unroll
            for (int nt = 0; nt < 2; ++nt) {
                int bc = wn + nt * 8 + g;
                u32 bh0 = *(const u32*)&sm->Bh[buf][bc][kb + q2];
                u32 bh1 = *(const u32*)&sm->Bh[buf][bc][kb + q2 + 8];
                u32 bl0 = *(const u32*)&sm->Bl[buf][bc][kb + q2];
                u32 bl1 = *(const u32*)&sm->Bl[buf][bc][kb + q2 + 8];
#pragma unroll
                for (int mt = 0; mt < 2; ++mt) {
                    mma_b(acc[mt][nt], ah[mt][0], ah[mt][1], ah[mt][2], ah[mt][3], bh0, bh1);
                    mma_b(acc[mt][nt], al[mt][0], al[mt][1], al[mt][2], al[mt][3], bh0, bh1);
                    mma_b(acc[mt][nt], ah[mt][0], ah[mt][1], ah[mt][2], ah[mt][3], bl0, bl1);
                }
            }
        }
    }

#pragma unroll
    for (int mt = 0; mt < 2; ++mt) {
        int r0 = m0 + wm + mt * 16 + g;
#pragma unroll
        for (int nt = 0; nt < 2; ++nt) {
            int c = n0 + wn + nt * 8 + q2;
            float b0 = __ldg(&bs1[c]) + __ldg(&bs2[c]);
            float b1 = __ldg(&bs1[c + 1]) + __ldg(&bs2[c + 1]);
            OUT[(size_t)r0 * G4 + c]           = acc[mt][nt][0] + b0;
            OUT[(size_t)r0 * G4 + c + 1]       = acc[mt][nt][1] + b1;
            OUT[(size_t)(r0 + 8) * G4 + c]     = acc[mt][nt][2] + b0;
            OUT[(size_t)(r0 + 8) * G4 + c + 1] = acc[mt][nt][3] + b1;
        }
    }
}

// ---------------- grid barrier ----------------------------------------------
__device__ __forceinline__ void gbar(unsigned& epoch)
{
    __syncthreads();
    epoch += NCTA;
    if (threadIdx.x == 0) {
        __threadfence();
        atomicAdd(&g_bar, 1u);
        while (*(volatile unsigned*)&g_bar < epoch) { }
        __threadfence();
    }
    __syncthreads();
}

// ---------------- recurrent smem ---------------------------------------------
struct RecSmem {
    __half A1[3][64][PK];
    __half A2[3][64][PK];
    __half B1[3][64][PK];
    __half B2r[32][PK2];      // resident U1 slice [32 cols][1024 k]
    float pre1[32][66];
    float pre0[32][66];
    float c0[8][66];
    float c1[8][66];
};
#define REC_SMEM_BYTES ((int)sizeof(RecSmem))

// ---------------- persistent recurrent kernel --------------------------------
__global__ void __launch_bounds__(256, 1)
recur_kernel(float* __restrict__ out)
{
    extern __shared__ unsigned char smraw[];
    RecSmem* sm = (RecSmem*)smraw;

    const int tid = threadIdx.x;
    const int u0 = blockIdx.x * 8;
    const int lane = tid & 31, w = tid >> 5;
    const int g = lane >> 2, q2 = (lane & 3) * 2;
    const int cu = tid & 7, cb = tid >> 3;

    const int lin1 = tid + 256;
    const int arow0 = tid >> 3,  aseg0 = (tid & 7) * 8;
    const int arow1 = lin1 >> 3, aseg1 = (lin1 & 7) * 8;
    const size_t offA0 = (size_t)arow0 * HH + aseg0;
    const size_t offA1 = (size_t)arow1 * HH + aseg1;
    const int jj0 = arow0 & 31, jj1 = arow1 & 31;
    const __half* pB1_0 = g_Wt + ((size_t)1 * G4 + ((jj0 >> 3) << 10) + u0 + (jj0 & 7)) * HH + aseg0;
    const __half* pB1_1 = g_Wt + ((size_t)0 * G4 + ((jj1 >> 3) << 10) + u0 + (jj1 & 7)) * HH + aseg1;

    const int wlo = (w < 4) ? w : (w - 4);
    const int wm = (wlo >> 1) * 32;
    const int wn = (w < 4) ? ((wlo & 1) * 32) : ((wlo & 1) * 16);

    // ---- load resident U1 slice (constant across all steps) ----
#pragma unroll
    for (int i = 0; i < 16; ++i) {
        int lin = tid + i * 256;
        int row = lin >> 7, seg = (lin & 127) * 8;
        size_t c = ((size_t)2 * G4 + ((row >> 3) << 10) + u0 + (row & 7));
        *(uint4*)&sm->B2r[row][seg] = *(const uint4*)(g_Wt + c * HH + seg);
    }

    // ---- prologue: zero cell state, layer0(t=0) ----
    for (int i = tid; i < 8 * 66; i += 256) {
        ((float*)sm->c0)[i] = 0.f;
        ((float*)sm->c1)[i] = 0.f;
    }
    __syncthreads();
#pragma unroll
    for (int half = 0; half < 2; ++half) {
        int b = cb + half * 32;
        size_t base = ((size_t)b * SS) * G4 + u0 + cu;
        float pi = g_P0[base + 1024];
        float pg = g_P0[base + 2048];
        float po = g_P0[base + 3072];
        float cn = sigf(pi) * tanha(pg);
        sm->c0[cu][b] = cn;
        float h = sigf(po) * tanha(cn);
        g_h0[0][b * HH + u0 + cu] = __float2half(h);
    }
    unsigned epoch = 0;
    gbar(epoch);

    for (int t = 0; t < SS; ++t) {
        const __half* h0r = g_h0[t & 1];
        const __half* h1r = g_h1[(t + 1) & 1];
        __half* h0w = g_h0[(t + 1) & 1];
        __half* h1w = g_h1[t & 1];

        float acc[2][4][4];
#pragma unroll
        for (int a = 0; a < 2; ++a)
#pragma unroll
            for (int b = 0; b < 4; ++b)
#pragma unroll
                for (int c = 0; c < 4; ++c) acc[a][b][c] = 0.f;

#pragma unroll
        for (int pc = 0; pc < 2; ++pc) {
            int k0 = pc * KC;
            cpa16(&sm->A1[pc][arow0][aseg0], h0r + offA0 + k0);
            cpa16(&sm->A1[pc][arow1][aseg1], h0r + offA1 + k0);
            cpa16(&sm->A2[pc][arow0][aseg0], h1r + offA0 + k0);
            cpa16(&sm->A2[pc][arow1][aseg1], h1r + offA1 + k0);
            cpa16(&sm->B1[pc][arow0][aseg0], pB1_0 + k0);
            cpa16(&sm->B1[pc][arow1][aseg1], pB1_1 + k0);
            CP_COMMIT();
        }

        for (int ch = 0; ch < NCH; ++ch) {
            if (ch < NCH - 1) asm volatile("cp.async.wait_group 1;\n" ::: "memory");
            else              asm volatile("cp.async.wait_group 0;\n" ::: "memory");
            __syncthreads();
            if (ch + 2 < NCH) {
                int buf = (ch + 2) % 3;
                int k0 = (ch + 2) * KC;
                cpa16(&sm->A1[buf][arow0][aseg0], h0r + offA0 + k0);
                cpa16(&sm->A1[buf][arow1][aseg1], h0r + offA1 + k0);
                cpa16(&sm->A2[buf][arow0][aseg0], h1r + offA0 + k0);
                cpa16(&sm->A2[buf][arow1][aseg1], h1r + offA1 + k0);
                cpa16(&sm->B1[buf][arow0][aseg0], pB1_0 + k0);
                cpa16(&sm->B1[buf][arow1][aseg1], pB1_1 + k0);
                CP_COMMIT();
            }
            const int buf = ch % 3;
            if (w < 4) {
#pragma unroll
                for (int kk = 0; kk < 4; ++kk) {
                    const int kb = kk * 16;
                    u32 a[2][4];
#pragma unroll
                    for (int mt = 0; mt < 2; ++mt) {
                        a[mt][0] = *(const u32*)&sm->A1[buf][wm + mt * 16 + g][kb + q2];
                        a[mt][1] = *(const u32*)&sm->A1[buf][wm + mt * 16 + g + 8][kb + q2];
                        a[mt][2] = *(const u32*)&sm->A1[buf][wm + mt * 16 + g][kb + q2 + 8];
                        a[mt][3] = *(const u32*)&sm->A1[buf][wm + mt * 16 + g + 8][kb + q2 + 8];
                    }
#pragma unroll
                    for (int nt = 0; nt < 4; ++nt) {
                        int bc = wn + nt * 8 + g;
                        u32 b0 = *(const u32*)&sm->B1[buf][bc][kb + q2];
                        u32 b1 = *(const u32*)&sm->B1[buf][bc][kb + q2 + 8];
                        mma_h(acc[0][nt], a[0][0], a[0][1], a[0][2], a[0][3], b0, b1);
                        mma_h(acc[1][nt], a[1][0], a[1][1], a[1][2], a[1][3], b0, b1);
                    }
                }
            } else {
                const int kgl = ch * KC;
#pragma unroll
                for (int kk = 0; kk < 4; ++kk) {
                    const int kb = kk * 16;
                    u32 a[2][4];
#pragma unroll
                    for (int mt = 0; mt < 2; ++mt) {
                        a[mt][0] = *(const u32*)&sm->A2[buf][wm + mt * 16 + g][kb + q2];
                        a[mt][1] = *(const u32*)&sm->A2[buf][wm + mt * 16 + g + 8][kb + q2];
                        a[mt][2] = *(const u32*)&sm->A2[buf][wm + mt * 16 + g][kb + q2 + 8];
                        a[mt][3] = *(const u32*)&sm->A2[buf][wm + mt * 16 + g + 8][kb + q2 + 8];
                    }
#pragma unroll
                    for (int nt = 0; nt < 2; ++nt) {
                        int bc = wn + nt * 8 + g;
                        u32 b0 = *(const u32*)&sm->B2r[bc][kgl + kb + q2];
                        u32 b1 = *(const u32*)&sm->B2r[bc][kgl + kb + q2 + 8];
                        mma_h(acc[0][nt], a[0][0], a[0][1], a[0][2], a[0][3], b0, b1);
                        mma_h(acc[1][nt], a[1][0], a[1][1], a[1][2], a[1][3], b0, b1);
                    }
                }
            }
        }
        __syncthreads();

        // ---- epilogue stage 1: warps 0-3 write pre1/pre0 (+P) ----
        if (w < 4) {
            const bool isL1 = (wn == 0);
#pragma unroll
            for (int mt = 0; mt < 2; ++mt) {
                int r0 = wm + mt * 16 + g;
#pragma unroll
                for (int nt = 0; nt < 4; ++nt) {
                    int cj = (wn & 31) + nt * 8 + q2;
                    int gate = cj >> 3, un = cj & 7;
                    if (isL1) {
                        const float* base = g_P1 + ((size_t)gate << 10) + u0 + un;
                        float2 pa = *(const float2*)(base + ((size_t)r0 * SS + t) * G4);
                        float2 pb = *(const float2*)(base + ((size_t)(r0 + 8) * SS + t) * G4);
                        sm->pre1[cj][r0]         = acc[mt][nt][0] + pa.x;
                        sm->pre1[cj + 1][r0]     = acc[mt][nt][1] + pa.y;
                        sm->pre1[cj][r0 + 8]     = acc[mt][nt][2] + pb.x;
                        sm->pre1[cj + 1][r0 + 8] = acc[mt][nt][3] + pb.y;
                    } else if (t < SS - 1) {
                        const float* base = g_P0 + ((size_t)gate << 10) + u0 + un;
                        float2 pa = *(const float2*)(base + ((size_t)r0 * SS + t + 1) * G4);
                        float2 pb = *(const float2*)(base + ((size_t)(r0 + 8) * SS + t + 1) * G4);
                        sm->pre0[cj][r0]         = acc[mt][nt][0] + pa.x;
                        sm->pre0[cj + 1][r0]     = acc[mt][nt][1] + pa.y;
                        sm->pre0[cj][r0 + 8]     = acc[mt][nt][2] + pb.x;
                        sm->pre0[cj + 1][r0 + 8] = acc[mt][nt][3] + pb.y;
                    }
                }
            }
        }
        __syncthreads();

        // ---- epilogue stage 2: warps 4-7 add U1 term into pre1 ----
        if (w >= 4) {
#pragma unroll
            for (int mt = 0; mt < 2; ++mt) {
                int r0 = wm + mt * 16 + g;
#pragma unroll
                for (int nt = 0; nt < 2; ++nt) {
                    int cj = wn + nt * 8 + q2;
                    sm->pre1[cj][r0]         += acc[mt][nt][0];
                    sm->pre1[cj + 1][r0]     += acc[mt][nt][1];
                    sm->pre1[cj][r0 + 8]     += acc[mt][nt][2];
                    sm->pre1[cj + 1][r0 + 8] += acc[mt][nt][3];
                }
            }
        }
        __syncthreads();

        // ---- cells ----
#pragma unroll
        for (int half = 0; half < 2; ++half) {
            int b = cb + half * 32;
            {
                float f  = sigf(sm->pre1[cu][b]);
                float ii = sigf(sm->pre1[8 + cu][b]);
                float gg = tanha(sm->pre1[16 + cu][b]);
                float oo = sigf(sm->pre1[24 + cu][b]);
                float cn = f * sm->c1[cu][b] + ii * gg;
                sm->c1[cu][b] = cn;
                float h = oo * tanha(cn);
                h1w[b * HH + u0 + cu] = __float2half(h);
                g_Hout[((size_t)b * SS + t) * HH + u0 + cu] = h;
                if (t == SS - 1) {
                    out[98304 + 65536 + b * HH + u0 + cu] = h;
                    out[229376 + 65536 + b * HH + u0 + cu] = cn;
                }
            }
            if (t < SS - 1) {
                float f  = sigf(sm->pre0[cu][b]);
                float ii = sigf(sm->pre0[8 + cu][b]);
                float gg = tanha(sm->pre0[16 + cu][b]);
                float oo = sigf(sm->pre0[24 + cu][b]);
                float cn = f * sm->c0[cu][b] + ii * gg;
                sm->c0[cu][b] = cn;
                float h = oo * tanha(cn);
                h0w[b * HH + u0 + cu] = __float2half(h);
                if (t == SS - 2) {
                    out[98304 + b * HH + u0 + cu] = h;
                    out[229376 + b * HH + u0 + cu] = cn;
                }
            }
        }
        gbar(epoch);
    }
}

// ---------------- output head ------------------------------------------------
__global__ void __launch_bounds__(256)
head_kernel(const float* __restrict__ fcW, const float* __restrict__ fcb,
            float* __restrict__ out)
{
    int warp = (blockIdx.x * blockDim.x + threadIdx.x) >> 5;
    int lane = threadIdx.x & 31;
    if (warp >= BB * SS) return;
    const float* hrow = &g_Hout[(size_t)warp * HH];
    float a0 = 0.f, a1 = 0.f, a2 = 0.f;
    for (int k = lane; k < HH; k += 32) {
        float h = __ldg(&hrow[k]);
        a0 += h * __ldg(&fcW[k * 3 + 0]);
        a1 += h * __ldg(&fcW[k * 3 + 1]);
        a2 += h * __ldg(&fcW[k * 3 + 2]);
    }
#pragma unroll
    for (int off = 16; off; off >>= 1) {
        a0 += __shfl_xor_sync(0xffffffffu, a0, off);
        a1 += __shfl_xor_sync(0xffffffffu, a1, off);
        a2 += __shfl_xor_sync(0xffffffffu, a2, off);
    }
    if (lane == 0) {
        out[warp * 3 + 0] = a0 + __ldg(&fcb[0]);
        out[warp * 3 + 1] = a1 + __ldg(&fcb[1]);
        out[warp * 3 + 2] = a2 + __ldg(&fcb[2]);
    }
}

extern "C" void kernel_launch(void* const* d_in, const int* in_sizes, int n_in,
                              void* d_out, int out_size)
{
    const float* x    = (const float*)d_in[0];
    const float* z    = (const float*)d_in[1];
    const float* W0   = (const float*)d_in[2];
    const float* bW0  = (const float*)d_in[3];
    const float* U0   = (const float*)d_in[4];
    const float* V0   = (const float*)d_in[5];
    const float* b0   = (const float*)d_in[6];
    const float* W1   = (const float*)d_in[7];
    const float* bW1  = (const float*)d_in[8];
    const float* U1   = (const float*)d_in[9];
    const float* V1   = (const float*)d_in[10];
    const float* b1   = (const float*)d_in[11];
    const float* fcW  = (const float*)d_in[12];
    const float* fcb  = (const float*)d_in[13];
    float* out = (float*)d_out;

    static int smem_set = 0;
    if (!smem_set) {
        cudaFuncSetAttribute(recur_kernel, cudaFuncAttributeMaxDynamicSharedMemorySize,
                             REC_SMEM_BYTES);
        cudaFuncSetAttribute(gemm_mma_kernel, cudaFuncAttributeMaxDynamicSharedMemorySize,
                             G_SMEM_BYTES);
        smem_set = 1;
    }

    init_kernel<<<256, 256>>>();
    prep_kernel<<<dim3(64, 16, 3), 256>>>(U0, W1, U1);
    prep2a_kernel<<<2048, 256>>>(x, z);
    prep2b_kernel<<<dim3(64, 8), 256>>>(W0, 0);
    prep2b_kernel<<<dim3(64, 2), 256>>>(V0, 1);
    prep2b_kernel<<<dim3(64, 2), 256>>>(V1, 2);
    gemm_mma_kernel<<<dim3(64, 512), 256, G_SMEM_BYTES>>>(0, bW0, b0);
    gemm_mma_kernel<<<dim3(64, 512), 256, G_SMEM_BYTES>>>(1, bW1, b1);
    recur_kernel<<<NCTA, 256, REC_SMEM_BYTES>>>(out);
    head_kernel<<<4096, 256>>>(fcW, fcb, out);
}

// round 7
// speedup vs baseline: 4.9020x; 1.0384x over previous
#include <cuda_runtime.h>
#include <cuda_fp16.h>
#include <cuda_bf16.h>
#include <math.h>

#define BB   64
#define SS   512
#define HH   1024
#define G4   4096
#define NCTA 128
#define KC   64
#define NCH  16
#define PK   72
#define PK2  1032
#define KA   640

typedef unsigned int u32;
typedef __nv_bfloat16 bf16;

// ---------------- device scratch ---------------------------------------------
__device__ float g_P0[BB * SS * G4];
__device__ float g_P1[BB * SS * G4];
__device__ float g_Hout[BB * SS * HH];
__device__ __half g_Wt[3ULL * G4 * HH];   // recur weights [mat][col][k] fp16
__device__ bf16 g_Ah[BB * SS * KA], g_Al[BB * SS * KA];     // [r][640] = [x|z] hi/lo
__device__ bf16 g_B0h[G4 * KA],     g_B0l[G4 * KA];         // [n][640] = [W0|V0]^T
__device__ bf16 g_B1h[G4 * 128],    g_B1l[G4 * 128];        // [n][128] = V1^T
__device__ __half g_h0[2][BB * HH];
__device__ __half g_h1[2][BB * HH];
__device__ unsigned g_bar;

__device__ __forceinline__ float4 ldg4(const float* p)  { return __ldg((const float4*)p); }
__device__ __forceinline__ float sigf(float x)  { return 1.0f / (1.0f + __expf(-x)); }
__device__ __forceinline__ float tanha(float x) { return 1.0f - 2.0f / (__expf(2.0f * x) + 1.0f); }

__device__ __forceinline__ void mma_h(float* c, u32 a0, u32 a1, u32 a2, u32 a3,
                                      u32 b0, u32 b1)
{
    asm volatile(
        "mma.sync.aligned.m16n8k16.row.col.f32.f16.f16.f32 "
        "{%0,%1,%2,%3}, {%4,%5,%6,%7}, {%8,%9}, {%0,%1,%2,%3};\n"
        : "+f"(c[0]), "+f"(c[1]), "+f"(c[2]), "+f"(c[3])
        : "r"(a0), "r"(a1), "r"(a2), "r"(a3), "r"(b0), "r"(b1));
}
__device__ __forceinline__ void mma_b(float* c, u32 a0, u32 a1, u32 a2, u32 a3,
                                      u32 b0, u32 b1)
{
    asm volatile(
        "mma.sync.aligned.m16n8k16.row.col.f32.bf16.bf16.f32 "
        "{%0,%1,%2,%3}, {%4,%5,%6,%7}, {%8,%9}, {%0,%1,%2,%3};\n"
        : "+f"(c[0]), "+f"(c[1]), "+f"(c[2]), "+f"(c[3])
        : "r"(a0), "r"(a1), "r"(a2), "r"(a3), "r"(b0), "r"(b1));
}

__device__ __forceinline__ void ldsm4(u32& r0, u32& r1, u32& r2, u32& r3, u32 a)
{
    asm volatile("ldmatrix.sync.aligned.m8n8.x4.shared.b16 {%0,%1,%2,%3}, [%4];\n"
                 : "=r"(r0), "=r"(r1), "=r"(r2), "=r"(r3) : "r"(a));
}

__device__ __forceinline__ void cpa16(void* dst, const void* src) {
    u32 d = (u32)__cvta_generic_to_shared(dst);
    asm volatile("cp.async.cg.shared.global [%0], [%1], 16;\n" :: "r"(d), "l"(src));
}
#define CP_COMMIT() asm volatile("cp.async.commit_group;\n" ::: "memory")

// ---------------- init -------------------------------------------------------
__global__ void init_kernel() {
    int tid = blockIdx.x * blockDim.x + threadIdx.x;
    __half z = __float2half(0.f);
    for (int i = tid; i < BB * HH; i += gridDim.x * blockDim.x) {
        g_h0[0][i] = z; g_h0[1][i] = z;
        g_h1[0][i] = z; g_h1[1][i] = z;
    }
    if (blockIdx.x == 0 && threadIdx.x == 0) g_bar = 0u;
}

// ---------------- prep: recur weights -> fp16 [col][k] ------------------------
__global__ void __launch_bounds__(256)
prep_kernel(const float* __restrict__ U0, const float* __restrict__ W1,
            const float* __restrict__ U1)
{
    __shared__ float tile[64][65];
    int mat = blockIdx.z;
    const float* src = (mat == 0) ? U0 : ((mat == 1) ? W1 : U1);
    int c0 = blockIdx.x * 64;
    int k0 = blockIdx.y * 64;
    int tid = threadIdx.x;
#pragma unroll
    for (int i = 0; i < 4; ++i) {
        int lin = tid + i * 256;
        int kr = lin >> 4, cq = lin & 15;
        float4 v = ldg4(src + (size_t)(k0 + kr) * G4 + c0 + cq * 4);
        tile[kr][cq * 4 + 0] = v.x; tile[kr][cq * 4 + 1] = v.y;
        tile[kr][cq * 4 + 2] = v.z; tile[kr][cq * 4 + 3] = v.w;
    }
    __syncthreads();
#pragma unroll
    for (int i = 0; i < 2; ++i) {
        int lin = tid + i * 256;
        int cr = lin >> 3, seg = (lin & 7) * 8;
        __half tmp[8];
#pragma unroll
        for (int j = 0; j < 8; ++j) tmp[j] = __float2half(tile[seg + j][cr]);
        *(uint4*)(g_Wt + ((size_t)mat * G4 + c0 + cr) * HH + k0 + seg) = *(uint4*)tmp;
    }
}

// ---------------- prep2a: A = [x|z] rows -> bf16 hi/lo [32768][640] ----------
__global__ void __launch_bounds__(256)
prep2a_kernel(const float* __restrict__ x, const float* __restrict__ z)
{
    size_t stride = (size_t)gridDim.x * blockDim.x;
    size_t total = (size_t)BB * SS * KA;
    for (size_t idx = (size_t)blockIdx.x * blockDim.x + threadIdx.x; idx < total; idx += stride) {
        size_t r = idx / KA;
        int k = (int)(idx - r * KA);
        float v = (k < 512) ? __ldg(&x[r * 512 + k]) : __ldg(&z[r * 128 + (k - 512)]);
        bf16 hi = __float2bfloat16(v);
        g_Ah[idx] = hi;
        g_Al[idx] = __float2bfloat16(v - __bfloat162float(hi));
    }
}

// ---------------- prep2b (merged): transpose -> bf16 hi/lo -------------------
// z=0 -> B0 cols 0..511 from W0 (grid.y 0..7); z=1 -> B0 cols 512..639 from V0
// (grid.y 0..1); z=2 -> B1 from V1 (grid.y 0..1)
__global__ void __launch_bounds__(256)
prep2b_kernel(const float* __restrict__ W0, const float* __restrict__ V0,
              const float* __restrict__ V1)
{
    int which = blockIdx.z;
    if (which != 0 && blockIdx.y >= 2) return;
    const float* W = (which == 0) ? W0 : ((which == 1) ? V0 : V1);
    __shared__ float tile[64][65];
    int n0 = blockIdx.x * 64;
    int k0 = blockIdx.y * 64;
    int tid = threadIdx.x;
#pragma unroll
    for (int i = 0; i < 4; ++i) {
        int lin = tid + i * 256;
        int kr = lin >> 4, nq = lin & 15;
        float4 v = ldg4(W + (size_t)(k0 + kr) * G4 + n0 + nq * 4);
        tile[kr][nq * 4 + 0] = v.x; tile[kr][nq * 4 + 1] = v.y;
        tile[kr][nq * 4 + 2] = v.z; tile[kr][nq * 4 + 3] = v.w;
    }
    __syncthreads();
    bf16* dsth; bf16* dstl; int ldb, kb;
    if (which == 0)      { dsth = g_B0h; dstl = g_B0l; ldb = KA;  kb = k0; }
    else if (which == 1) { dsth = g_B0h; dstl = g_B0l; ldb = KA;  kb = 512 + k0; }
    else                 { dsth = g_B1h; dstl = g_B1l; ldb = 128; kb = k0; }
#pragma unroll
    for (int i = 0; i < 2; ++i) {
        int lin = tid + i * 256;
        int nr = lin >> 3, seg = (lin & 7) * 8;
        bf16 th[8], tl[8];
#pragma unroll
        for (int j = 0; j < 8; ++j) {
            float v = tile[seg + j][nr];
            th[j] = __float2bfloat16(v);
            tl[j] = __float2bfloat16(v - __bfloat162float(th[j]));
        }
        *(uint4*)(dsth + (size_t)(n0 + nr) * ldb + kb + seg) = *(uint4*)th;
        *(uint4*)(dstl + (size_t)(n0 + nr) * ldb + kb + seg) = *(uint4*)tl;
    }
}

// ---------------- tensorized precompute GEMM (merged, ldmatrix) --------------
struct GSmem {
    bf16 Ah[3][64][PK];
    bf16 Al[3][64][PK];
    bf16 Bh[3][64][PK];
    bf16 Bl[3][64][PK];
};
#define G_SMEM_BYTES ((int)sizeof(GSmem))

__global__ void __launch_bounds__(256, 2)
gemm_mma_kernel(const float* __restrict__ bsA1, const float* __restrict__ bsA2,
                const float* __restrict__ bsB1, const float* __restrict__ bsB2)
{
    const int which = blockIdx.z;
    const bf16* __restrict__ Ah; const bf16* __restrict__ Al;
    const bf16* __restrict__ Bh; const bf16* __restrict__ Bl;
    const float* bs1; const float* bs2;
    int lda, ldb, K; float* OUT;
    if (which == 0) { Ah = g_Ah;       Al = g_Al;       lda = KA; Bh = g_B0h; Bl = g_B0l;
                      ldb = KA;  K = KA;  OUT = g_P0; bs1 = bsA1; bs2 = bsA2; }
    else            { Ah = g_Ah + 512; Al = g_Al + 512; lda = KA; Bh = g_B1h; Bl = g_B1l;
                      ldb = 128; K = 128; OUT = g_P1; bs1 = bsB1; bs2 = bsB2; }

    extern __shared__ unsigned char smraw[];
    GSmem* sm = (GSmem*)smraw;
    const int tid = threadIdx.x;
    const int n0 = blockIdx.x * 64;
    const int m0 = blockIdx.y * 64;
    const int lane = tid & 31, w = tid >> 5;
    const int g = lane >> 2, q2 = (lane & 3) * 2;
    const int lg = lane >> 3, lr = lane & 7;
    const int wm = (w >> 2) * 32;
    const int wn = (w & 3) * 16;
    const int nch = K / KC;

    const int l0 = tid * 2, l1 = tid * 2 + 1;
    const int ar0 = l0 >> 3, as0 = (l0 & 7) * 8;
    const int ar1 = l1 >> 3, as1 = (l1 & 7) * 8;

    // ldmatrix base addrs (byte offsets into each buffer)
    const u32 bufstr = 64 * PK * 2;
    const u32 baseAh = (u32)__cvta_generic_to_shared(&sm->Ah[0][0][0]);
    const u32 baseAl = (u32)__cvta_generic_to_shared(&sm->Al[0][0][0]);
    const u32 baseBh = (u32)__cvta_generic_to_shared(&sm->Bh[0][0][0]);
    const u32 baseBl = (u32)__cvta_generic_to_shared(&sm->Bl[0][0][0]);
    const u32 offA0 = (u32)(wm + (lg & 1) * 8 + lr) * (PK * 2) + (lg >> 1) * 16;
    const u32 offA1 = offA0 + 16 * (PK * 2);
    const u32 offB  = (u32)(wn + (lg >> 1) * 8 + lr) * (PK * 2) + (lg & 1) * 16;

    float acc[2][2][4];
#pragma unroll
    for (int a = 0; a < 2; ++a)
#pragma unroll
        for (int b = 0; b < 2; ++b)
#pragma unroll
            for (int c = 0; c < 4; ++c) acc[a][b][c] = 0.f;

#pragma unroll
    for (int pc = 0; pc < 2; ++pc) {
        int k0 = pc * KC;
        cpa16(&sm->Ah[pc][ar0][as0], Ah + (size_t)(m0 + ar0) * lda + k0 + as0);
        cpa16(&sm->Ah[pc][ar1][as1], Ah + (size_t)(m0 + ar1) * lda + k0 + as1);
        cpa16(&sm->Al[pc][ar0][as0], Al + (size_t)(m0 + ar0) * lda + k0 + as0);
        cpa16(&sm->Al[pc][ar1][as1], Al + (size_t)(m0 + ar1) * lda + k0 + as1);
        cpa16(&sm->Bh[pc][ar0][as0], Bh + (size_t)(n0 + ar0) * ldb + k0 + as0);
        cpa16(&sm->Bh[pc][ar1][as1], Bh + (size_t)(n0 + ar1) * ldb + k0 + as1);
        cpa16(&sm->Bl[pc][ar0][as0], Bl + (size_t)(n0 + ar0) * ldb + k0 + as0);
        cpa16(&sm->Bl[pc][ar1][as1], Bl + (size_t)(n0 + ar1) * ldb + k0 + as1);
        CP_COMMIT();
    }

    for (int ch = 0; ch < nch; ++ch) {
        if (ch < nch - 1) asm volatile("cp.async.wait_group 1;\n" ::: "memory");
        else              asm volatile("cp.async.wait_group 0;\n" ::: "memory");
        __syncthreads();
        if (ch + 2 < nch) {
            int buf = (ch + 2) % 3;
            int k0 = (ch + 2) * KC;
            cpa16(&sm->Ah[buf][ar0][as0], Ah + (size_t)(m0 + ar0) * lda + k0 + as0);
            cpa16(&sm->Ah[buf][ar1][as1], Ah + (size_t)(m0 + ar1) * lda + k0 + as1);
            cpa16(&sm->Al[buf][ar0][as0], Al + (size_t)(m0 + ar0) * lda + k0 + as0);
            cpa16(&sm->Al[buf][ar1][as1], Al + (size_t)(m0 + ar1) * lda + k0 + as1);
            cpa16(&sm->Bh[buf][ar0][as0], Bh + (size_t)(n0 + ar0) * ldb + k0 + as0);
            cpa16(&sm->Bh[buf][ar1][as1], Bh + (size_t)(n0 + ar1) * ldb + k0 + as1);
            cpa16(&sm->Bl[buf][ar0][as0], Bl + (size_t)(n0 + ar0) * ldb + k0 + as0);
            cpa16(&sm->Bl[buf][ar1][as1], Bl + (size_t)(n0 + ar1) * ldb + k0 + as1);
            CP_COMMIT();
        }
        const int buf = ch % 3;
        const u32 bo = buf * bufstr;
#pragma unroll
        for (int kk = 0; kk < 4; ++kk) {
            const u32 kb2 = kk * 32;
            u32 ah[2][4], al[2][4], bh[4], bl[4];
            ldsm4(ah[0][0], ah[0][1], ah[0][2], ah[0][3], baseAh + bo + offA0 + kb2);
            ldsm4(ah[1][0], ah[1][1], ah[1][2], ah[1][3], baseAh + bo + offA1 + kb2);
            ldsm4(al[0][0], al[0][1], al[0][2], al[0][3], baseAl + bo + offA0 + kb2);
            ldsm4(al[1][0], al[1][1], al[1][2], al[1][3], baseAl + bo + offA1 + kb2);
            ldsm4(bh[0], bh[1], bh[2], bh[3], baseBh + bo + offB + kb2);
            ldsm4(bl[0], bl[1], bl[2], bl[3], baseBl + bo + offB + kb2);
#pragma unroll
            for (int nt = 0; nt < 2; ++nt) {
                u32 b0 = bh[nt * 2], b1 = bh[nt * 2 + 1];
                u32 c0 = bl[nt * 2], c1 = bl[nt * 2 + 1];
#pragma unroll
                for (int mt = 0; mt < 2; ++mt) {
                    mma_b(acc[mt][nt], ah[mt][0], ah[mt][1], ah[mt][2], ah[mt][3], b0, b1);
                    mma_b(acc[mt][nt], al[mt][0], al[mt][1], al[mt][2], al[mt][3], b0, b1);
                    mma_b(acc[mt][nt], ah[mt][0], ah[mt][1], ah[mt][2], ah[mt][3], c0, c1);
                }
            }
        }
    }

#pragma unroll
    for (int mt = 0; mt < 2; ++mt) {
        int r0 = m0 + wm + mt * 16 + g;
#pragma unroll
        for (int nt = 0; nt < 2; ++nt) {
            int c = n0 + wn + nt * 8 + q2;
            float b0 = __ldg(&bs1[c]) + __ldg(&bs2[c]);
            float b1 = __ldg(&bs1[c + 1]) + __ldg(&bs2[c + 1]);
            OUT[(size_t)r0 * G4 + c]           = acc[mt][nt][0] + b0;
            OUT[(size_t)r0 * G4 + c + 1]       = acc[mt][nt][1] + b1;
            OUT[(size_t)(r0 + 8) * G4 + c]     = acc[mt][nt][2] + b0;
            OUT[(size_t)(r0 + 8) * G4 + c + 1] = acc[mt][nt][3] + b1;
        }
    }
}

// ---------------- grid barrier ----------------------------------------------
__device__ __forceinline__ void gbar(unsigned& epoch)
{
    __syncthreads();
    epoch += NCTA;
    if (threadIdx.x == 0) {
        __threadfence();
        atomicAdd(&g_bar, 1u);
        while (*(volatile unsigned*)&g_bar < epoch) { }
        __threadfence();
    }
    __syncthreads();
}

// ---------------- recurrent smem ---------------------------------------------
struct RecSmem {
    __half A1[3][64][PK];
    __half A2[3][64][PK];
    __half B1[3][64][PK];
    __half B2r[32][PK2];      // resident U1 slice [32 cols][1024 k]
    float pre1[32][66];
    float pre0[32][66];
    float c0[8][66];
    float c1[8][66];
};
#define REC_SMEM_BYTES ((int)sizeof(RecSmem))

// ---------------- persistent recurrent kernel --------------------------------
__global__ void __launch_bounds__(256, 1)
recur_kernel(float* __restrict__ out)
{
    extern __shared__ unsigned char smraw[];
    RecSmem* sm = (RecSmem*)smraw;

    const int tid = threadIdx.x;
    const int u0 = blockIdx.x * 8;
    const int lane = tid & 31, w = tid >> 5;
    const int g = lane >> 2, q2 = (lane & 3) * 2;
    const int lg = lane >> 3, lr = lane & 7;
    const int cu = tid & 7, cb = tid >> 3;

    const int lin1 = tid + 256;
    const int arow0 = tid >> 3,  aseg0 = (tid & 7) * 8;
    const int arow1 = lin1 >> 3, aseg1 = (lin1 & 7) * 8;
    const size_t offGA0 = (size_t)arow0 * HH + aseg0;
    const size_t offGA1 = (size_t)arow1 * HH + aseg1;
    const int jj0 = arow0 & 31, jj1 = arow1 & 31;
    const __half* pB1_0 = g_Wt + ((size_t)1 * G4 + ((jj0 >> 3) << 10) + u0 + (jj0 & 7)) * HH + aseg0;
    const __half* pB1_1 = g_Wt + ((size_t)0 * G4 + ((jj1 >> 3) << 10) + u0 + (jj1 & 7)) * HH + aseg1;

    const int wlo = (w < 4) ? w : (w - 4);
    const int wm = (wlo >> 1) * 32;
    const int wn = (w < 4) ? ((wlo & 1) * 32) : ((wlo & 1) * 16);

    // ldmatrix addressing
    const u32 bufstr = 64 * PK * 2;
    const u32 baseA1 = (u32)__cvta_generic_to_shared(&sm->A1[0][0][0]);
    const u32 baseA2 = (u32)__cvta_generic_to_shared(&sm->A2[0][0][0]);
    const u32 baseB1 = (u32)__cvta_generic_to_shared(&sm->B1[0][0][0]);
    const u32 baseB2 = (u32)__cvta_generic_to_shared(&sm->B2r[0][0]);
    const u32 offA_0 = (u32)(wm + (lg & 1) * 8 + lr) * (PK * 2) + (lg >> 1) * 16;
    const u32 offA_1 = offA_0 + 16 * (PK * 2);
    const u32 offB1_0 = (u32)(wn + (lg >> 1) * 8 + lr) * (PK * 2) + (lg & 1) * 16;          // nt pair 0
    const u32 offB1_1 = offB1_0 + 16 * (PK * 2);                                            // nt pair 1
    const u32 offB2  = (u32)(wn + (lg >> 1) * 8 + lr) * (PK2 * 2) + (lg & 1) * 16;

    // ---- load resident U1 slice ----
#pragma unroll
    for (int i = 0; i < 16; ++i) {
        int lin = tid + i * 256;
        int row = lin >> 7, seg = (lin & 127) * 8;
        size_t c = ((size_t)2 * G4 + ((row >> 3) << 10) + u0 + (row & 7));
        *(uint4*)&sm->B2r[row][seg] = *(const uint4*)(g_Wt + c * HH + seg);
    }

    // ---- prologue: zero cell state, layer0(t=0) ----
    for (int i = tid; i < 8 * 66; i += 256) {
        ((float*)sm->c0)[i] = 0.f;
        ((float*)sm->c1)[i] = 0.f;
    }
    __syncthreads();
#pragma unroll
    for (int half = 0; half < 2; ++half) {
        int b = cb + half * 32;
        size_t base = ((size_t)b * SS) * G4 + u0 + cu;
        float pi = g_P0[base + 1024];
        float pg = g_P0[base + 2048];
        float po = g_P0[base + 3072];
        float cn = sigf(pi) * tanha(pg);
        sm->c0[cu][b] = cn;
        float h = sigf(po) * tanha(cn);
        g_h0[0][b * HH + u0 + cu] = __float2half(h);
    }
    unsigned epoch = 0;
    gbar(epoch);

    for (int t = 0; t < SS; ++t) {
        const __half* h0r = g_h0[t & 1];
        const __half* h1r = g_h1[(t + 1) & 1];
        __half* h0w = g_h0[(t + 1) & 1];
        __half* h1w = g_h1[t & 1];

        float acc[2][4][4];
#pragma unroll
        for (int a = 0; a < 2; ++a)
#pragma unroll
            for (int b = 0; b < 4; ++b)
#pragma unroll
                for (int c = 0; c < 4; ++c) acc[a][b][c] = 0.f;

#pragma unroll
        for (int pc = 0; pc < 2; ++pc) {
            int k0 = pc * KC;
            cpa16(&sm->A1[pc][arow0][aseg0], h0r + offGA0 + k0);
            cpa16(&sm->A1[pc][arow1][aseg1], h0r + offGA1 + k0);
            cpa16(&sm->A2[pc][arow0][aseg0], h1r + offGA0 + k0);
            cpa16(&sm->A2[pc][arow1][aseg1], h1r + offGA1 + k0);
            cpa16(&sm->B1[pc][arow0][aseg0], pB1_0 + k0);
            cpa16(&sm->B1[pc][arow1][aseg1], pB1_1 + k0);
            CP_COMMIT();
        }

        for (int ch = 0; ch < NCH; ++ch) {
            if (ch < NCH - 1) asm volatile("cp.async.wait_group 1;\n" ::: "memory");
            else              asm volatile("cp.async.wait_group 0;\n" ::: "memory");
            __syncthreads();
            if (ch + 2 < NCH) {
                int buf = (ch + 2) % 3;
                int k0 = (ch + 2) * KC;
                cpa16(&sm->A1[buf][arow0][aseg0], h0r + offGA0 + k0);
                cpa16(&sm->A1[buf][arow1][aseg1], h0r + offGA1 + k0);
                cpa16(&sm->A2[buf][arow0][aseg0], h1r + offGA0 + k0);
                cpa16(&sm->A2[buf][arow1][aseg1], h1r + offGA1 + k0);
                cpa16(&sm->B1[buf][arow0][aseg0], pB1_0 + k0);
                cpa16(&sm->B1[buf][arow1][aseg1], pB1_1 + k0);
                CP_COMMIT();
            }
            const int buf = ch % 3;
            const u32 bo = buf * bufstr;
            if (w < 4) {
#pragma unroll
                for (int kk = 0; kk < 4; ++kk) {
                    const u32 kb2 = kk * 32;
                    u32 a[2][4], bA[4], bB[4];
                    ldsm4(a[0][0], a[0][1], a[0][2], a[0][3], baseA1 + bo + offA_0 + kb2);
                    ldsm4(a[1][0], a[1][1], a[1][2], a[1][3], baseA1 + bo + offA_1 + kb2);
                    ldsm4(bA[0], bA[1], bA[2], bA[3], baseB1 + bo + offB1_0 + kb2);
                    ldsm4(bB[0], bB[1], bB[2], bB[3], baseB1 + bo + offB1_1 + kb2);
#pragma unroll
                    for (int nt = 0; nt < 4; ++nt) {
                        u32 b0 = (nt < 2) ? bA[(nt & 1) * 2]     : bB[(nt & 1) * 2];
                        u32 b1 = (nt < 2) ? bA[(nt & 1) * 2 + 1] : bB[(nt & 1) * 2 + 1];
                        mma_h(acc[0][nt], a[0][0], a[0][1], a[0][2], a[0][3], b0, b1);
                        mma_h(acc[1][nt], a[1][0], a[1][1], a[1][2], a[1][3], b0, b1);
                    }
                }
            } else {
                const u32 kgl2 = (u32)(ch * KC) * 2;
#pragma unroll
                for (int kk = 0; kk < 4; ++kk) {
                    const u32 kb2 = kk * 32;
                    u32 a[2][4], bA[4];
                    ldsm4(a[0][0], a[0][1], a[0][2], a[0][3], baseA2 + bo + offA_0 + kb2);
                    ldsm4(a[1][0], a[1][1], a[1][2], a[1][3], baseA2 + bo + offA_1 + kb2);
                    ldsm4(bA[0], bA[1], bA[2], bA[3], baseB2 + offB2 + kgl2 + kb2);
#pragma unroll
                    for (int nt = 0; nt < 2; ++nt) {
                        u32 b0 = bA[nt * 2], b1 = bA[nt * 2 + 1];
                        mma_h(acc[0][nt], a[0][0], a[0][1], a[0][2], a[0][3], b0, b1);
                        mma_h(acc[1][nt], a[1][0], a[1][1], a[1][2], a[1][3], b0, b1);
                    }
                }
            }
        }
        __syncthreads();

        // ---- epilogue stage 1: warps 0-3 write pre1/pre0 (+P) ----
        if (w < 4) {
            const bool isL1 = (wn == 0);
#pragma unroll
            for (int mt = 0; mt < 2; ++mt) {
                int r0 = wm + mt * 16 + g;
#pragma unroll
                for (int nt = 0; nt < 4; ++nt) {
                    int cj = (wn & 31) + nt * 8 + q2;
                    int gate = cj >> 3, un = cj & 7;
                    if (isL1) {
                        const float* base = g_P1 + ((size_t)gate << 10) + u0 + un;
                        float2 pa = *(const float2*)(base + ((size_t)r0 * SS + t) * G4);
                        float2 pb = *(const float2*)(base + ((size_t)(r0 + 8) * SS + t) * G4);
                        sm->pre1[cj][r0]         = acc[mt][nt][0] + pa.x;
                        sm->pre1[cj + 1][r0]     = acc[mt][nt][1] + pa.y;
                        sm->pre1[cj][r0 + 8]     = acc[mt][nt][2] + pb.x;
                        sm->pre1[cj + 1][r0 + 8] = acc[mt][nt][3] + pb.y;
                    } else if (t < SS - 1) {
                        const float* base = g_P0 + ((size_t)gate << 10) + u0 + un;
                        float2 pa = *(const float2*)(base + ((size_t)r0 * SS + t + 1) * G4);
                        float2 pb = *(const float2*)(base + ((size_t)(r0 + 8) * SS + t + 1) * G4);
                        sm->pre0[cj][r0]         = acc[mt][nt][0] + pa.x;
                        sm->pre0[cj + 1][r0]     = acc[mt][nt][1] + pa.y;
                        sm->pre0[cj][r0 + 8]     = acc[mt][nt][2] + pb.x;
                        sm->pre0[cj + 1][r0 + 8] = acc[mt][nt][3] + pb.y;
                    }
                }
            }
        }
        __syncthreads();

        // ---- epilogue stage 2: warps 4-7 add U1 term into pre1 ----
        if (w >= 4) {
#pragma unroll
            for (int mt = 0; mt < 2; ++mt) {
                int r0 = wm + mt * 16 + g;
#pragma unroll
                for (int nt = 0; nt < 2; ++nt) {
                    int cj = wn + nt * 8 + q2;
                    sm->pre1[cj][r0]         += acc[mt][nt][0];
                    sm->pre1[cj + 1][r0]     += acc[mt][nt][1];
                    sm->pre1[cj][r0 + 8]     += acc[mt][nt][2];
                    sm->pre1[cj + 1][r0 + 8] += acc[mt][nt][3];
                }
            }
        }
        __syncthreads();

        // ---- cells ----
#pragma unroll
        for (int half = 0; half < 2; ++half) {
            int b = cb + half * 32;
            {
                float f  = sigf(sm->pre1[cu][b]);
                float ii = sigf(sm->pre1[8 + cu][b]);
                float gg = tanha(sm->pre1[16 + cu][b]);
                float oo = sigf(sm->pre1[24 + cu][b]);
                float cn = f * sm->c1[cu][b] + ii * gg;
                sm->c1[cu][b] = cn;
                float h = oo * tanha(cn);
                h1w[b * HH + u0 + cu] = __float2half(h);
                g_Hout[((size_t)b * SS + t) * HH + u0 + cu] = h;
                if (t == SS - 1) {
                    out[98304 + 65536 + b * HH + u0 + cu] = h;
                    out[229376 + 65536 + b * HH + u0 + cu] = cn;
                }
            }
            if (t < SS - 1) {
                float f  = sigf(sm->pre0[cu][b]);
                float ii = sigf(sm->pre0[8 + cu][b]);
                float gg = tanha(sm->pre0[16 + cu][b]);
                float oo = sigf(sm->pre0[24 + cu][b]);
                float cn = f * sm->c0[cu][b] + ii * gg;
                sm->c0[cu][b] = cn;
                float h = oo * tanha(cn);
                h0w[b * HH + u0 + cu] = __float2half(h);
                if (t == SS - 2) {
                    out[98304 + b * HH + u0 + cu] = h;
                    out[229376 + b * HH + u0 + cu] = cn;
                }
            }
        }
        gbar(epoch);
    }
}

// ---------------- output head ------------------------------------------------
__global__ void __launch_bounds__(256)
head_kernel(const float* __restrict__ fcW, const float* __restrict__ fcb,
            float* __restrict__ out)
{
    int warp = (blockIdx.x * blockDim.x + threadIdx.x) >> 5;
    int lane = threadIdx.x & 31;
    if (warp >= BB * SS) return;
    const float* hrow = &g_Hout[(size_t)warp * HH];
    float a0 = 0.f, a1 = 0.f, a2 = 0.f;
    for (int k = lane; k < HH; k += 32) {
        float h = __ldg(&hrow[k]);
        a0 += h * __ldg(&fcW[k * 3 + 0]);
        a1 += h * __ldg(&fcW[k * 3 + 1]);
        a2 += h * __ldg(&fcW[k * 3 + 2]);
    }
#pragma unroll
    for (int off = 16; off; off >>= 1) {
        a0 += __shfl_xor_sync(0xffffffffu, a0, off);
        a1 += __shfl_xor_sync(0xffffffffu, a1, off);
        a2 += __shfl_xor_sync(0xffffffffu, a2, off);
    }
    if (lane == 0) {
        out[warp * 3 + 0] = a0 + __ldg(&fcb[0]);
        out[warp * 3 + 1] = a1 + __ldg(&fcb[1]);
        out[warp * 3 + 2] = a2 + __ldg(&fcb[2]);
    }
}

extern "C" void kernel_launch(void* const* d_in, const int* in_sizes, int n_in,
                              void* d_out, int out_size)
{
    const float* x    = (const float*)d_in[0];
    const float* z    = (const float*)d_in[1];
    const float* W0   = (const float*)d_in[2];
    const float* bW0  = (const float*)d_in[3];
    const float* U0   = (const float*)d_in[4];
    const float* V0   = (const float*)d_in[5];
    const float* b0   = (const float*)d_in[6];
    const float* W1   = (const float*)d_in[7];
    const float* bW1  = (const float*)d_in[8];
    const float* U1   = (const float*)d_in[9];
    const float* V1   = (const float*)d_in[10];
    const float* b1   = (const float*)d_in[11];
    const float* fcW  = (const float*)d_in[12];
    const float* fcb  = (const float*)d_in[13];
    float* out = (float*)d_out;

    static int smem_set = 0;
    if (!smem_set) {
        cudaFuncSetAttribute(recur_kernel, cudaFuncAttributeMaxDynamicSharedMemorySize,
                             REC_SMEM_BYTES);
        cudaFuncSetAttribute(gemm_mma_kernel, cudaFuncAttributeMaxDynamicSharedMemorySize,
                             G_SMEM_BYTES);
        smem_set = 1;
    }

    init_kernel<<<256, 256>>>();                                    // launch 1
    prep_kernel<<<dim3(64, 16, 3), 256>>>(U0, W1, U1);              // launch 2
    prep2a_kernel<<<2048, 256>>>(x, z);                             // launch 3
    prep2b_kernel<<<dim3(64, 8, 3), 256>>>(W0, V0, V1);             // launch 4
    gemm_mma_kernel<<<dim3(64, 512, 2), 256, G_SMEM_BYTES>>>(bW0, b0, bW1, b1); // launch 5
    recur_kernel<<<NCTA, 256, REC_SMEM_BYTES>>>(out);               // launch 6 (ncu -s 5)
    head_kernel<<<4096, 256>>>(fcW, fcb, out);                      // launch 7
}

// round 8
// speedup vs baseline: 4.9215x; 1.0040x over previous
#include <cuda_runtime.h>
#include <cuda_fp16.h>
#include <cuda_bf16.h>
#include <math.h>

#define BB   64
#define SS   512
#define HH   1024
#define G4   4096
#define NCTA 128
#define KC   64
#define NCH  16
#define PK   72
#define PK2  1032
#define KA   640

typedef unsigned int u32;
typedef __nv_bfloat16 bf16;

// ---------------- device scratch ---------------------------------------------
__device__ float g_P0[BB * SS * G4];
__device__ float g_P1[BB * SS * G4];
__device__ float g_Hout[BB * SS * HH];
__device__ __half g_Wt[3ULL * G4 * HH];   // recur weights [mat][col][k] fp16
__device__ bf16 g_Ah[BB * SS * KA], g_Al[BB * SS * KA];     // [r][640] = [x|z] hi/lo
__device__ bf16 g_B0h[G4 * KA],     g_B0l[G4 * KA];         // [n][640] = [W0|V0]^T
__device__ bf16 g_B1h[G4 * 128],    g_B1l[G4 * 128];        // [n][128] = V1^T
__device__ __half g_h0[2][BB * HH];
__device__ __half g_h1[2][BB * HH];
__device__ unsigned g_bar;

__device__ __forceinline__ float4 ldg4(const float* p)  { return __ldg((const float4*)p); }
__device__ __forceinline__ float sigf(float x)  { return 1.0f / (1.0f + __expf(-x)); }
__device__ __forceinline__ float tanha(float x) { return 1.0f - 2.0f / (__expf(2.0f * x) + 1.0f); }

__device__ __forceinline__ void mma_h(float* c, u32 a0, u32 a1, u32 a2, u32 a3,
                                      u32 b0, u32 b1)
{
    asm volatile(
        "mma.sync.aligned.m16n8k16.row.col.f32.f16.f16.f32 "
        "{%0,%1,%2,%3}, {%4,%5,%6,%7}, {%8,%9}, {%0,%1,%2,%3};\n"
        : "+f"(c[0]), "+f"(c[1]), "+f"(c[2]), "+f"(c[3])
        : "r"(a0), "r"(a1), "r"(a2), "r"(a3), "r"(b0), "r"(b1));
}
__device__ __forceinline__ void mma_b(float* c, u32 a0, u32 a1, u32 a2, u32 a3,
                                      u32 b0, u32 b1)
{
    asm volatile(
        "mma.sync.aligned.m16n8k16.row.col.f32.bf16.bf16.f32 "
        "{%0,%1,%2,%3}, {%4,%5,%6,%7}, {%8,%9}, {%0,%1,%2,%3};\n"
        : "+f"(c[0]), "+f"(c[1]), "+f"(c[2]), "+f"(c[3])
        : "r"(a0), "r"(a1), "r"(a2), "r"(a3), "r"(b0), "r"(b1));
}

__device__ __forceinline__ void ldsm4(u32& r0, u32& r1, u32& r2, u32& r3, u32 a)
{
    asm volatile("ldmatrix.sync.aligned.m8n8.x4.shared.b16 {%0,%1,%2,%3}, [%4];\n"
                 : "=r"(r0), "=r"(r1), "=r"(r2), "=r"(r3) : "r"(a));
}

__device__ __forceinline__ void cpa16(void* dst, const void* src) {
    u32 d = (u32)__cvta_generic_to_shared(dst);
    asm volatile("cp.async.cg.shared.global [%0], [%1], 16;\n" :: "r"(d), "l"(src));
}
#define CP_COMMIT() asm volatile("cp.async.commit_group;\n" ::: "memory")

// ---------------- init -------------------------------------------------------
__global__ void init_kernel() {
    int tid = blockIdx.x * blockDim.x + threadIdx.x;
    __half z = __float2half(0.f);
    for (int i = tid; i < BB * HH; i += gridDim.x * blockDim.x) {
        g_h0[0][i] = z; g_h0[1][i] = z;
        g_h1[0][i] = z; g_h1[1][i] = z;
    }
    if (blockIdx.x == 0 && threadIdx.x == 0) g_bar = 0u;
}

// ---------------- prep: recur weights -> fp16 [col][k] ------------------------
__global__ void __launch_bounds__(256)
prep_kernel(const float* __restrict__ U0, const float* __restrict__ W1,
            const float* __restrict__ U1)
{
    __shared__ float tile[64][65];
    int mat = blockIdx.z;
    const float* src = (mat == 0) ? U0 : ((mat == 1) ? W1 : U1);
    int c0 = blockIdx.x * 64;
    int k0 = blockIdx.y * 64;
    int tid = threadIdx.x;
#pragma unroll
    for (int i = 0; i < 4; ++i) {
        int lin = tid + i * 256;
        int kr = lin >> 4, cq = lin & 15;
        float4 v = ldg4(src + (size_t)(k0 + kr) * G4 + c0 + cq * 4);
        tile[kr][cq * 4 + 0] = v.x; tile[kr][cq * 4 + 1] = v.y;
        tile[kr][cq * 4 + 2] = v.z; tile[kr][cq * 4 + 3] = v.w;
    }
    __syncthreads();
#pragma unroll
    for (int i = 0; i < 2; ++i) {
        int lin = tid + i * 256;
        int cr = lin >> 3, seg = (lin & 7) * 8;
        __half tmp[8];
#pragma unroll
        for (int j = 0; j < 8; ++j) tmp[j] = __float2half(tile[seg + j][cr]);
        *(uint4*)(g_Wt + ((size_t)mat * G4 + c0 + cr) * HH + k0 + seg) = *(uint4*)tmp;
    }
}

// ---------------- prep2a: A = [x|z] rows -> bf16 hi/lo [32768][640] ----------
__global__ void __launch_bounds__(256)
prep2a_kernel(const float* __restrict__ x, const float* __restrict__ z)
{
    size_t stride = (size_t)gridDim.x * blockDim.x;
    size_t total = (size_t)BB * SS * KA;
    for (size_t idx = (size_t)blockIdx.x * blockDim.x + threadIdx.x; idx < total; idx += stride) {
        size_t r = idx / KA;
        int k = (int)(idx - r * KA);
        float v = (k < 512) ? __ldg(&x[r * 512 + k]) : __ldg(&z[r * 128 + (k - 512)]);
        bf16 hi = __float2bfloat16(v);
        g_Ah[idx] = hi;
        g_Al[idx] = __float2bfloat16(v - __bfloat162float(hi));
    }
}

// ---------------- prep2b (merged): transpose -> bf16 hi/lo -------------------
// z=0 -> B0 cols 0..511 from W0 (grid.y 0..7); z=1 -> B0 cols 512..639 from V0
// (grid.y 0..1); z=2 -> B1 from V1 (grid.y 0..1)
__global__ void __launch_bounds__(256)
prep2b_kernel(const float* __restrict__ W0, const float* __restrict__ V0,
              const float* __restrict__ V1)
{
    int which = blockIdx.z;
    if (which != 0 && blockIdx.y >= 2) return;
    const float* W = (which == 0) ? W0 : ((which == 1) ? V0 : V1);
    __shared__ float tile[64][65];
    int n0 = blockIdx.x * 64;
    int k0 = blockIdx.y * 64;
    int tid = threadIdx.x;
#pragma unroll
    for (int i = 0; i < 4; ++i) {
        int lin = tid + i * 256;
        int kr = lin >> 4, nq = lin & 15;
        float4 v = ldg4(W + (size_t)(k0 + kr) * G4 + n0 + nq * 4);
        tile[kr][nq * 4 + 0] = v.x; tile[kr][nq * 4 + 1] = v.y;
        tile[kr][nq * 4 + 2] = v.z; tile[kr][nq * 4 + 3] = v.w;
    }
    __syncthreads();
    bf16* dsth; bf16* dstl; int ldb, kb;
    if (which == 0)      { dsth = g_B0h; dstl = g_B0l; ldb = KA;  kb = k0; }
    else if (which == 1) { dsth = g_B0h; dstl = g_B0l; ldb = KA;  kb = 512 + k0; }
    else                 { dsth = g_B1h; dstl = g_B1l; ldb = 128; kb = k0; }
#pragma unroll
    for (int i = 0; i < 2; ++i) {
        int lin = tid + i * 256;
        int nr = lin >> 3, seg = (lin & 7) * 8;
        bf16 th[8], tl[8];
#pragma unroll
        for (int j = 0; j < 8; ++j) {
            float v = tile[seg + j][nr];
            th[j] = __float2bfloat16(v);
            tl[j] = __float2bfloat16(v - __bfloat162float(th[j]));
        }
        *(uint4*)(dsth + (size_t)(n0 + nr) * ldb + kb + seg) = *(uint4*)th;
        *(uint4*)(dstl + (size_t)(n0 + nr) * ldb + kb + seg) = *(uint4*)tl;
    }
}

// ---------------- tensorized precompute GEMM (merged, ldmatrix) --------------
struct GSmem {
    bf16 Ah[3][64][PK];
    bf16 Al[3][64][PK];
    bf16 Bh[3][64][PK];
    bf16 Bl[3][64][PK];
};
#define G_SMEM_BYTES ((int)sizeof(GSmem))

__global__ void __launch_bounds__(256, 2)
gemm_mma_kernel(const float* __restrict__ bsA1, const float* __restrict__ bsA2,
                const float* __restrict__ bsB1, const float* __restrict__ bsB2)
{
    const int which = blockIdx.z;
    const bf16* __restrict__ Ah; const bf16* __restrict__ Al;
    const bf16* __restrict__ Bh; const bf16* __restrict__ Bl;
    const float* bs1; const float* bs2;
    int lda, ldb, K; float* OUT;
    if (which == 0) { Ah = g_Ah;       Al = g_Al;       lda = KA; Bh = g_B0h; Bl = g_B0l;
                      ldb = KA;  K = KA;  OUT = g_P0; bs1 = bsA1; bs2 = bsA2; }
    else            { Ah = g_Ah + 512; Al = g_Al + 512; lda = KA; Bh = g_B1h; Bl = g_B1l;
                      ldb = 128; K = 128; OUT = g_P1; bs1 = bsB1; bs2 = bsB2; }

    extern __shared__ unsigned char smraw[];
    GSmem* sm = (GSmem*)smraw;
    const int tid = threadIdx.x;
    const int n0 = blockIdx.x * 64;
    const int m0 = blockIdx.y * 64;
    const int lane = tid & 31, w = tid >> 5;
    const int g = lane >> 2, q2 = (lane & 3) * 2;
    const int lg = lane >> 3, lr = lane & 7;
    const int wm = (w >> 2) * 32;
    const int wn = (w & 3) * 16;
    const int nch = K / KC;

    const int l0 = tid * 2, l1 = tid * 2 + 1;
    const int ar0 = l0 >> 3, as0 = (l0 & 7) * 8;
    const int ar1 = l1 >> 3, as1 = (l1 & 7) * 8;

    // ldmatrix base addrs (byte offsets into each buffer)
    const u32 bufstr = 64 * PK * 2;
    const u32 baseAh = (u32)__cvta_generic_to_shared(&sm->Ah[0][0][0]);
    const u32 baseAl = (u32)__cvta_generic_to_shared(&sm->Al[0][0][0]);
    const u32 baseBh = (u32)__cvta_generic_to_shared(&sm->Bh[0][0][0]);
    const u32 baseBl = (u32)__cvta_generic_to_shared(&sm->Bl[0][0][0]);
    const u32 offA0 = (u32)(wm + (lg & 1) * 8 + lr) * (PK * 2) + (lg >> 1) * 16;
    const u32 offA1 = offA0 + 16 * (PK * 2);
    const u32 offB  = (u32)(wn + (lg >> 1) * 8 + lr) * (PK * 2) + (lg & 1) * 16;

    float acc[2][2][4];
#pragma unroll
    for (int a = 0; a < 2; ++a)
#pragma unroll
        for (int b = 0; b < 2; ++b)
#pragma unroll
            for (int c = 0; c < 4; ++c) acc[a][b][c] = 0.f;

#pragma unroll
    for (int pc = 0; pc < 2; ++pc) {
        int k0 = pc * KC;
        cpa16(&sm->Ah[pc][ar0][as0], Ah + (size_t)(m0 + ar0) * lda + k0 + as0);
        cpa16(&sm->Ah[pc][ar1][as1], Ah + (size_t)(m0 + ar1) * lda + k0 + as1);
        cpa16(&sm->Al[pc][ar0][as0], Al + (size_t)(m0 + ar0) * lda + k0 + as0);
        cpa16(&sm->Al[pc][ar1][as1], Al + (size_t)(m0 + ar1) * lda + k0 + as1);
        cpa16(&sm->Bh[pc][ar0][as0], Bh + (size_t)(n0 + ar0) * ldb + k0 + as0);
        cpa16(&sm->Bh[pc][ar1][as1], Bh + (size_t)(n0 + ar1) * ldb + k0 + as1);
        cpa16(&sm->Bl[pc][ar0][as0], Bl + (size_t)(n0 + ar0) * ldb + k0 + as0);
        cpa16(&sm->Bl[pc][ar1][as1], Bl + (size_t)(n0 + ar1) * ldb + k0 + as1);
        CP_COMMIT();
    }

    for (int ch = 0; ch < nch; ++ch) {
        if (ch < nch - 1) asm volatile("cp.async.wait_group 1;\n" ::: "memory");
        else              asm volatile("cp.async.wait_group 0;\n" ::: "memory");
        __syncthreads();
        if (ch + 2 < nch) {
            int buf = (ch + 2) % 3;
            int k0 = (ch + 2) * KC;
            cpa16(&sm->Ah[buf][ar0][as0], Ah + (size_t)(m0 + ar0) * lda + k0 + as0);
            cpa16(&sm->Ah[buf][ar1][as1], Ah + (size_t)(m0 + ar1) * lda + k0 + as1);
            cpa16(&sm->Al[buf][ar0][as0], Al + (size_t)(m0 + ar0) * lda + k0 + as0);
            cpa16(&sm->Al[buf][ar1][as1], Al + (size_t)(m0 + ar1) * lda + k0 + as1);
            cpa16(&sm->Bh[buf][ar0][as0], Bh + (size_t)(n0 + ar0) * ldb + k0 + as0);
            cpa16(&sm->Bh[buf][ar1][as1], Bh + (size_t)(n0 + ar1) * ldb + k0 + as1);
            cpa16(&sm->Bl[buf][ar0][as0], Bl + (size_t)(n0 + ar0) * ldb + k0 + as0);
            cpa16(&sm->Bl[buf][ar1][as1], Bl + (size_t)(n0 + ar1) * ldb + k0 + as1);
            CP_COMMIT();
        }
        const int buf = ch % 3;
        const u32 bo = buf * bufstr;
#pragma unroll
        for (int kk = 0; kk < 4; ++kk) {
            const u32 kb2 = kk * 32;
            u32 ah[2][4], al[2][4], bh[4], bl[4];
            ldsm4(ah[0][0], ah[0][1], ah[0][2], ah[0][3], baseAh + bo + offA0 + kb2);
            ldsm4(ah[1][0], ah[1][1], ah[1][2], ah[1][3], baseAh + bo + offA1 + kb2);
            ldsm4(al[0][0], al[0][1], al[0][2], al[0][3], baseAl + bo + offA0 + kb2);
            ldsm4(al[1][0], al[1][1], al[1][2], al[1][3], baseAl + bo + offA1 + kb2);
            ldsm4(bh[0], bh[1], bh[2], bh[3], baseBh + bo + offB + kb2);
            ldsm4(bl[0], bl[1], bl[2], bl[3], baseBl + bo + offB + kb2);
#pragma unroll
            for (int nt = 0; nt < 2; ++nt) {
                u32 b0 = bh[nt * 2], b1 = bh[nt * 2 + 1];
                u32 c0 = bl[nt * 2], c1 = bl[nt * 2 + 1];
#pragma unroll
                for (int mt = 0; mt < 2; ++mt) {
                    mma_b(acc[mt][nt], ah[mt][0], ah[mt][1], ah[mt][2], ah[mt][3], b0, b1);
                    mma_b(acc[mt][nt], al[mt][0], al[mt][1], al[mt][2], al[mt][3], b0, b1);
                    mma_b(acc[mt][nt], ah[mt][0], ah[mt][1], ah[mt][2], ah[mt][3], c0, c1);
                }
            }
        }
    }

#pragma unroll
    for (int mt = 0; mt < 2; ++mt) {
        int r0 = m0 + wm + mt * 16 + g;
#pragma unroll
        for (int nt = 0; nt < 2; ++nt) {
            int c = n0 + wn + nt * 8 + q2;
            float b0 = __ldg(&bs1[c]) + __ldg(&bs2[c]);
            float b1 = __ldg(&bs1[c + 1]) + __ldg(&bs2[c + 1]);
            OUT[(size_t)r0 * G4 + c]           = acc[mt][nt][0] + b0;
            OUT[(size_t)r0 * G4 + c + 1]       = acc[mt][nt][1] + b1;
            OUT[(size_t)(r0 + 8) * G4 + c]     = acc[mt][nt][2] + b0;
            OUT[(size_t)(r0 + 8) * G4 + c + 1] = acc[mt][nt][3] + b1;
        }
    }
}

// ---------------- grid barrier ----------------------------------------------
__device__ __forceinline__ void gbar(unsigned& epoch)
{
    __syncthreads();
    epoch += NCTA;
    if (threadIdx.x == 0) {
        __threadfence();
        atomicAdd(&g_bar, 1u);
        while (*(volatile unsigned*)&g_bar < epoch) { }
        __threadfence();
    }
    __syncthreads();
}

// ---------------- recurrent smem ---------------------------------------------
struct RecSmem {
    __half A1[3][64][PK];
    __half A2[3][64][PK];
    __half B1[3][64][PK];
    __half B2r[32][PK2];      // resident U1 slice [32 cols][1024 k]
    float pre1[32][66];
    float pre0[32][66];
    float c0[8][66];
    float c1[8][66];
};
#define REC_SMEM_BYTES ((int)sizeof(RecSmem))

// ---------------- persistent recurrent kernel --------------------------------
__global__ void __launch_bounds__(256, 1)
recur_kernel(float* __restrict__ out)
{
    extern __shared__ unsigned char smraw[];
    RecSmem* sm = (RecSmem*)smraw;

    const int tid = threadIdx.x;
    const int u0 = blockIdx.x * 8;
    const int lane = tid & 31, w = tid >> 5;
    const int g = lane >> 2, q2 = (lane & 3) * 2;
    const int lg = lane >> 3, lr = lane & 7;
    const int cu = tid & 7, cb = tid >> 3;

    const int lin1 = tid + 256;
    const int arow0 = tid >> 3,  aseg0 = (tid & 7) * 8;
    const int arow1 = lin1 >> 3, aseg1 = (lin1 & 7) * 8;
    const size_t offGA0 = (size_t)arow0 * HH + aseg0;
    const size_t offGA1 = (size_t)arow1 * HH + aseg1;
    const int jj0 = arow0 & 31, jj1 = arow1 & 31;
    const __half* pB1_0 = g_Wt + ((size_t)1 * G4 + ((jj0 >> 3) << 10) + u0 + (jj0 & 7)) * HH + aseg0;
    const __half* pB1_1 = g_Wt + ((size_t)0 * G4 + ((jj1 >> 3) << 10) + u0 + (jj1 & 7)) * HH + aseg1;

    const int wlo = (w < 4) ? w : (w - 4);
    const int wm = (wlo >> 1) * 32;
    const int wn = (w < 4) ? ((wlo & 1) * 32) : ((wlo & 1) * 16);

    // ldmatrix addressing
    const u32 bufstr = 64 * PK * 2;
    const u32 baseA1 = (u32)__cvta_generic_to_shared(&sm->A1[0][0][0]);
    const u32 baseA2 = (u32)__cvta_generic_to_shared(&sm->A2[0][0][0]);
    const u32 baseB1 = (u32)__cvta_generic_to_shared(&sm->B1[0][0][0]);
    const u32 baseB2 = (u32)__cvta_generic_to_shared(&sm->B2r[0][0]);
    const u32 offA_0 = (u32)(wm + (lg & 1) * 8 + lr) * (PK * 2) + (lg >> 1) * 16;
    const u32 offA_1 = offA_0 + 16 * (PK * 2);
    const u32 offB1_0 = (u32)(wn + (lg >> 1) * 8 + lr) * (PK * 2) + (lg & 1) * 16;          // nt pair 0
    const u32 offB1_1 = offB1_0 + 16 * (PK * 2);                                            // nt pair 1
    const u32 offB2  = (u32)(wn + (lg >> 1) * 8 + lr) * (PK2 * 2) + (lg & 1) * 16;

    // ---- load resident U1 slice ----
#pragma unroll
    for (int i = 0; i < 16; ++i) {
        int lin = tid + i * 256;
        int row = lin >> 7, seg = (lin & 127) * 8;
        size_t c = ((size_t)2 * G4 + ((row >> 3) << 10) + u0 + (row & 7));
        *(uint4*)&sm->B2r[row][seg] = *(const uint4*)(g_Wt + c * HH + seg);
    }

    // ---- prologue: zero cell state, layer0(t=0) ----
    for (int i = tid; i < 8 * 66; i += 256) {
        ((float*)sm->c0)[i] = 0.f;
        ((float*)sm->c1)[i] = 0.f;
    }
    __syncthreads();
#pragma unroll
    for (int half = 0; half < 2; ++half) {
        int b = cb + half * 32;
        size_t base = ((size_t)b * SS) * G4 + u0 + cu;
        float pi = g_P0[base + 1024];
        float pg = g_P0[base + 2048];
        float po = g_P0[base + 3072];
        float cn = sigf(pi) * tanha(pg);
        sm->c0[cu][b] = cn;
        float h = sigf(po) * tanha(cn);
        g_h0[0][b * HH + u0 + cu] = __float2half(h);
    }
    unsigned epoch = 0;
    gbar(epoch);

    for (int t = 0; t < SS; ++t) {
        const __half* h0r = g_h0[t & 1];
        const __half* h1r = g_h1[(t + 1) & 1];
        __half* h0w = g_h0[(t + 1) & 1];
        __half* h1w = g_h1[t & 1];

        float acc[2][4][4];
#pragma unroll
        for (int a = 0; a < 2; ++a)
#pragma unroll
            for (int b = 0; b < 4; ++b)
#pragma unroll
                for (int c = 0; c < 4; ++c) acc[a][b][c] = 0.f;

#pragma unroll
        for (int pc = 0; pc < 2; ++pc) {
            int k0 = pc * KC;
            cpa16(&sm->A1[pc][arow0][aseg0], h0r + offGA0 + k0);
            cpa16(&sm->A1[pc][arow1][aseg1], h0r + offGA1 + k0);
            cpa16(&sm->A2[pc][arow0][aseg0], h1r + offGA0 + k0);
            cpa16(&sm->A2[pc][arow1][aseg1], h1r + offGA1 + k0);
            cpa16(&sm->B1[pc][arow0][aseg0], pB1_0 + k0);
            cpa16(&sm->B1[pc][arow1][aseg1], pB1_1 + k0);
            CP_COMMIT();
        }

        for (int ch = 0; ch < NCH; ++ch) {
            if (ch < NCH - 1) asm volatile("cp.async.wait_group 1;\n" ::: "memory");
            else              asm volatile("cp.async.wait_group 0;\n" ::: "memory");
            __syncthreads();
            if (ch + 2 < NCH) {
                int buf = (ch + 2) % 3;
                int k0 = (ch + 2) * KC;
                cpa16(&sm->A1[buf][arow0][aseg0], h0r + offGA0 + k0);
                cpa16(&sm->A1[buf][arow1][aseg1], h0r + offGA1 + k0);
                cpa16(&sm->A2[buf][arow0][aseg0], h1r + offGA0 + k0);
                cpa16(&sm->A2[buf][arow1][aseg1], h1r + offGA1 + k0);
                cpa16(&sm->B1[buf][arow0][aseg0], pB1_0 + k0);
                cpa16(&sm->B1[buf][arow1][aseg1], pB1_1 + k0);
                CP_COMMIT();
            }
            const int buf = ch % 3;
            const u32 bo = buf * bufstr;
            if (w < 4) {
#pragma unroll
                for (int kk = 0; kk < 4; ++kk) {
                    const u32 kb2 = kk * 32;
                    u32 a[2][4], bA[4], bB[4];
                    ldsm4(a[0][0], a[0][1], a[0][2], a[0][3], baseA1 + bo + offA_0 + kb2);
                    ldsm4(a[1][0], a[1][1], a[1][2], a[1][3], baseA1 + bo + offA_1 + kb2);
                    ldsm4(bA[0], bA[1], bA[2], bA[3], baseB1 + bo + offB1_0 + kb2);
                    ldsm4(bB[0], bB[1], bB[2], bB[3], baseB1 + bo + offB1_1 + kb2);
#pragma unroll
                    for (int nt = 0; nt < 4; ++nt) {
                        u32 b0 = (nt < 2) ? bA[(nt & 1) * 2]     : bB[(nt & 1) * 2];
                        u32 b1 = (nt < 2) ? bA[(nt & 1) * 2 + 1] : bB[(nt & 1) * 2 + 1];
                        mma_h(acc[0][nt], a[0][0], a[0][1], a[0][2], a[0][3], b0, b1);
                        mma_h(acc[1][nt], a[1][0], a[1][1], a[1][2], a[1][3], b0, b1);
                    }
                }
            } else {
                const u32 kgl2 = (u32)(ch * KC) * 2;
#pragma unroll
                for (int kk = 0; kk < 4; ++kk) {
                    const u32 kb2 = kk * 32;
                    u32 a[2][4], bA[4];
                    ldsm4(a[0][0], a[0][1], a[0][2], a[0][3], baseA2 + bo + offA_0 + kb2);
                    ldsm4(a[1][0], a[1][1], a[1][2], a[1][3], baseA2 + bo + offA_1 + kb2);
                    ldsm4(bA[0], bA[1], bA[2], bA[3], baseB2 + offB2 + kgl2 + kb2);
#pragma unroll
                    for (int nt = 0; nt < 2; ++nt) {
                        u32 b0 = bA[nt * 2], b1 = bA[nt * 2 + 1];
                        mma_h(acc[0][nt], a[0][0], a[0][1], a[0][2], a[0][3], b0, b1);
                        mma_h(acc[1][nt], a[1][0], a[1][1], a[1][2], a[1][3], b0, b1);
                    }
                }
            }
        }
        __syncthreads();

        // ---- epilogue stage 1: warps 0-3 write pre1/pre0 (+P) ----
        if (w < 4) {
            const bool isL1 = (wn == 0);
#pragma unroll
            for (int mt = 0; mt < 2; ++mt) {
                int r0 = wm + mt * 16 + g;
#pragma unroll
                for (int nt = 0; nt < 4; ++nt) {
                    int cj = (wn & 31) + nt * 8 + q2;
                    int gate = cj >> 3, un = cj & 7;
                    if (isL1) {
                        const float* base = g_P1 + ((size_t)gate << 10) + u0 + un;
                        float2 pa = *(const float2*)(base + ((size_t)r0 * SS + t) * G4);
                        float2 pb = *(const float2*)(base + ((size_t)(r0 + 8) * SS + t) * G4);
                        sm->pre1[cj][r0]         = acc[mt][nt][0] + pa.x;
                        sm->pre1[cj + 1][r0]     = acc[mt][nt][1] + pa.y;
                        sm->pre1[cj][r0 + 8]     = acc[mt][nt][2] + pb.x;
                        sm->pre1[cj + 1][r0 + 8] = acc[mt][nt][3] + pb.y;
                    } else if (t < SS - 1) {
                        const float* base = g_P0 + ((size_t)gate << 10) + u0 + un;
                        float2 pa = *(const float2*)(base + ((size_t)r0 * SS + t + 1) * G4);
                        float2 pb = *(const float2*)(base + ((size_t)(r0 + 8) * SS + t + 1) * G4);
                        sm->pre0[cj][r0]         = acc[mt][nt][0] + pa.x;
                        sm->pre0[cj + 1][r0]     = acc[mt][nt][1] + pa.y;
                        sm->pre0[cj][r0 + 8]     = acc[mt][nt][2] + pb.x;
                        sm->pre0[cj + 1][r0 + 8] = acc[mt][nt][3] + pb.y;
                    }
                }
            }
        }
        __syncthreads();

        // ---- epilogue stage 2: warps 4-7 add U1 term into pre1 ----
        if (w >= 4) {
#pragma unroll
            for (int mt = 0; mt < 2; ++mt) {
                int r0 = wm + mt * 16 + g;
#pragma unroll
                for (int nt = 0; nt < 2; ++nt) {
                    int cj = wn + nt * 8 + q2;
                    sm->pre1[cj][r0]         += acc[mt][nt][0];
                    sm->pre1[cj + 1][r0]     += acc[mt][nt][1];
                    sm->pre1[cj][r0 + 8]     += acc[mt][nt][2];
                    sm->pre1[cj + 1][r0 + 8] += acc[mt][nt][3];
                }
            }
        }
        __syncthreads();

        // ---- cells ----
#pragma unroll
        for (int half = 0; half < 2; ++half) {
            int b = cb + half * 32;
            {
                float f  = sigf(sm->pre1[cu][b]);
                float ii = sigf(sm->pre1[8 + cu][b]);
                float gg = tanha(sm->pre1[16 + cu][b]);
                float oo = sigf(sm->pre1[24 + cu][b]);
                float cn = f * sm->c1[cu][b] + ii * gg;
                sm->c1[cu][b] = cn;
                float h = oo * tanha(cn);
                h1w[b * HH + u0 + cu] = __float2half(h);
                g_Hout[((size_t)b * SS + t) * HH + u0 + cu] = h;
                if (t == SS - 1) {
                    out[98304 + 65536 + b * HH + u0 + cu] = h;
                    out[229376 + 65536 + b * HH + u0 + cu] = cn;
                }
            }
            if (t < SS - 1) {
                float f  = sigf(sm->pre0[cu][b]);
                float ii = sigf(sm->pre0[8 + cu][b]);
                float gg = tanha(sm->pre0[16 + cu][b]);
                float oo = sigf(sm->pre0[24 + cu][b]);
                float cn = f * sm->c0[cu][b] + ii * gg;
                sm->c0[cu][b] = cn;
                float h = oo * tanha(cn);
                h0w[b * HH + u0 + cu] = __float2half(h);
                if (t == SS - 2) {
                    out[98304 + b * HH + u0 + cu] = h;
                    out[229376 + b * HH + u0 + cu] = cn;
                }
            }
        }
        gbar(epoch);
    }
}

// ---------------- output head ------------------------------------------------
__global__ void __launch_bounds__(256)
head_kernel(const float* __restrict__ fcW, const float* __restrict__ fcb,
            float* __restrict__ out)
{
    int warp = (blockIdx.x * blockDim.x + threadIdx.x) >> 5;
    int lane = threadIdx.x & 31;
    if (warp >= BB * SS) return;
    const float* hrow = &g_Hout[(size_t)warp * HH];
    float a0 = 0.f, a1 = 0.f, a2 = 0.f;
    for (int k = lane; k < HH; k += 32) {
        float h = __ldg(&hrow[k]);
        a0 += h * __ldg(&fcW[k * 3 + 0]);
        a1 += h * __ldg(&fcW[k * 3 + 1]);
        a2 += h * __ldg(&fcW[k * 3 + 2]);
    }
#pragma unroll
    for (int off = 16; off; off >>= 1) {
        a0 += __shfl_xor_sync(0xffffffffu, a0, off);
        a1 += __shfl_xor_sync(0xffffffffu, a1, off);
        a2 += __shfl_xor_sync(0xffffffffu, a2, off);
    }
    if (lane == 0) {
        out[warp * 3 + 0] = a0 + __ldg(&fcb[0]);
        out[warp * 3 + 1] = a1 + __ldg(&fcb[1]);
        out[warp * 3 + 2] = a2 + __ldg(&fcb[2]);
    }
}

extern "C" void kernel_launch(void* const* d_in, const int* in_sizes, int n_in,
                              void* d_out, int out_size)
{
    const float* x    = (const float*)d_in[0];
    const float* z    = (const float*)d_in[1];
    const float* W0   = (const float*)d_in[2];
    const float* bW0  = (const float*)d_in[3];
    const float* U0   = (const float*)d_in[4];
    const float* V0   = (const float*)d_in[5];
    const float* b0   = (const float*)d_in[6];
    const float* W1   = (const float*)d_in[7];
    const float* bW1  = (const float*)d_in[8];
    const float* U1   = (const float*)d_in[9];
    const float* V1   = (const float*)d_in[10];
    const float* b1   = (const float*)d_in[11];
    const float* fcW  = (const float*)d_in[12];
    const float* fcb  = (const float*)d_in[13];
    float* out = (float*)d_out;

    static int smem_set = 0;
    if (!smem_set) {
        cudaFuncSetAttribute(recur_kernel, cudaFuncAttributeMaxDynamicSharedMemorySize,
                             REC_SMEM_BYTES);
        cudaFuncSetAttribute(gemm_mma_kernel, cudaFuncAttributeMaxDynamicSharedMemorySize,
                             G_SMEM_BYTES);
        smem_set = 1;
    }

    init_kernel<<<256, 256>>>();                                    // launch 1
    prep_kernel<<<dim3(64, 16, 3), 256>>>(U0, W1, U1);              // launch 2
    prep2a_kernel<<<2048, 256>>>(x, z);                             // launch 3
    prep2b_kernel<<<dim3(64, 8, 3), 256>>>(W0, V0, V1);             // launch 4
    gemm_mma_kernel<<<dim3(64, 512, 2), 256, G_SMEM_BYTES>>>(bW0, b0, bW1, b1); // launch 5
    recur_kernel<<<NCTA, 256, REC_SMEM_BYTES>>>(out);               // launch 6 (ncu -s 5)
    head_kernel<<<4096, 256>>>(fcW, fcb, out);                      // launch 7
}

// round 10
// speedup vs baseline: 5.3037x; 1.0777x over previous
#include <cuda_runtime.h>
#include <cuda_fp16.h>
#include <cuda_bf16.h>
#include <math.h>

#define BB   64
#define SS   512
#define HH   1024
#define G4   4096
#define NCTA 128
#define KC   64
#define NCH  16
#define PK   72
#define PK2  1032
#define KA   640

typedef unsigned int u32;

__device__ float g_P0[BB * SS * G4];
__device__ float g_P1[BB * SS * G4];
__device__ float g_Hout[BB * SS * HH];
__device__ __half g_Wt[3ULL * G4 * HH];   // recur weights [mat][col][k]
__device__ __half g_A[BB * SS * KA];      // [r][640] = [x|z] fp16
__device__ __half g_B0[G4 * KA];          // [n][640] = [W0|V0]^T fp16
__device__ __half g_B1[G4 * 128];         // [n][128] = V1^T fp16
__device__ __half g_h0[2][BB * HH];
__device__ __half g_h1[2][BB * HH];
__device__ unsigned g_bar;

__device__ __forceinline__ float4 ldg4(const float* p)  { return __ldg((const float4*)p); }
__device__ __forceinline__ float sigf(float x)  { return 1.0f / (1.0f + __expf(-x)); }
__device__ __forceinline__ float tanha(float x) { return 1.0f - 2.0f / (__expf(2.0f * x) + 1.0f); }

__device__ __forceinline__ void mma_h(float* c, u32 a0, u32 a1, u32 a2, u32 a3,
                                      u32 b0, u32 b1)
{
    asm volatile(
        "mma.sync.aligned.m16n8k16.row.col.f32.f16.f16.f32 "
        "{%0,%1,%2,%3}, {%4,%5,%6,%7}, {%8,%9}, {%0,%1,%2,%3};\n"
        : "+f"(c[0]), "+f"(c[1]), "+f"(c[2]), "+f"(c[3])
        : "r"(a0), "r"(a1), "r"(a2), "r"(a3), "r"(b0), "r"(b1));
}
__device__ __forceinline__ void ldsm4(u32& r0, u32& r1, u32& r2, u32& r3, u32 a)
{
    asm volatile("ldmatrix.sync.aligned.m8n8.x4.shared.b16 {%0,%1,%2,%3}, [%4];\n"
                 : "=r"(r0), "=r"(r1), "=r"(r2), "=r"(r3) : "r"(a));
}
__device__ __forceinline__ void cpa16(void* dst, const void* src) {
    u32 d = (u32)__cvta_generic_to_shared(dst);
    asm volatile("cp.async.cg.shared.global [%0], [%1], 16;\n" :: "r"(d), "l"(src));
}
#define CP_COMMIT() asm volatile("cp.async.commit_group;\n" ::: "memory")

__global__ void init_kernel() {
    int tid = blockIdx.x * blockDim.x + threadIdx.x;
    __half z = __float2half(0.f);
    for (int i = tid; i < BB * HH; i += gridDim.x * blockDim.x) {
        g_h0[0][i] = z; g_h0[1][i] = z;
        g_h1[0][i] = z; g_h1[1][i] = z;
    }
    if (blockIdx.x == 0 && threadIdx.x == 0) g_bar = 0u;
}

__global__ void __launch_bounds__(256)
prep_kernel(const float* __restrict__ U0, const float* __restrict__ W1,
            const float* __restrict__ U1)
{
    __shared__ float tile[64][65];
    int mat = blockIdx.z;
    const float* src = (mat == 0) ? U0 : ((mat == 1) ? W1 : U1);
    int c0 = blockIdx.x * 64;
    int k0 = blockIdx.y * 64;
    int tid = threadIdx.x;
#pragma unroll
    for (int i = 0; i < 4; ++i) {
        int lin = tid + i * 256;
        int kr = lin >> 4, cq = lin & 15;
        float4 v = ldg4(src + (size_t)(k0 + kr) * G4 + c0 + cq * 4);
        tile[kr][cq * 4 + 0] = v.x; tile[kr][cq * 4 + 1] = v.y;
        tile[kr][cq * 4 + 2] = v.z; tile[kr][cq * 4 + 3] = v.w;
    }
    __syncthreads();
#pragma unroll
    for (int i = 0; i < 2; ++i) {
        int lin = tid + i * 256;
        int cr = lin >> 3, seg = (lin & 7) * 8;
        __half tmp[8];
#pragma unroll
        for (int j = 0; j < 8; ++j) tmp[j] = __float2half(tile[seg + j][cr]);
        *(uint4*)(g_Wt + ((size_t)mat * G4 + c0 + cr) * HH + k0 + seg) = *(uint4*)tmp;
    }
}

__global__ void __launch_bounds__(256)
prep2a_kernel(const float* __restrict__ x, const float* __restrict__ z)
{
    size_t stride = (size_t)gridDim.x * blockDim.x;
    size_t total = (size_t)BB * SS * KA;
    for (size_t idx = (size_t)blockIdx.x * blockDim.x + threadIdx.x; idx < total; idx += stride) {
        size_t r = idx / KA;
        int k = (int)(idx - r * KA);
        float v = (k < 512) ? __ldg(&x[r * 512 + k]) : __ldg(&z[r * 128 + (k - 512)]);
        g_A[idx] = __float2half(v);
    }
}

__global__ void __launch_bounds__(256)
prep2b_kernel(const float* __restrict__ W0, const float* __restrict__ V0,
              const float* __restrict__ V1)
{
    int which = blockIdx.z;
    if (which != 0 && blockIdx.y >= 2) return;
    const float* W = (which == 0) ? W0 : ((which == 1) ? V0 : V1);
    __shared__ float tile[64][65];
    int n0 = blockIdx.x * 64;
    int k0 = blockIdx.y * 64;
    int tid = threadIdx.x;
#pragma unroll
    for (int i = 0; i < 4; ++i) {
        int lin = tid + i * 256;
        int kr = lin >> 4, nq = lin & 15;
        float4 v = ldg4(W + (size_t)(k0 + kr) * G4 + n0 + nq * 4);
        tile[kr][nq * 4 + 0] = v.x; tile[kr][nq * 4 + 1] = v.y;
        tile[kr][nq * 4 + 2] = v.z; tile[kr][nq * 4 + 3] = v.w;
    }
    __syncthreads();
    __half* dst; int ldb, kb;
    if (which == 0)      { dst = g_B0; ldb = KA;  kb = k0; }
    else if (which == 1) { dst = g_B0; ldb = KA;  kb = 512 + k0; }
    else                 { dst = g_B1; ldb = 128; kb = k0; }
#pragma unroll
    for (int i = 0; i < 2; ++i) {
        int lin = tid + i * 256;
        int nr = lin >> 3, seg = (lin & 7) * 8;
        __half th[8];
#pragma unroll
        for (int j = 0; j < 8; ++j) th[j] = __float2half(tile[seg + j][nr]);
        *(uint4*)(dst + (size_t)(n0 + nr) * ldb + kb + seg) = *(uint4*)th;
    }
}

// ---------------- precompute GEMM: fp16 single-term --------------------------
struct GSmem {
    __half A[3][64][PK];
    __half B[3][64][PK];
};
#define G_SMEM_BYTES ((int)sizeof(GSmem))

__global__ void __launch_bounds__(256, 2)
gemm_mma_kernel(const float* __restrict__ bsA1, const float* __restrict__ bsA2,
                const float* __restrict__ bsB1, const float* __restrict__ bsB2)
{
    const int which = blockIdx.z;
    const __half* __restrict__ A; const __half* __restrict__ B;
    const float* bs1; const float* bs2;
    int ldb, K; float* OUT;
    if (which == 0) { A = g_A;       B = g_B0; ldb = KA;  K = KA;  OUT = g_P0; bs1 = bsA1; bs2 = bsA2; }
    else            { A = g_A + 512; B = g_B1; ldb = 128; K = 128; OUT = g_P1; bs1 = bsB1; bs2 = bsB2; }
    const int lda = KA;

    extern __shared__ unsigned char smraw[];
    GSmem* sm = (GSmem*)smraw;
    const int tid = threadIdx.x;
    const int n0 = blockIdx.x * 64;
    const int m0 = blockIdx.y * 64;
    const int lane = tid & 31, w = tid >> 5;
    const int g = lane >> 2, q2 = (lane & 3) * 2;
    const int lg = lane >> 3, lr = lane & 7;
    const int wm = (w >> 2) * 32;
    const int wn = (w & 3) * 16;
    const int nch = K / KC;

    const int l0 = tid * 2, l1 = tid * 2 + 1;
    const int ar0 = l0 >> 3, as0 = (l0 & 7) * 8;
    const int ar1 = l1 >> 3, as1 = (l1 & 7) * 8;

    const u32 bufstr = 64 * PK * 2;
    const u32 baseA = (u32)__cvta_generic_to_shared(&sm->A[0][0][0]);
    const u32 baseB = (u32)__cvta_generic_to_shared(&sm->B[0][0][0]);
    const u32 offA0 = (u32)(wm + (lg & 1) * 8 + lr) * (PK * 2) + (lg >> 1) * 16;
    const u32 offA1 = offA0 + 16 * (PK * 2);
    const u32 offB  = (u32)(wn + (lg >> 1) * 8 + lr) * (PK * 2) + (lg & 1) * 16;

    float acc[2][2][4];
#pragma unroll
    for (int a = 0; a < 2; ++a)
#pragma unroll
        for (int b = 0; b < 2; ++b)
#pragma unroll
            for (int c = 0; c < 4; ++c) acc[a][b][c] = 0.f;

#pragma unroll
    for (int pc = 0; pc < 2; ++pc) {
        int k0 = pc * KC;
        cpa16(&sm->A[pc][ar0][as0], A + (size_t)(m0 + ar0) * lda + k0 + as0);
        cpa16(&sm->A[pc][ar1][as1], A + (size_t)(m0 + ar1) * lda + k0 + as1);
        cpa16(&sm->B[pc][ar0][as0], B + (size_t)(n0 + ar0) * ldb + k0 + as0);
        cpa16(&sm->B[pc][ar1][as1], B + (size_t)(n0 + ar1) * ldb + k0 + as1);
        CP_COMMIT();
    }

    for (int ch = 0; ch < nch; ++ch) {
        if (ch < nch - 1) asm volatile("cp.async.wait_group 1;\n" ::: "memory");
        else              asm volatile("cp.async.wait_group 0;\n" ::: "memory");
        __syncthreads();
        if (ch + 2 < nch) {
            int buf = (ch + 2) % 3;
            int k0 = (ch + 2) * KC;
            cpa16(&sm->A[buf][ar0][as0], A + (size_t)(m0 + ar0) * lda + k0 + as0);
            cpa16(&sm->A[buf][ar1][as1], A + (size_t)(m0 + ar1) * lda + k0 + as1);
            cpa16(&sm->B[buf][ar0][as0], B + (size_t)(n0 + ar0) * ldb + k0 + as0);
            cpa16(&sm->B[buf][ar1][as1], B + (size_t)(n0 + ar1) * ldb + k0 + as1);
            CP_COMMIT();
        }
        const int buf = ch % 3;
        const u32 bo = buf * bufstr;
#pragma unroll
        for (int kk = 0; kk < 4; ++kk) {
            const u32 kb2 = kk * 32;
            u32 a[2][4], b[4];
            ldsm4(a[0][0], a[0][1], a[0][2], a[0][3], baseA + bo + offA0 + kb2);
            ldsm4(a[1][0], a[1][1], a[1][2], a[1][3], baseA + bo + offA1 + kb2);
            ldsm4(b[0], b[1], b[2], b[3], baseB + bo + offB + kb2);
#pragma unroll
            for (int nt = 0; nt < 2; ++nt)
#pragma unroll
                for (int mt = 0; mt < 2; ++mt)
                    mma_h(acc[mt][nt], a[mt][0], a[mt][1], a[mt][2], a[mt][3],
                          b[nt * 2], b[nt * 2 + 1]);
        }
    }

#pragma unroll
    for (int mt = 0; mt < 2; ++mt) {
        int r0 = m0 + wm + mt * 16 + g;
#pragma unroll
        for (int nt = 0; nt < 2; ++nt) {
            int c = n0 + wn + nt * 8 + q2;
            float b0 = __ldg(&bs1[c]) + __ldg(&bs2[c]);
            float b1 = __ldg(&bs1[c + 1]) + __ldg(&bs2[c + 1]);
            OUT[(size_t)r0 * G4 + c]           = acc[mt][nt][0] + b0;
            OUT[(size_t)r0 * G4 + c + 1]       = acc[mt][nt][1] + b1;
            OUT[(size_t)(r0 + 8) * G4 + c]     = acc[mt][nt][2] + b0;
            OUT[(size_t)(r0 + 8) * G4 + c + 1] = acc[mt][nt][3] + b1;
        }
    }
}

__device__ __forceinline__ void gbar(unsigned& epoch)
{
    __syncthreads();
    epoch += NCTA;
    if (threadIdx.x == 0) {
        __threadfence();
        atomicAdd(&g_bar, 1u);
        while (*(volatile unsigned*)&g_bar < epoch) { }
        __threadfence();
    }
    __syncthreads();
}

// ---------------- recurrent: W1 + U1 slices smem-resident --------------------
struct RecSmem {
    __half A1[3][64][PK];
    __half A2[3][64][PK];
    __half B1s[3][32][PK];    // streamed U0 slice
    __half B1r[32][PK2];      // resident W1 slice
    __half B2r[32][PK2];      // resident U1 slice
    float pre1[32][66];
    float pre0[32][66];
    float c0[8][66];
    float c1[8][66];
};
#define REC_SMEM_BYTES ((int)sizeof(RecSmem))

__global__ void __launch_bounds__(256, 1)
recur_kernel(float* __restrict__ out)
{
    extern __shared__ unsigned char smraw[];
    RecSmem* sm = (RecSmem*)smraw;

    const int tid = threadIdx.x;
    const int u0 = blockIdx.x * 8;
    const int lane = tid & 31, w = tid >> 5;
    const int g = lane >> 2, q2 = (lane & 3) * 2;
    const int lg = lane >> 3, lr = lane & 7;
    const int cu = tid & 7, cb = tid >> 3;

    const int lin1 = tid + 256;
    const int arow0 = tid >> 3,  aseg0 = (tid & 7) * 8;
    const int arow1 = lin1 >> 3, aseg1 = (lin1 & 7) * 8;
    const size_t offGA0 = (size_t)arow0 * HH + aseg0;
    const size_t offGA1 = (size_t)arow1 * HH + aseg1;

    // streamed B1s (U0, 32 cols): 1 line per thread
    const int bj = tid >> 3, bks = tid & 7;
    const __half* pB1s = g_Wt + ((size_t)0 * G4 + ((size_t)(bj >> 3) << 10) + u0 + (bj & 7)) * HH + bks * 8;

    const int wlo = (w < 4) ? w : (w - 4);
    const int wm = (wlo >> 1) * 32;
    const int wn = (w < 4) ? ((wlo & 1) * 32) : ((wlo & 1) * 16);

    const u32 bufstr = 64 * PK * 2;
    const u32 b1sstr = 32 * PK * 2;
    const u32 baseA1 = (u32)__cvta_generic_to_shared(&sm->A1[0][0][0]);
    const u32 baseA2 = (u32)__cvta_generic_to_shared(&sm->A2[0][0][0]);
    const u32 baseB1s = (u32)__cvta_generic_to_shared(&sm->B1s[0][0][0]);
    const u32 baseB1r = (u32)__cvta_generic_to_shared(&sm->B1r[0][0]);
    const u32 baseB2r = (u32)__cvta_generic_to_shared(&sm->B2r[0][0]);
    const u32 offA_0 = (u32)(wm + (lg & 1) * 8 + lr) * (PK * 2) + (lg >> 1) * 16;
    const u32 offA_1 = offA_0 + 16 * (PK * 2);
    // resident-stride offsets (PK2)
    const u32 offRr0 = (u32)((lg >> 1) * 8 + lr) * (PK2 * 2) + (lg & 1) * 16;
    const u32 offRr1 = offRr0 + 16 * (PK2 * 2);
    // streamed-stride offsets (local rows 0..31)
    const u32 offS0 = (u32)((lg >> 1) * 8 + lr) * (PK * 2) + (lg & 1) * 16;
    const u32 offS1 = offS0 + 16 * (PK * 2);
    // B2r offsets for w>=4 (wn = 0 or 16)
    const u32 offB2 = (u32)(wn + (lg >> 1) * 8 + lr) * (PK2 * 2) + (lg & 1) * 16;

    // resident fills: B1r = W1 slice (mat 1), B2r = U1 slice (mat 2)
#pragma unroll
    for (int i = 0; i < 16; ++i) {
        int lin = tid + i * 256;
        int row = lin >> 7, seg = (lin & 127) * 8;
        size_t colflat = ((size_t)(row >> 3) << 10) + u0 + (row & 7);
        *(uint4*)&sm->B1r[row][seg] =
            *(const uint4*)(g_Wt + ((size_t)1 * G4 + colflat) * HH + seg);
        *(uint4*)&sm->B2r[row][seg] =
            *(const uint4*)(g_Wt + ((size_t)2 * G4 + colflat) * HH + seg);
    }

    for (int i = tid; i < 8 * 66; i += 256) {
        ((float*)sm->c0)[i] = 0.f;
        ((float*)sm->c1)[i] = 0.f;
    }
    __syncthreads();
#pragma unroll
    for (int half = 0; half < 2; ++half) {
        int b = cb + half * 32;
        size_t base = ((size_t)b * SS) * G4 + u0 + cu;
        float pi = g_P0[base + 1024];
        float pg = g_P0[base + 2048];
        float po = g_P0[base + 3072];
        float cn = sigf(pi) * tanha(pg);
        sm->c0[cu][b] = cn;
        g_h0[0][b * HH + u0 + cu] = __float2half(sigf(po) * tanha(cn));
    }
    unsigned epoch = 0;
    gbar(epoch);

    for (int t = 0; t < SS; ++t) {
        const __half* h0r = g_h0[t & 1];
        const __half* h1r = g_h1[(t + 1) & 1];
        __half* h0w = g_h0[(t + 1) & 1];
        __half* h1w = g_h1[t & 1];

        float acc[2][4][4];
#pragma unroll
        for (int a = 0; a < 2; ++a)
#pragma unroll
            for (int b = 0; b < 4; ++b)
#pragma unroll
                for (int c = 0; c < 4; ++c) acc[a][b][c] = 0.f;

#pragma unroll
        for (int pc = 0; pc < 2; ++pc) {
            int k0 = pc * KC;
            cpa16(&sm->A1[pc][arow0][aseg0], h0r + offGA0 + k0);
            cpa16(&sm->A1[pc][arow1][aseg1], h0r + offGA1 + k0);
            cpa16(&sm->A2[pc][arow0][aseg0], h1r + offGA0 + k0);
            cpa16(&sm->A2[pc][arow1][aseg1], h1r + offGA1 + k0);
            cpa16(&sm->B1s[pc][bj][bks * 8], pB1s + k0);
            CP_COMMIT();
        }

        for (int ch = 0; ch < NCH; ++ch) {
            if (ch < NCH - 1) asm volatile("cp.async.wait_group 1;\n" ::: "memory");
            else              asm volatile("cp.async.wait_group 0;\n" ::: "memory");
            __syncthreads();
            if (ch + 2 < NCH) {
                int buf = (ch + 2) % 3;
                int k0 = (ch + 2) * KC;
                cpa16(&sm->A1[buf][arow0][aseg0], h0r + offGA0 + k0);
                cpa16(&sm->A1[buf][arow1][aseg1], h0r + offGA1 + k0);
                cpa16(&sm->A2[buf][arow0][aseg0], h1r + offGA0 + k0);
                cpa16(&sm->A2[buf][arow1][aseg1], h1r + offGA1 + k0);
                cpa16(&sm->B1s[buf][bj][bks * 8], pB1s + k0);
                CP_COMMIT();
            }
            const int buf = ch % 3;
            const u32 bo = buf * bufstr;
            const u32 kgl2 = (u32)(ch * KC) * 2;
            if (w < 4) {
#pragma unroll
                for (int kk = 0; kk < 4; ++kk) {
                    const u32 kb2 = kk * 32;
                    u32 a[2][4], bA[4], bB[4];
                    ldsm4(a[0][0], a[0][1], a[0][2], a[0][3], baseA1 + bo + offA_0 + kb2);
                    ldsm4(a[1][0], a[1][1], a[1][2], a[1][3], baseA1 + bo + offA_1 + kb2);
                    if (wn == 0) {
                        ldsm4(bA[0], bA[1], bA[2], bA[3], baseB1r + offRr0 + kgl2 + kb2);
                        ldsm4(bB[0], bB[1], bB[2], bB[3], baseB1r + offRr1 + kgl2 + kb2);
                    } else {
                        ldsm4(bA[0], bA[1], bA[2], bA[3], baseB1s + buf * b1sstr + offS0 + kb2);
                        ldsm4(bB[0], bB[1], bB[2], bB[3], baseB1s + buf * b1sstr + offS1 + kb2);
                    }
#pragma unroll
                    for (int nt = 0; nt < 4; ++nt) {
                        u32 b0 = (nt < 2) ? bA[(nt & 1) * 2]     : bB[(nt & 1) * 2];
                        u32 b1 = (nt < 2) ? bA[(nt & 1) * 2 + 1] : bB[(nt & 1) * 2 + 1];
                        mma_h(acc[0][nt], a[0][0], a[0][1], a[0][2], a[0][3], b0, b1);
                        mma_h(acc[1][nt], a[1][0], a[1][1], a[1][2], a[1][3], b0, b1);
                    }
                }
            } else {
#pragma unroll
                for (int kk = 0; kk < 4; ++kk) {
                    const u32 kb2 = kk * 32;
                    u32 a[2][4], bA[4];
                    ldsm4(a[0][0], a[0][1], a[0][2], a[0][3], baseA2 + bo + offA_0 + kb2);
                    ldsm4(a[1][0], a[1][1], a[1][2], a[1][3], baseA2 + bo + offA_1 + kb2);
                    ldsm4(bA[0], bA[1], bA[2], bA[3], baseB2r + offB2 + kgl2 + kb2);
#pragma unroll
                    for (int nt = 0; nt < 2; ++nt) {
                        u32 b0 = bA[nt * 2], b1 = bA[nt * 2 + 1];
                        mma_h(acc[0][nt], a[0][0], a[0][1], a[0][2], a[0][3], b0, b1);
                        mma_h(acc[1][nt], a[1][0], a[1][1], a[1][2], a[1][3], b0, b1);
                    }
                }
            }
        }
        __syncthreads();

        if (w < 4) {
            const bool isL1 = (wn == 0);
#pragma unroll
            for (int mt = 0; mt < 2; ++mt) {
                int r0 = wm + mt * 16 + g;
#pragma unroll
                for (int nt = 0; nt < 4; ++nt) {
                    int cj = (wn & 31) + nt * 8 + q2;
                    int gate = cj >> 3, un = cj & 7;
                    if (isL1) {
                        const float* base = g_P1 + ((size_t)gate << 10) + u0 + un;
                        float2 pa = *(const float2*)(base + ((size_t)r0 * SS + t) * G4);
                        float2 pb = *(const float2*)(base + ((size_t)(r0 + 8) * SS + t) * G4);
                        sm->pre1[cj][r0]         = acc[mt][nt][0] + pa.x;
                        sm->pre1[cj + 1][r0]     = acc[mt][nt][1] + pa.y;
                        sm->pre1[cj][r0 + 8]     = acc[mt][nt][2] + pb.x;
                        sm->pre1[cj + 1][r0 + 8] = acc[mt][nt][3] + pb.y;
                    } else if (t < SS - 1) {
                        const float* base = g_P0 + ((size_t)gate << 10) + u0 + un;
                        float2 pa = *(const float2*)(base + ((size_t)r0 * SS + t + 1) * G4);
                        float2 pb = *(const float2*)(base + ((size_t)(r0 + 8) * SS + t + 1) * G4);
                        sm->pre0[cj][r0]         = acc[mt][nt][0] + pa.x;
                        sm->pre0[cj + 1][r0]     = acc[mt][nt][1] + pa.y;
                        sm->pre0[cj][r0 + 8]     = acc[mt][nt][2] + pb.x;
                        sm->pre0[cj + 1][r0 + 8] = acc[mt][nt][3] + pb.y;
                    }
                }
            }
        }
        __syncthreads();

        if (w >= 4) {
#pragma unroll
            for (int mt = 0; mt < 2; ++mt) {
                int r0 = wm + mt * 16 + g;
#pragma unroll
                for (int nt = 0; nt < 2; ++nt) {
                    int cj = wn + nt * 8 + q2;
                    sm->pre1[cj][r0]         += acc[mt][nt][0];
                    sm->pre1[cj + 1][r0]     += acc[mt][nt][1];
                    sm->pre1[cj][r0 + 8]     += acc[mt][nt][2];
                    sm->pre1[cj + 1][r0 + 8] += acc[mt][nt][3];
                }
            }
        }
        __syncthreads();

#pragma unroll
        for (int half = 0; half < 2; ++half) {
            int b = cb + half * 32;
            {
                float f  = sigf(sm->pre1[cu][b]);
                float ii = sigf(sm->pre1[8 + cu][b]);
                float gg = tanha(sm->pre1[16 + cu][b]);
                float oo = sigf(sm->pre1[24 + cu][b]);
                float cn = f * sm->c1[cu][b] + ii * gg;
                sm->c1[cu][b] = cn;
                float h = oo * tanha(cn);
                h1w[b * HH + u0 + cu] = __float2half(h);
                g_Hout[((size_t)b * SS + t) * HH + u0 + cu] = h;
                if (t == SS - 1) {
                    out[98304 + 65536 + b * HH + u0 + cu] = h;
                    out[229376 + 65536 + b * HH + u0 + cu] = cn;
                }
            }
            if (t < SS - 1) {
                float f  = sigf(sm->pre0[cu][b]);
                float ii = sigf(sm->pre0[8 + cu][b]);
                float gg = tanha(sm->pre0[16 + cu][b]);
                float oo = sigf(sm->pre0[24 + cu][b]);
                float cn = f * sm->c0[cu][b] + ii * gg;
                sm->c0[cu][b] = cn;
                float h = oo * tanha(cn);
                h0w[b * HH + u0 + cu] = __float2half(h);
                if (t == SS - 2) {
                    out[98304 + b * HH + u0 + cu] = h;
                    out[229376 + b * HH + u0 + cu] = cn;
                }
            }
        }
        gbar(epoch);
    }
}

__global__ void __launch_bounds__(256)
head_kernel(const float* __restrict__ fcW, const float* __restrict__ fcb,
            float* __restrict__ out)
{
    int warp = (blockIdx.x * blockDim.x + threadIdx.x) >> 5;
    int lane = threadIdx.x & 31;
    if (warp >= BB * SS) return;
    const float* hrow = &g_Hout[(size_t)warp * HH];
    float a0 = 0.f, a1 = 0.f, a2 = 0.f;
    for (int k = lane; k < HH; k += 32) {
        float h = __ldg(&hrow[k]);
        a0 += h * __ldg(&fcW[k * 3 + 0]);
        a1 += h * __ldg(&fcW[k * 3 + 1]);
        a2 += h * __ldg(&fcW[k * 3 + 2]);
    }
#pragma unroll
    for (int off = 16; off; off >>= 1) {
        a0 += __shfl_xor_sync(0xffffffffu, a0, off);
        a1 += __shfl_xor_sync(0xffffffffu, a1, off);
        a2 += __shfl_xor_sync(0xffffffffu, a2, off);
    }
    if (lane == 0) {
        out[warp * 3 + 0] = a0 + __ldg(&fcb[0]);
        out[warp * 3 + 1] = a1 + __ldg(&fcb[1]);
        out[warp * 3 + 2] = a2 + __ldg(&fcb[2]);
    }
}

extern "C" void kernel_launch(void* const* d_in, const int* in_sizes, int n_in,
                              void* d_out, int out_size)
{
    const float* x    = (const float*)d_in[0];
    const float* z    = (const float*)d_in[1];
    const float* W0   = (const float*)d_in[2];
    const float* bW0  = (const float*)d_in[3];
    const float* U0   = (const float*)d_in[4];
    const float* V0   = (const float*)d_in[5];
    const float* b0   = (const float*)d_in[6];
    const float* W1   = (const float*)d_in[7];
    const float* bW1  = (const float*)d_in[8];
    const float* U1   = (const float*)d_in[9];
    const float* V1   = (const float*)d_in[10];
    const float* b1   = (const float*)d_in[11];
    const float* fcW  = (const float*)d_in[12];
    const float* fcb  = (const float*)d_in[13];
    float* out = (float*)d_out;

    static int smem_set = 0;
    if (!smem_set) {
        cudaFuncSetAttribute(recur_kernel, cudaFuncAttributeMaxDynamicSharedMemorySize,
                             REC_SMEM_BYTES);
        cudaFuncSetAttribute(gemm_mma_kernel, cudaFuncAttributeMaxDynamicSharedMemorySize,
                             G_SMEM_BYTES);
        smem_set = 1;
    }

    init_kernel<<<256, 256>>>();
    prep_kernel<<<dim3(64, 16, 3), 256>>>(U0, W1, U1);
    prep2a_kernel<<<2048, 256>>>(x, z);
    prep2b_kernel<<<dim3(64, 8, 3), 256>>>(W0, V0, V1);
    gemm_mma_kernel<<<dim3(64, 512, 2), 256, G_SMEM_BYTES>>>(bW0, b0, bW1, b1);
    recur_kernel<<<NCTA, 256, REC_SMEM_BYTES>>>(out);
    head_kernel<<<4096, 256>>>(fcW, fcb, out);
}

// round 11
// speedup vs baseline: 5.6741x; 1.0698x over previous
#include <cuda_runtime.h>
#include <cuda_fp16.h>
#include <math.h>

#define BB   64
#define SS   512
#define HH   1024
#define G4   4096
#define NCTA 128
#define KC   64
#define NCH  16
#define PK   72
#define PK2  1032
#define KA   640

typedef unsigned int u32;

__device__ float g_P0[BB * SS * G4];
__device__ float g_P1[BB * SS * G4];
__device__ float g_Hout[BB * SS * HH];
__device__ __half g_Wt[3ULL * G4 * HH];   // recur weights [mat][col][k]
__device__ __half g_A[BB * SS * KA];      // [r][640] = [x|z] fp16
__device__ __half g_B0[G4 * KA];          // [n][640] = [W0|V0]^T fp16
__device__ __half g_B1[G4 * 128];         // [n][128] = V1^T fp16
__device__ __half g_h0[2][BB * HH];
__device__ __half g_h1[2][BB * HH];
__device__ unsigned g_bar;

__device__ __forceinline__ float4 ldg4(const float* p)  { return __ldg((const float4*)p); }
__device__ __forceinline__ float sigf(float x)  { return 1.0f / (1.0f + __expf(-x)); }
__device__ __forceinline__ float tanha(float x) { return 1.0f - 2.0f / (__expf(2.0f * x) + 1.0f); }

__device__ __forceinline__ void mma_h(float* c, u32 a0, u32 a1, u32 a2, u32 a3,
                                      u32 b0, u32 b1)
{
    asm volatile(
        "mma.sync.aligned.m16n8k16.row.col.f32.f16.f16.f32 "
        "{%0,%1,%2,%3}, {%4,%5,%6,%7}, {%8,%9}, {%0,%1,%2,%3};\n"
        : "+f"(c[0]), "+f"(c[1]), "+f"(c[2]), "+f"(c[3])
        : "r"(a0), "r"(a1), "r"(a2), "r"(a3), "r"(b0), "r"(b1));
}
__device__ __forceinline__ void ldsm4(u32& r0, u32& r1, u32& r2, u32& r3, u32 a)
{
    asm volatile("ldmatrix.sync.aligned.m8n8.x4.shared.b16 {%0,%1,%2,%3}, [%4];\n"
                 : "=r"(r0), "=r"(r1), "=r"(r2), "=r"(r3) : "r"(a));
}
__device__ __forceinline__ void cpa16(void* dst, const void* src) {
    u32 d = (u32)__cvta_generic_to_shared(dst);
    asm volatile("cp.async.cg.shared.global [%0], [%1], 16;\n" :: "r"(d), "l"(src));
}
#define CP_COMMIT() asm volatile("cp.async.commit_group;\n" ::: "memory")

// ---------------- prep2a + init (merged) -------------------------------------
__global__ void __launch_bounds__(256)
prep2a_kernel(const float* __restrict__ x, const float* __restrict__ z)
{
    size_t gtid = (size_t)blockIdx.x * blockDim.x + threadIdx.x;
    size_t stride = (size_t)gridDim.x * blockDim.x;
    __half hz = __float2half(0.f);
    for (size_t i = gtid; i < BB * HH; i += stride) {
        g_h0[0][i] = hz; g_h0[1][i] = hz;
        g_h1[0][i] = hz; g_h1[1][i] = hz;
    }
    if (gtid == 0) g_bar = 0u;
    size_t total = (size_t)BB * SS * KA;
    for (size_t idx = gtid; idx < total; idx += stride) {
        size_t r = idx / KA;
        int k = (int)(idx - r * KA);
        float v = (k < 512) ? __ldg(&x[r * 512 + k]) : __ldg(&z[r * 128 + (k - 512)]);
        g_A[idx] = __float2half(v);
    }
}

// ---------------- prep_all (merged transpose kernels) ------------------------
// z 0..2: recur weights -> g_Wt [mat][col][k]   (y 0..15)
// z 3: W0 -> B0[.., 0..511]  (y 0..7) ; z 4: V0 -> B0[.., 512..639] (y 0..1)
// z 5: V1 -> B1 (y 0..1)
__global__ void __launch_bounds__(256)
prep_all_kernel(const float* __restrict__ U0, const float* __restrict__ W1,
                const float* __restrict__ U1, const float* __restrict__ W0,
                const float* __restrict__ V0, const float* __restrict__ V1)
{
    int zi = blockIdx.z;
    __shared__ float tile[64][65];
    int tid = threadIdx.x;
    if (zi < 3) {
        const float* src = (zi == 0) ? U0 : ((zi == 1) ? W1 : U1);
        int c0 = blockIdx.x * 64;
        int k0 = blockIdx.y * 64;
#pragma unroll
        for (int i = 0; i < 4; ++i) {
            int lin = tid + i * 256;
            int kr = lin >> 4, cq = lin & 15;
            float4 v = ldg4(src + (size_t)(k0 + kr) * G4 + c0 + cq * 4);
            tile[kr][cq * 4 + 0] = v.x; tile[kr][cq * 4 + 1] = v.y;
            tile[kr][cq * 4 + 2] = v.z; tile[kr][cq * 4 + 3] = v.w;
        }
        __syncthreads();
#pragma unroll
        for (int i = 0; i < 2; ++i) {
            int lin = tid + i * 256;
            int cr = lin >> 3, seg = (lin & 7) * 8;
            __half tmp[8];
#pragma unroll
            for (int j = 0; j < 8; ++j) tmp[j] = __float2half(tile[seg + j][cr]);
            *(uint4*)(g_Wt + ((size_t)zi * G4 + c0 + cr) * HH + k0 + seg) = *(uint4*)tmp;
        }
        return;
    }
    int which = zi - 3;
    if (which == 0) { if (blockIdx.y >= 8) return; }
    else            { if (blockIdx.y >= 2) return; }
    const float* W = (which == 0) ? W0 : ((which == 1) ? V0 : V1);
    int n0 = blockIdx.x * 64;
    int k0 = blockIdx.y * 64;
#pragma unroll
    for (int i = 0; i < 4; ++i) {
        int lin = tid + i * 256;
        int kr = lin >> 4, nq = lin & 15;
        float4 v = ldg4(W + (size_t)(k0 + kr) * G4 + n0 + nq * 4);
        tile[kr][nq * 4 + 0] = v.x; tile[kr][nq * 4 + 1] = v.y;
        tile[kr][nq * 4 + 2] = v.z; tile[kr][nq * 4 + 3] = v.w;
    }
    __syncthreads();
    __half* dst; int ldb, kb;
    if (which == 0)      { dst = g_B0; ldb = KA;  kb = k0; }
    else if (which == 1) { dst = g_B0; ldb = KA;  kb = 512 + k0; }
    else                 { dst = g_B1; ldb = 128; kb = k0; }
#pragma unroll
    for (int i = 0; i < 2; ++i) {
        int lin = tid + i * 256;
        int nr = lin >> 3, seg = (lin & 7) * 8;
        __half th[8];
#pragma unroll
        for (int j = 0; j < 8; ++j) th[j] = __float2half(tile[seg + j][nr]);
        *(uint4*)(dst + (size_t)(n0 + nr) * ldb + kb + seg) = *(uint4*)th;
    }
}

// ---------------- precompute GEMM: fp16 single-term --------------------------
struct GSmem {
    __half A[3][64][PK];
    __half B[3][64][PK];
};
#define G_SMEM_BYTES ((int)sizeof(GSmem))

__global__ void __launch_bounds__(256, 2)
gemm_mma_kernel(const float* __restrict__ bsA1, const float* __restrict__ bsA2,
                const float* __restrict__ bsB1, const float* __restrict__ bsB2)
{
    const int which = blockIdx.z;
    const __half* __restrict__ A; const __half* __restrict__ B;
    const float* bs1; const float* bs2;
    int ldb, K; float* OUT;
    if (which == 0) { A = g_A;       B = g_B0; ldb = KA;  K = KA;  OUT = g_P0; bs1 = bsA1; bs2 = bsA2; }
    else            { A = g_A + 512; B = g_B1; ldb = 128; K = 128; OUT = g_P1; bs1 = bsB1; bs2 = bsB2; }
    const int lda = KA;

    extern __shared__ unsigned char smraw[];
    GSmem* sm = (GSmem*)smraw;
    const int tid = threadIdx.x;
    const int n0 = blockIdx.x * 64;
    const int m0 = blockIdx.y * 64;
    const int lane = tid & 31, w = tid >> 5;
    const int g = lane >> 2, q2 = (lane & 3) * 2;
    const int lg = lane >> 3, lr = lane & 7;
    const int wm = (w >> 2) * 32;
    const int wn = (w & 3) * 16;
    const int nch = K / KC;

    const int l0 = tid * 2, l1 = tid * 2 + 1;
    const int ar0 = l0 >> 3, as0 = (l0 & 7) * 8;
    const int ar1 = l1 >> 3, as1 = (l1 & 7) * 8;

    const u32 bufstr = 64 * PK * 2;
    const u32 baseA = (u32)__cvta_generic_to_shared(&sm->A[0][0][0]);
    const u32 baseB = (u32)__cvta_generic_to_shared(&sm->B[0][0][0]);
    const u32 offA0 = (u32)(wm + (lg & 1) * 8 + lr) * (PK * 2) + (lg >> 1) * 16;
    const u32 offA1 = offA0 + 16 * (PK * 2);
    const u32 offB  = (u32)(wn + (lg >> 1) * 8 + lr) * (PK * 2) + (lg & 1) * 16;

    float acc[2][2][4];
#pragma unroll
    for (int a = 0; a < 2; ++a)
#pragma unroll
        for (int b = 0; b < 2; ++b)
#pragma unroll
            for (int c = 0; c < 4; ++c) acc[a][b][c] = 0.f;

#pragma unroll
    for (int pc = 0; pc < 2; ++pc) {
        int k0 = pc * KC;
        cpa16(&sm->A[pc][ar0][as0], A + (size_t)(m0 + ar0) * lda + k0 + as0);
        cpa16(&sm->A[pc][ar1][as1], A + (size_t)(m0 + ar1) * lda + k0 + as1);
        cpa16(&sm->B[pc][ar0][as0], B + (size_t)(n0 + ar0) * ldb + k0 + as0);
        cpa16(&sm->B[pc][ar1][as1], B + (size_t)(n0 + ar1) * ldb + k0 + as1);
        CP_COMMIT();
    }

    for (int ch = 0; ch < nch; ++ch) {
        if (ch < nch - 1) asm volatile("cp.async.wait_group 1;\n" ::: "memory");
        else              asm volatile("cp.async.wait_group 0;\n" ::: "memory");
        __syncthreads();
        if (ch + 2 < nch) {
            int buf = (ch + 2) % 3;
            int k0 = (ch + 2) * KC;
            cpa16(&sm->A[buf][ar0][as0], A + (size_t)(m0 + ar0) * lda + k0 + as0);
            cpa16(&sm->A[buf][ar1][as1], A + (size_t)(m0 + ar1) * lda + k0 + as1);
            cpa16(&sm->B[buf][ar0][as0], B + (size_t)(n0 + ar0) * ldb + k0 + as0);
            cpa16(&sm->B[buf][ar1][as1], B + (size_t)(n0 + ar1) * ldb + k0 + as1);
            CP_COMMIT();
        }
        const int buf = ch % 3;
        const u32 bo = buf * bufstr;
#pragma unroll
        for (int kk = 0; kk < 4; ++kk) {
            const u32 kb2 = kk * 32;
            u32 a[2][4], b[4];
            ldsm4(a[0][0], a[0][1], a[0][2], a[0][3], baseA + bo + offA0 + kb2);
            ldsm4(a[1][0], a[1][1], a[1][2], a[1][3], baseA + bo + offA1 + kb2);
            ldsm4(b[0], b[1], b[2], b[3], baseB + bo + offB + kb2);
#pragma unroll
            for (int nt = 0; nt < 2; ++nt)
#pragma unroll
                for (int mt = 0; mt < 2; ++mt)
                    mma_h(acc[mt][nt], a[mt][0], a[mt][1], a[mt][2], a[mt][3],
                          b[nt * 2], b[nt * 2 + 1]);
        }
    }

#pragma unroll
    for (int mt = 0; mt < 2; ++mt) {
        int r0 = m0 + wm + mt * 16 + g;
#pragma unroll
        for (int nt = 0; nt < 2; ++nt) {
            int c = n0 + wn + nt * 8 + q2;
            float b0 = __ldg(&bs1[c]) + __ldg(&bs2[c]);
            float b1 = __ldg(&bs1[c + 1]) + __ldg(&bs2[c + 1]);
            OUT[(size_t)r0 * G4 + c]           = acc[mt][nt][0] + b0;
            OUT[(size_t)r0 * G4 + c + 1]       = acc[mt][nt][1] + b1;
            OUT[(size_t)(r0 + 8) * G4 + c]     = acc[mt][nt][2] + b0;
            OUT[(size_t)(r0 + 8) * G4 + c + 1] = acc[mt][nt][3] + b1;
        }
    }
}

__device__ __forceinline__ void gbar(unsigned& epoch)
{
    __syncthreads();
    epoch += NCTA;
    if (threadIdx.x == 0) {
        __threadfence();
        atomicAdd(&g_bar, 1u);
        while (*(volatile unsigned*)&g_bar < epoch) { }
        __threadfence();
    }
    __syncthreads();
}

// ---------------- recurrent: 4-deep pipeline, U1 resident --------------------
struct RecSmem {
    __half A1[4][64][PK];
    __half A2[4][64][PK];
    __half B1[4][64][PK];     // streamed [W1 | U0] slice
    __half B2r[32][PK2];      // resident U1 slice
    float pre1[32][66];
    float pre0[32][66];
    float c0[8][66];
    float c1[8][66];
};
#define REC_SMEM_BYTES ((int)sizeof(RecSmem))

__global__ void __launch_bounds__(256, 1)
recur_kernel(float* __restrict__ out)
{
    extern __shared__ unsigned char smraw[];
    RecSmem* sm = (RecSmem*)smraw;

    const int tid = threadIdx.x;
    const int u0 = blockIdx.x * 8;
    const int lane = tid & 31, w = tid >> 5;
    const int g = lane >> 2, q2 = (lane & 3) * 2;
    const int lg = lane >> 3, lr = lane & 7;
    const int cu = tid & 7, cb = tid >> 3;

    const int lin1 = tid + 256;
    const int arow0 = tid >> 3,  aseg0 = (tid & 7) * 8;
    const int arow1 = lin1 >> 3, aseg1 = (lin1 & 7) * 8;
    const size_t offGA0 = (size_t)arow0 * HH + aseg0;
    const size_t offGA1 = (size_t)arow1 * HH + aseg1;
    const int jj0 = arow0 & 31, jj1 = arow1 & 31;
    const __half* pB1_0 = g_Wt + ((size_t)1 * G4 + ((jj0 >> 3) << 10) + u0 + (jj0 & 7)) * HH + aseg0;
    const __half* pB1_1 = g_Wt + ((size_t)0 * G4 + ((jj1 >> 3) << 10) + u0 + (jj1 & 7)) * HH + aseg1;

    const int wlo = (w < 4) ? w : (w - 4);
    const int wm = (wlo >> 1) * 32;
    const int wn = (w < 4) ? ((wlo & 1) * 32) : ((wlo & 1) * 16);

    const u32 bufstr = 64 * PK * 2;
    const u32 baseA1 = (u32)__cvta_generic_to_shared(&sm->A1[0][0][0]);
    const u32 baseA2 = (u32)__cvta_generic_to_shared(&sm->A2[0][0][0]);
    const u32 baseB1 = (u32)__cvta_generic_to_shared(&sm->B1[0][0][0]);
    const u32 baseB2 = (u32)__cvta_generic_to_shared(&sm->B2r[0][0]);
    const u32 offA_0 = (u32)(wm + (lg & 1) * 8 + lr) * (PK * 2) + (lg >> 1) * 16;
    const u32 offA_1 = offA_0 + 16 * (PK * 2);
    const u32 offB1_0 = (u32)(wn + (lg >> 1) * 8 + lr) * (PK * 2) + (lg & 1) * 16;
    const u32 offB1_1 = offB1_0 + 16 * (PK * 2);
    const u32 offB2  = (u32)(wn + (lg >> 1) * 8 + lr) * (PK2 * 2) + (lg & 1) * 16;

    // resident U1 slice
#pragma unroll
    for (int i = 0; i < 16; ++i) {
        int lin = tid + i * 256;
        int row = lin >> 7, seg = (lin & 127) * 8;
        size_t c = ((size_t)2 * G4 + ((row >> 3) << 10) + u0 + (row & 7));
        *(uint4*)&sm->B2r[row][seg] = *(const uint4*)(g_Wt + c * HH + seg);
    }
    for (int i = tid; i < 8 * 66; i += 256) {
        ((float*)sm->c0)[i] = 0.f;
        ((float*)sm->c1)[i] = 0.f;
    }
    __syncthreads();
#pragma unroll
    for (int half = 0; half < 2; ++half) {
        int b = cb + half * 32;
        size_t base = ((size_t)b * SS) * G4 + u0 + cu;
        float pi = g_P0[base + 1024];
        float pg = g_P0[base + 2048];
        float po = g_P0[base + 3072];
        float cn = sigf(pi) * tanha(pg);
        sm->c0[cu][b] = cn;
        g_h0[0][b * HH + u0 + cu] = __float2half(sigf(po) * tanha(cn));
    }
    unsigned epoch = 0;
    gbar(epoch);

    for (int t = 0; t < SS; ++t) {
        const __half* h0r = g_h0[t & 1];
        const __half* h1r = g_h1[(t + 1) & 1];
        __half* h0w = g_h0[(t + 1) & 1];
        __half* h1w = g_h1[t & 1];

        float acc[2][4][4];
#pragma unroll
        for (int a = 0; a < 2; ++a)
#pragma unroll
            for (int b = 0; b < 4; ++b)
#pragma unroll
                for (int c = 0; c < 4; ++c) acc[a][b][c] = 0.f;

#pragma unroll
        for (int pc = 0; pc < 3; ++pc) {
            int k0 = pc * KC;
            cpa16(&sm->A1[pc][arow0][aseg0], h0r + offGA0 + k0);
            cpa16(&sm->A1[pc][arow1][aseg1], h0r + offGA1 + k0);
            cpa16(&sm->A2[pc][arow0][aseg0], h1r + offGA0 + k0);
            cpa16(&sm->A2[pc][arow1][aseg1], h1r + offGA1 + k0);
            cpa16(&sm->B1[pc][arow0][aseg0], pB1_0 + k0);
            cpa16(&sm->B1[pc][arow1][aseg1], pB1_1 + k0);
            CP_COMMIT();
        }

        for (int ch = 0; ch < NCH; ++ch) {
            if (ch <= NCH - 3)      asm volatile("cp.async.wait_group 2;\n" ::: "memory");
            else if (ch == NCH - 2) asm volatile("cp.async.wait_group 1;\n" ::: "memory");
            else                    asm volatile("cp.async.wait_group 0;\n" ::: "memory");
            __syncthreads();
            if (ch + 3 < NCH) {
                int buf = (ch + 3) & 3;
                int k0 = (ch + 3) * KC;
                cpa16(&sm->A1[buf][arow0][aseg0], h0r + offGA0 + k0);
                cpa16(&sm->A1[buf][arow1][aseg1], h0r + offGA1 + k0);
                cpa16(&sm->A2[buf][arow0][aseg0], h1r + offGA0 + k0);
                cpa16(&sm->A2[buf][arow1][aseg1], h1r + offGA1 + k0);
                cpa16(&sm->B1[buf][arow0][aseg0], pB1_0 + k0);
                cpa16(&sm->B1[buf][arow1][aseg1], pB1_1 + k0);
                CP_COMMIT();
            }
            const int buf = ch & 3;
            const u32 bo = buf * bufstr;
            if (w < 4) {
#pragma unroll
                for (int kk = 0; kk < 4; ++kk) {
                    const u32 kb2 = kk * 32;
                    u32 a[2][4], bA[4], bB[4];
                    ldsm4(a[0][0], a[0][1], a[0][2], a[0][3], baseA1 + bo + offA_0 + kb2);
                    ldsm4(a[1][0], a[1][1], a[1][2], a[1][3], baseA1 + bo + offA_1 + kb2);
                    ldsm4(bA[0], bA[1], bA[2], bA[3], baseB1 + bo + offB1_0 + kb2);
                    ldsm4(bB[0], bB[1], bB[2], bB[3], baseB1 + bo + offB1_1 + kb2);
#pragma unroll
                    for (int nt = 0; nt < 4; ++nt) {
                        u32 b0 = (nt < 2) ? bA[(nt & 1) * 2]     : bB[(nt & 1) * 2];
                        u32 b1 = (nt < 2) ? bA[(nt & 1) * 2 + 1] : bB[(nt & 1) * 2 + 1];
                        mma_h(acc[0][nt], a[0][0], a[0][1], a[0][2], a[0][3], b0, b1);
                        mma_h(acc[1][nt], a[1][0], a[1][1], a[1][2], a[1][3], b0, b1);
                    }
                }
            } else {
                const u32 kgl2 = (u32)(ch * KC) * 2;
#pragma unroll
                for (int kk = 0; kk < 4; ++kk) {
                    const u32 kb2 = kk * 32;
                    u32 a[2][4], bA[4];
                    ldsm4(a[0][0], a[0][1], a[0][2], a[0][3], baseA2 + bo + offA_0 + kb2);
                    ldsm4(a[1][0], a[1][1], a[1][2], a[1][3], baseA2 + bo + offA_1 + kb2);
                    ldsm4(bA[0], bA[1], bA[2], bA[3], baseB2 + offB2 + kgl2 + kb2);
#pragma unroll
                    for (int nt = 0; nt < 2; ++nt) {
                        u32 b0 = bA[nt * 2], b1 = bA[nt * 2 + 1];
                        mma_h(acc[0][nt], a[0][0], a[0][1], a[0][2], a[0][3], b0, b1);
                        mma_h(acc[1][nt], a[1][0], a[1][1], a[1][2], a[1][3], b0, b1);
                    }
                }
            }
        }
        __syncthreads();

        if (w < 4) {
            const bool isL1 = (wn == 0);
#pragma unroll
            for (int mt = 0; mt < 2; ++mt) {
                int r0 = wm + mt * 16 + g;
#pragma unroll
                for (int nt = 0; nt < 4; ++nt) {
                    int cj = (wn & 31) + nt * 8 + q2;
                    int gate = cj >> 3, un = cj & 7;
                    if (isL1) {
                        const float* base = g_P1 + ((size_t)gate << 10) + u0 + un;
                        float2 pa = *(const float2*)(base + ((size_t)r0 * SS + t) * G4);
                        float2 pb = *(const float2*)(base + ((size_t)(r0 + 8) * SS + t) * G4);
                        sm->pre1[cj][r0]         = acc[mt][nt][0] + pa.x;
                        sm->pre1[cj + 1][r0]     = acc[mt][nt][1] + pa.y;
                        sm->pre1[cj][r0 + 8]     = acc[mt][nt][2] + pb.x;
                        sm->pre1[cj + 1][r0 + 8] = acc[mt][nt][3] + pb.y;
                    } else if (t < SS - 1) {
                        const float* base = g_P0 + ((size_t)gate << 10) + u0 + un;
                        float2 pa = *(const float2*)(base + ((size_t)r0 * SS + t + 1) * G4);
                        float2 pb = *(const float2*)(base + ((size_t)(r0 + 8) * SS + t + 1) * G4);
                        sm->pre0[cj][r0]         = acc[mt][nt][0] + pa.x;
                        sm->pre0[cj + 1][r0]     = acc[mt][nt][1] + pa.y;
                        sm->pre0[cj][r0 + 8]     = acc[mt][nt][2] + pb.x;
                        sm->pre0[cj + 1][r0 + 8] = acc[mt][nt][3] + pb.y;
                    }
                }
            }
        }
        __syncthreads();

        if (w >= 4) {
#pragma unroll
            for (int mt = 0; mt < 2; ++mt) {
                int r0 = wm + mt * 16 + g;
#pragma unroll
                for (int nt = 0; nt < 2; ++nt) {
                    int cj = wn + nt * 8 + q2;
                    sm->pre1[cj][r0]         += acc[mt][nt][0];
                    sm->pre1[cj + 1][r0]     += acc[mt][nt][1];
                    sm->pre1[cj][r0 + 8]     += acc[mt][nt][2];
                    sm->pre1[cj + 1][r0 + 8] += acc[mt][nt][3];
                }
            }
        }
        __syncthreads();

#pragma unroll
        for (int half = 0; half < 2; ++half) {
            int b = cb + half * 32;
            {
                float f  = sigf(sm->pre1[cu][b]);
                float ii = sigf(sm->pre1[8 + cu][b]);
                float gg = tanha(sm->pre1[16 + cu][b]);
                float oo = sigf(sm->pre1[24 + cu][b]);
                float cn = f * sm->c1[cu][b] + ii * gg;
                sm->c1[cu][b] = cn;
                float h = oo * tanha(cn);
                h1w[b * HH + u0 + cu] = __float2half(h);
                g_Hout[((size_t)b * SS + t) * HH + u0 + cu] = h;
                if (t == SS - 1) {
                    out[98304 + 65536 + b * HH + u0 + cu] = h;
                    out[229376 + 65536 + b * HH + u0 + cu] = cn;
                }
            }
            if (t < SS - 1) {
                float f  = sigf(sm->pre0[cu][b]);
                float ii = sigf(sm->pre0[8 + cu][b]);
                float gg = tanha(sm->pre0[16 + cu][b]);
                float oo = sigf(sm->pre0[24 + cu][b]);
                float cn = f * sm->c0[cu][b] + ii * gg;
                sm->c0[cu][b] = cn;
                float h = oo * tanha(cn);
                h0w[b * HH + u0 + cu] = __float2half(h);
                if (t == SS - 2) {
                    out[98304 + b * HH + u0 + cu] = h;
                    out[229376 + b * HH + u0 + cu] = cn;
                }
            }
        }
        gbar(epoch);
    }
}

__global__ void __launch_bounds__(256)
head_kernel(const float* __restrict__ fcW, const float* __restrict__ fcb,
            float* __restrict__ out)
{
    int warp = (blockIdx.x * blockDim.x + threadIdx.x) >> 5;
    int lane = threadIdx.x & 31;
    if (warp >= BB * SS) return;
    const float* hrow = &g_Hout[(size_t)warp * HH];
    float a0 = 0.f, a1 = 0.f, a2 = 0.f;
    for (int k = lane; k < HH; k += 32) {
        float h = __ldg(&hrow[k]);
        a0 += h * __ldg(&fcW[k * 3 + 0]);
        a1 += h * __ldg(&fcW[k * 3 + 1]);
        a2 += h * __ldg(&fcW[k * 3 + 2]);
    }
#pragma unroll
    for (int off = 16; off; off >>= 1) {
        a0 += __shfl_xor_sync(0xffffffffu, a0, off);
        a1 += __shfl_xor_sync(0xffffffffu, a1, off);
        a2 += __shfl_xor_sync(0xffffffffu, a2, off);
    }
    if (lane == 0) {
        out[warp * 3 + 0] = a0 + __ldg(&fcb[0]);
        out[warp * 3 + 1] = a1 + __ldg(&fcb[1]);
        out[warp * 3 + 2] = a2 + __ldg(&fcb[2]);
    }
}

extern "C" void kernel_launch(void* const* d_in, const int* in_sizes, int n_in,
                              void* d_out, int out_size)
{
    const float* x    = (const float*)d_in[0];
    const float* z    = (const float*)d_in[1];
    const float* W0   = (const float*)d_in[2];
    const float* bW0  = (const float*)d_in[3];
    const float* U0   = (const float*)d_in[4];
    const float* V0   = (const float*)d_in[5];
    const float* b0   = (const float*)d_in[6];
    const float* W1   = (const float*)d_in[7];
    const float* bW1  = (const float*)d_in[8];
    const float* U1   = (const float*)d_in[9];
    const float* V1   = (const float*)d_in[10];
    const float* b1   = (const float*)d_in[11];
    const float* fcW  = (const float*)d_in[12];
    const float* fcb  = (const float*)d_in[13];
    float* out = (float*)d_out;

    static int smem_set = 0;
    if (!smem_set) {
        cudaFuncSetAttribute(recur_kernel, cudaFuncAttributeMaxDynamicSharedMemorySize,
                             REC_SMEM_BYTES);
        cudaFuncSetAttribute(gemm_mma_kernel, cudaFuncAttributeMaxDynamicSharedMemorySize,
                             G_SMEM_BYTES);
        smem_set = 1;
    }

    prep2a_kernel<<<2048, 256>>>(x, z);                               // launch 1
    prep_all_kernel<<<dim3(64, 16, 6), 256>>>(U0, W1, U1, W0, V0, V1); // launch 2
    gemm_mma_kernel<<<dim3(64, 512, 2), 256, G_SMEM_BYTES>>>(bW0, b0, bW1, b1); // launch 3
    recur_kernel<<<NCTA, 256, REC_SMEM_BYTES>>>(out);                 // launch 4
    head_kernel<<<4096, 256>>>(fcW, fcb, out);                        // launch 5
}